// round 2
// baseline (speedup 1.0000x reference)
#include <cuda_runtime.h>

#define B_  2048
#define T_  40
#define H_  128
#define V_  4450
#define C_  102
#define G3  384   // 3H

// Scratch: __device__ globals (the sanctioned no-alloc workaround)
__device__ float g_gx [2][T_][B_][G3];   // input gates (b_ih + b_hh[r,z] folded)
__device__ float g_mix[2][B_][T_][H_];   // mixed fwd/bwd states per stream

// ---------------------------------------------------------------- helpers ---
__device__ __forceinline__ unsigned f2tf(float f) {
    unsigned u; asm("cvt.rna.tf32.f32 %0, %1;" : "=r"(u) : "f"(f)); return u;
}
__device__ __forceinline__ float sigf(float x)  { return 1.f / (1.f + __expf(-x)); }
__device__ __forceinline__ float tanha(float x) { return 2.f / (1.f + __expf(-2.f * x)) - 1.f; }
__device__ __forceinline__ int SW(int r, int k) { return k ^ ((r & 7) << 2); }

__device__ __forceinline__ void mma_tf32(float* d,
                                         unsigned a0, unsigned a1, unsigned a2, unsigned a3,
                                         unsigned b0, unsigned b1) {
    asm volatile(
        "mma.sync.aligned.m16n8k8.row.col.f32.tf32.tf32.f32 "
        "{%0,%1,%2,%3},{%4,%5,%6,%7},{%8,%9},{%0,%1,%2,%3};"
        : "+f"(d[0]), "+f"(d[1]), "+f"(d[2]), "+f"(d[3])
        : "r"(a0), "r"(a1), "r"(a2), "r"(a3), "r"(b0), "r"(b1));
}

// 64x384x128 tile GEMM: A (fp32 swizzled smem) x W^T (tf32 bits swizzled smem).
// warp: rt=warp&3 (16-row tile), ct=warp>>2 (64-col tile per 128-wide gate).
__device__ __forceinline__ void gemm_block(const float* __restrict__ A_s,
                                           const float* __restrict__ W_s,
                                           float acc[3][8][4],
                                           int rt, int ct, int gid, int qid) {
    const int rowa = rt * 16 + gid;
    const float* ar0 = A_s + (rowa << 7);
    const float* ar1 = A_s + ((rowa + 8) << 7);
    const int sw = gid << 2;    // (row&7)<<2 == gid<<2 for rows and W rows alike
#pragma unroll 4
    for (int kb = 0; kb < 128; kb += 8) {
        unsigned a0 = f2tf(ar0[(kb + qid)     ^ sw]);
        unsigned a1 = f2tf(ar1[(kb + qid)     ^ sw]);
        unsigned a2 = f2tf(ar0[(kb + qid + 4) ^ sw]);
        unsigned a3 = f2tf(ar1[(kb + qid + 4) ^ sw]);
#pragma unroll
        for (int g = 0; g < 3; g++)
#pragma unroll
            for (int nf = 0; nf < 8; nf++) {
                const float* wr = W_s + ((g * 128 + ct * 64 + nf * 8 + gid) << 7);
                unsigned b0 = __float_as_uint(wr[(kb + qid)     ^ sw]);
                unsigned b1 = __float_as_uint(wr[(kb + qid + 4) ^ sw]);
                mma_tf32(acc[g][nf], a0, a1, a2, a3, b0, b1);
            }
    }
}

// --------------------------------------------------------------- kernel 1 ---
// gx = emb[tok] @ W_ih^T + b_ih (+ b_hh folded for r,z). grid (4,40,2).
__global__ __launch_bounds__(256, 1) void gx_kernel(const int* __restrict__ tokens,
                                                    const float* __restrict__ emb_a,
                                                    const float* __restrict__ emb_c,
                                                    const float* __restrict__ W_ih,
                                                    const float* __restrict__ b_ih,
                                                    const float* __restrict__ b_hh) {
    extern __shared__ float sm[];
    float* W_s    = sm;                  // 384*128 tf32 bits, swizzled
    float* A_s    = sm + 384 * 128;      // 64*128 fp32, swizzled
    float* bias_s = A_s + 64 * 128;      // 384

    const int tid = threadIdx.x;
    const int chunk = blockIdx.x, t = blockIdx.y, stream = blockIdx.z;
    const float* emb = (stream == 0) ? emb_a : emb_c;

    for (int i = tid; i < 384 * 128; i += 256) {
        int n = i >> 7, k = i & 127;
        W_s[(n << 7) + SW(n, k)] = __uint_as_float(f2tf(W_ih[i]));
    }
    for (int i = tid; i < 384; i += 256)
        bias_s[i] = b_ih[i] + (i < 256 ? b_hh[i] : 0.f);

    const int warp = tid >> 5, lane = tid & 31;
    const int rt = warp & 3, ct = warp >> 2, gid = lane >> 2, qid = lane & 3;

    for (int tile = 0; tile < 8; tile++) {
        const int row0 = chunk * 512 + tile * 64;
        __syncthreads();   // A_s free from previous gemm; publishes W_s on iter 0
        for (int i = tid; i < 64 * 32; i += 256) {
            int r = i >> 5, c4 = i & 31;
            int tok = tokens[(row0 + r) * T_ + t];
            float4 v = *(const float4*)(emb + (size_t)tok * H_ + c4 * 4);
            *(float4*)(A_s + (r << 7) + SW(r, c4 * 4)) = v;
        }
        __syncthreads();

        float acc[3][8][4];
#pragma unroll
        for (int g = 0; g < 3; g++)
#pragma unroll
            for (int nf = 0; nf < 8; nf++)
#pragma unroll
                for (int e = 0; e < 4; e++) acc[g][nf][e] = 0.f;

        gemm_block(A_s, W_s, acc, rt, ct, gid, qid);

        float* gxp = &g_gx[stream][t][row0][0];
#pragma unroll
        for (int m = 0; m < 2; m++) {
            const int row = rt * 16 + gid + 8 * m;
#pragma unroll
            for (int nf = 0; nf < 8; nf++) {
                const int j0 = ct * 64 + nf * 8 + qid * 2;
#pragma unroll
                for (int g = 0; g < 3; g++) {
                    const int j = g * 128 + j0;
                    float2 v;
                    v.x = acc[g][nf][2 * m]     + bias_s[j];
                    v.y = acc[g][nf][2 * m + 1] + bias_s[j + 1];
                    *(float2*)(gxp + (size_t)row * G3 + j) = v;
                }
            }
        }
    }
}

// --------------------------------------------------------------- kernel 2 ---
// 4 independent GRU scans. block = (scan, 64-row tile); h in smem for 40 steps.
__global__ __launch_bounds__(256, 1) void scan_kernel(const float* __restrict__ W_hh,
                                                      const float* __restrict__ b_hh) {
    extern __shared__ float sm[];
    float* W_s  = sm;               // 384*128
    float* h_s  = sm + 384 * 128;   // 64*128 fp32, swizzled
    float* bn_s = h_s + 64 * 128;   // 128 = b_hh for n gate

    const int tid = threadIdx.x;
    const int scan = blockIdx.x >> 5, tile = blockIdx.x & 31;
    const int stream = scan >> 1, rev = scan & 1;
    const int row0 = tile * 64;

    for (int i = tid; i < 384 * 128; i += 256) {
        int n = i >> 7, k = i & 127;
        W_s[(n << 7) + SW(n, k)] = __uint_as_float(f2tf(W_hh[i]));
    }
    for (int i = tid; i < 64 * 128; i += 256) h_s[i] = 0.f;
    if (tid < 128) bn_s[tid] = b_hh[256 + tid];
    __syncthreads();

    const int warp = tid >> 5, lane = tid & 31;
    const int rt = warp & 3, ct = warp >> 2, gid = lane >> 2, qid = lane & 3;

    for (int step = 0; step < 40; step++) {
        const int t = rev ? 39 - step : step;
        float acc[3][8][4];
#pragma unroll
        for (int g = 0; g < 3; g++)
#pragma unroll
            for (int nf = 0; nf < 8; nf++)
#pragma unroll
                for (int e = 0; e < 4; e++) acc[g][nf][e] = 0.f;

        gemm_block(h_s, W_s, acc, rt, ct, gid, qid);
        __syncthreads();   // all h_s reads done before overwrite

        const float* gxp = &g_gx[stream][t][row0][0];
        const bool wr = (step >= 20);   // fwd: t>=20; rev: t<20  -> both step>=20
#pragma unroll
        for (int m = 0; m < 2; m++) {
            const int row = rt * 16 + gid + 8 * m;
            const float* gr = gxp + (size_t)row * G3;
#pragma unroll
            for (int nf = 0; nf < 8; nf++) {
                const int j = ct * 64 + nf * 8 + qid * 2;
                float2 xr = *(const float2*)(gr + j);
                float2 xz = *(const float2*)(gr + 128 + j);
                float2 xn = *(const float2*)(gr + 256 + j);
                float2* hp = (float2*)(h_s + (row << 7) + SW(row, j));
                float2 ho = *hp;
                float2 hn;
                {
                    float r = sigf(xr.x + acc[0][nf][2 * m]);
                    float z = sigf(xz.x + acc[1][nf][2 * m]);
                    float n = tanha(xn.x + r * (acc[2][nf][2 * m] + bn_s[j]));
                    hn.x = (1.f - z) * n + z * ho.x;
                }
                {
                    float r = sigf(xr.y + acc[0][nf][2 * m + 1]);
                    float z = sigf(xz.y + acc[1][nf][2 * m + 1]);
                    float n = tanha(xn.y + r * (acc[2][nf][2 * m + 1] + bn_s[j + 1]));
                    hn.y = (1.f - z) * n + z * ho.y;
                }
                *hp = hn;
                if (wr) *(float2*)(&g_mix[stream][row0 + row][t][j]) = hn;
            }
        }
        __syncthreads();   // h_s writes visible before next gemm
    }
}

// --------------------------------------------------------------- kernel 3 ---
// per-batch: M = mix_a mix_a^T; col-softmax; hid = P mix_c; classifier+softmax.
#define SMX 132
__global__ __launch_bounds__(256, 2) void attn_kernel(const float* __restrict__ W_cls,
                                                      const float* __restrict__ b_cls,
                                                      float* __restrict__ out) {
    extern __shared__ float sm[];
    float* U1 = sm;                 // mix_a, later hid   [40*132]
    float* U2 = U1 + 40 * SMX;      // mix_c, later L     [40*132]
    float* E  = U2 + 40 * SMX;      // [40*40]
    float* Z  = E + 1600;           // [40]
    float* Wt = Z + 40;             // transposed W_cls [128][104]

    const int b = blockIdx.x, tid = threadIdx.x;
    const float* pma = &g_mix[0][b][0][0];
    const float* pmc = &g_mix[1][b][0][0];

    for (int i = tid; i < 40 * 128; i += 256) {
        int t = i >> 7, k = i & 127;
        U1[t * SMX + k] = pma[i];
        U2[t * SMX + k] = pmc[i];
    }
    for (int i = tid; i < 128 * 104; i += 256) {
        int k = i / 104, c = i % 104;
        Wt[i] = (c < 102) ? W_cls[c * 256 + k] : 0.f;
    }
    __syncthreads();

    // M -> E = exp(M); 2x2 register tiles, 400 tasks
    for (int task = tid; task < 400; task += 256) {
        int ib = task / 20, jb = task % 20;
        float a00 = 0, a01 = 0, a10 = 0, a11 = 0;
        const float4* A0 = (const float4*)(U1 + (2 * ib) * SMX);
        const float4* A1 = (const float4*)(U1 + (2 * ib + 1) * SMX);
        const float4* B0 = (const float4*)(U1 + (2 * jb) * SMX);
        const float4* B1 = (const float4*)(U1 + (2 * jb + 1) * SMX);
#pragma unroll 8
        for (int k4 = 0; k4 < 32; k4++) {
            float4 x0 = A0[k4], x1 = A1[k4], y0 = B0[k4], y1 = B1[k4];
            a00 += x0.x * y0.x + x0.y * y0.y + x0.z * y0.z + x0.w * y0.w;
            a01 += x0.x * y1.x + x0.y * y1.y + x0.z * y1.z + x0.w * y1.w;
            a10 += x1.x * y0.x + x1.y * y0.y + x1.z * y0.z + x1.w * y0.w;
            a11 += x1.x * y1.x + x1.y * y1.y + x1.z * y1.z + x1.w * y1.w;
        }
        E[(2 * ib)     * 40 + 2 * jb]     = __expf(a00);
        E[(2 * ib)     * 40 + 2 * jb + 1] = __expf(a01);
        E[(2 * ib + 1) * 40 + 2 * jb]     = __expf(a10);
        E[(2 * ib + 1) * 40 + 2 * jb + 1] = __expf(a11);
    }
    __syncthreads();

    if (tid < 40) {   // Z[t] = sum over rows s of E[s][t]  (softmax dim=1)
        float z = 0.f;
        for (int s = 0; s < 40; s++) z += E[s * 40 + tid];
        Z[tid] = 1.f / z;
    }
    __syncthreads();
    for (int i = tid; i < 1600; i += 256) E[i] *= Z[i % 40];
    __syncthreads();

    // hid[s][k] = sum_t P[s][t] * mix_c[t][k]  (overwrite U1)
    {
        const int k = tid & 127, s0 = tid >> 7;
        for (int s = s0; s < 40; s += 2) {
            float acc = 0.f;
            const float* Er = E + s * 40;
#pragma unroll 8
            for (int t = 0; t < 40; t++) acc += Er[t] * U2[t * SMX + k];
            U1[s * SMX + k] = acc;
        }
    }
    __syncthreads();

    // logits: 4s x 4c register tiles; L (stride 104) overwrites U2
    for (int task = tid; task < 260; task += 256) {
        int sb = task / 26, cq = task % 26;
        float acc[4][4];
#pragma unroll
        for (int i = 0; i < 4; i++)
#pragma unroll
            for (int q = 0; q < 4; q++)
                acc[i][q] = (4 * cq + q < 102) ? b_cls[4 * cq + q] : 0.f;
        const float4* W4 = (const float4*)Wt + cq;
        const float* h0 = U1 + (4 * sb)     * SMX;
        const float* h1 = U1 + (4 * sb + 1) * SMX;
        const float* h2 = U1 + (4 * sb + 2) * SMX;
        const float* h3 = U1 + (4 * sb + 3) * SMX;
#pragma unroll 4
        for (int k = 0; k < 128; k++) {
            float4 w = W4[k * 26];
            float v0 = h0[k], v1 = h1[k], v2 = h2[k], v3 = h3[k];
            acc[0][0] += v0 * w.x; acc[0][1] += v0 * w.y; acc[0][2] += v0 * w.z; acc[0][3] += v0 * w.w;
            acc[1][0] += v1 * w.x; acc[1][1] += v1 * w.y; acc[1][2] += v1 * w.z; acc[1][3] += v1 * w.w;
            acc[2][0] += v2 * w.x; acc[2][1] += v2 * w.y; acc[2][2] += v2 * w.z; acc[2][3] += v2 * w.w;
            acc[3][0] += v3 * w.x; acc[3][1] += v3 * w.y; acc[3][2] += v3 * w.z; acc[3][3] += v3 * w.w;
        }
#pragma unroll
        for (int i = 0; i < 4; i++)
#pragma unroll
            for (int q = 0; q < 4; q++) {
                int c = 4 * cq + q;
                if (c < 102) U2[(4 * sb + i) * 104 + c] = acc[i][q];
            }
    }
    __syncthreads();

    // per-row softmax over classes -> out
    {
        const int w = tid >> 5, lane = tid & 31;
        for (int s = w; s < 40; s += 8) {
            const float* L = U2 + s * 104;
            float m = -1e30f;
            for (int c = lane; c < 102; c += 32) m = fmaxf(m, L[c]);
#pragma unroll
            for (int o = 16; o; o >>= 1) m = fmaxf(m, __shfl_xor_sync(~0u, m, o));
            float e[4]; int cnt = 0; float sum = 0.f;
            for (int c = lane; c < 102; c += 32) { float v = __expf(L[c] - m); e[cnt++] = v; sum += v; }
#pragma unroll
            for (int o = 16; o; o >>= 1) sum += __shfl_xor_sync(~0u, sum, o);
            float r = 1.f / sum; cnt = 0;
            float* op = out + ((size_t)b * 40 + s) * 102;
            for (int c = lane; c < 102; c += 32) op[c] = e[cnt++] * r;
        }
    }
}

// ------------------------------------------------------------------ launch --
#define GX_SMEM   ((384 * 128 + 64 * 128 + 384) * 4)
#define SCAN_SMEM ((384 * 128 + 64 * 128 + 128) * 4)
#define ATTN_SMEM ((40 * SMX * 2 + 1600 + 40 + 128 * 104) * 4)

extern "C" void kernel_launch(void* const* d_in, const int* in_sizes, int n_in,
                              void* d_out, int out_size) {
    const int*   tokens = (const int*)  d_in[0];
    const float* emb_c  = (const float*)d_in[1];
    const float* emb_a  = (const float*)d_in[2];
    const float* W_ih   = (const float*)d_in[3];
    const float* W_hh   = (const float*)d_in[4];
    const float* b_ih   = (const float*)d_in[5];
    const float* b_hh   = (const float*)d_in[6];
    const float* W_cls  = (const float*)d_in[7];
    const float* b_cls  = (const float*)d_in[8];
    float* out = (float*)d_out;

    cudaFuncSetAttribute(gx_kernel,   cudaFuncAttributeMaxDynamicSharedMemorySize, GX_SMEM);
    cudaFuncSetAttribute(scan_kernel, cudaFuncAttributeMaxDynamicSharedMemorySize, SCAN_SMEM);
    cudaFuncSetAttribute(attn_kernel, cudaFuncAttributeMaxDynamicSharedMemorySize, ATTN_SMEM);

    gx_kernel  <<<dim3(4, T_, 2), 256, GX_SMEM>>>(tokens, emb_a, emb_c, W_ih, b_ih, b_hh);
    scan_kernel<<<128,            256, SCAN_SMEM>>>(W_hh, b_hh);
    attn_kernel<<<B_,             256, ATTN_SMEM>>>(W_cls, b_cls, out);
}

// round 3
// speedup vs baseline: 1.3055x; 1.3055x over previous
#include <cuda_runtime.h>

#define B_  2048
#define T_  40
#define H_  128
#define V_  4450
#define VP_ 4480   // 70 * 64, padded vocab for guard-free tile stores
#define C_  102
#define G3  384    // 3H

// Scratch: __device__ globals (the sanctioned no-alloc workaround)
__device__ float g_tokG[2][VP_][G3];     // per-token input gates (b_ih + b_hh[r,z] folded), 13.8 MB -> L2
__device__ float g_mix [2][B_][T_][H_];  // mixed fwd/bwd states per stream

// ---------------------------------------------------------------- helpers ---
__device__ __forceinline__ unsigned f2tf(float f) {
    unsigned u; asm("cvt.rna.tf32.f32 %0, %1;" : "=r"(u) : "f"(f)); return u;
}
__device__ __forceinline__ float sigf(float x)  { return 1.f / (1.f + __expf(-x)); }
__device__ __forceinline__ float tanha(float x) { return 2.f / (1.f + __expf(-2.f * x)) - 1.f; }
__device__ __forceinline__ int SW(int r, int k) { return k ^ ((r & 7) << 2); }

__device__ __forceinline__ void mma_tf32(float* d,
                                         unsigned a0, unsigned a1, unsigned a2, unsigned a3,
                                         unsigned b0, unsigned b1) {
    asm volatile(
        "mma.sync.aligned.m16n8k8.row.col.f32.tf32.tf32.f32 "
        "{%0,%1,%2,%3},{%4,%5,%6,%7},{%8,%9},{%0,%1,%2,%3};"
        : "+f"(d[0]), "+f"(d[1]), "+f"(d[2]), "+f"(d[3])
        : "r"(a0), "r"(a1), "r"(a2), "r"(a3), "r"(b0), "r"(b1));
}

// 64x384x128 tile GEMM: A (fp32 swizzled smem) x W^T (tf32 bits swizzled smem).
// warp: rt=warp&3 (16-row tile), ct=warp>>2 (64-col tile per 128-wide gate).
__device__ __forceinline__ void gemm_block(const float* __restrict__ A_s,
                                           const float* __restrict__ W_s,
                                           float acc[3][8][4],
                                           int rt, int ct, int gid, int qid) {
    const int rowa = rt * 16 + gid;
    const float* ar0 = A_s + (rowa << 7);
    const float* ar1 = A_s + ((rowa + 8) << 7);
    const int sw = gid << 2;    // (row&7)<<2 == gid<<2 for rows and W rows alike
#pragma unroll 4
    for (int kb = 0; kb < 128; kb += 8) {
        unsigned a0 = f2tf(ar0[(kb + qid)     ^ sw]);
        unsigned a1 = f2tf(ar1[(kb + qid)     ^ sw]);
        unsigned a2 = f2tf(ar0[(kb + qid + 4) ^ sw]);
        unsigned a3 = f2tf(ar1[(kb + qid + 4) ^ sw]);
#pragma unroll
        for (int g = 0; g < 3; g++)
#pragma unroll
            for (int nf = 0; nf < 8; nf++) {
                const float* wr = W_s + ((g * 128 + ct * 64 + nf * 8 + gid) << 7);
                unsigned b0 = __float_as_uint(wr[(kb + qid)     ^ sw]);
                unsigned b1 = __float_as_uint(wr[(kb + qid + 4) ^ sw]);
                mma_tf32(acc[g][nf], a0, a1, a2, a3, b0, b1);
            }
    }
}

// --------------------------------------------------------------- kernel 1 ---
// Token-gate table: tokG[s][v] = W_ih @ emb_s[v] + b_ih (+ b_hh folded for r,z).
// Only 4450 vocab rows instead of 81920 (B*T) rows: 18x less compute, and the
// 503 MB g_gx DRAM round-trip disappears (table is L2-resident).
// grid (70, 2): 70 vocab tiles of 64 x 2 streams. One wave.
__global__ __launch_bounds__(256, 1) void tok_gx_kernel(const float* __restrict__ emb_a,
                                                        const float* __restrict__ emb_c,
                                                        const float* __restrict__ W_ih,
                                                        const float* __restrict__ b_ih,
                                                        const float* __restrict__ b_hh) {
    extern __shared__ float sm[];
    float* W_s    = sm;                  // 384*128 tf32 bits, swizzled
    float* A_s    = sm + 384 * 128;      // 64*128 fp32, swizzled
    float* bias_s = A_s + 64 * 128;      // 384

    const int tid = threadIdx.x;
    const int tile = blockIdx.x, stream = blockIdx.y;
    const float* emb = (stream == 0) ? emb_a : emb_c;
    const int row0 = tile * 64;

    for (int i = tid; i < 384 * 128; i += 256) {
        int n = i >> 7, k = i & 127;
        W_s[(n << 7) + SW(n, k)] = __uint_as_float(f2tf(W_ih[i]));
    }
    for (int i = tid; i < 384; i += 256)
        bias_s[i] = b_ih[i] + (i < 256 ? b_hh[i] : 0.f);
    // gather 64 vocab embedding rows (clamp the 4450..4479 tail; values unused)
    for (int i = tid; i < 64 * 32; i += 256) {
        int r = i >> 5, c4 = i & 31;
        int vr = row0 + r; if (vr >= V_) vr = V_ - 1;
        float4 v = *(const float4*)(emb + (size_t)vr * H_ + c4 * 4);
        *(float4*)(A_s + (r << 7) + SW(r, c4 * 4)) = v;
    }
    __syncthreads();

    const int warp = tid >> 5, lane = tid & 31;
    const int rt = warp & 3, ct = warp >> 2, gid = lane >> 2, qid = lane & 3;

    float acc[3][8][4];
#pragma unroll
    for (int g = 0; g < 3; g++)
#pragma unroll
        for (int nf = 0; nf < 8; nf++)
#pragma unroll
            for (int e = 0; e < 4; e++) acc[g][nf][e] = 0.f;

    gemm_block(A_s, W_s, acc, rt, ct, gid, qid);

#pragma unroll
    for (int m = 0; m < 2; m++) {
        const int row = rt * 16 + gid + 8 * m;
        float* gp = &g_tokG[stream][row0 + row][0];
#pragma unroll
        for (int nf = 0; nf < 8; nf++) {
            const int j0 = ct * 64 + nf * 8 + qid * 2;
#pragma unroll
            for (int g = 0; g < 3; g++) {
                const int j = g * 128 + j0;
                float2 v;
                v.x = acc[g][nf][2 * m]     + bias_s[j];
                v.y = acc[g][nf][2 * m + 1] + bias_s[j + 1];
                *(float2*)(gp + j) = v;
            }
        }
    }
}

// --------------------------------------------------------------- kernel 2 ---
// 4 independent GRU scans. block = (scan, 64-row tile); h in smem for 40 steps.
// Input gates gathered per-step from the L2-resident token table; token loads
// hoisted above the GEMM so L2 latency hides under MMA work.
__global__ __launch_bounds__(256, 1) void scan_kernel(const float* __restrict__ W_hh,
                                                      const float* __restrict__ b_hh,
                                                      const int* __restrict__ tokens) {
    extern __shared__ float sm[];
    float* W_s  = sm;               // 384*128
    float* h_s  = sm + 384 * 128;   // 64*128 fp32, swizzled
    float* bn_s = h_s + 64 * 128;   // 128 = b_hh for n gate

    const int tid = threadIdx.x;
    const int scan = blockIdx.x >> 5, tile = blockIdx.x & 31;
    const int stream = scan >> 1, rev = scan & 1;
    const int row0 = tile * 64;

    for (int i = tid; i < 384 * 128; i += 256) {
        int n = i >> 7, k = i & 127;
        W_s[(n << 7) + SW(n, k)] = __uint_as_float(f2tf(W_hh[i]));
    }
    for (int i = tid; i < 64 * 128; i += 256) h_s[i] = 0.f;
    if (tid < 128) bn_s[tid] = b_hh[256 + tid];
    __syncthreads();

    const int warp = tid >> 5, lane = tid & 31;
    const int rt = warp & 3, ct = warp >> 2, gid = lane >> 2, qid = lane & 3;
    const float* tokG = &g_tokG[stream][0][0];
    const int rbase = row0 + rt * 16 + gid;

    for (int step = 0; step < 40; step++) {
        const int t = rev ? 39 - step : step;
        // hoist token loads: independent of the GEMM, latency hides under it
        const int tk0 = __ldg(&tokens[(rbase)     * T_ + t]);
        const int tk1 = __ldg(&tokens[(rbase + 8) * T_ + t]);

        float acc[3][8][4];
#pragma unroll
        for (int g = 0; g < 3; g++)
#pragma unroll
            for (int nf = 0; nf < 8; nf++)
#pragma unroll
                for (int e = 0; e < 4; e++) acc[g][nf][e] = 0.f;

        gemm_block(h_s, W_s, acc, rt, ct, gid, qid);
        __syncthreads();   // all h_s reads done before overwrite

        const bool wr = (step >= 20);   // fwd: t>=20; rev: t<20  -> both step>=20
#pragma unroll
        for (int m = 0; m < 2; m++) {
            const int row = rt * 16 + gid + 8 * m;
            const float* gr = tokG + (size_t)(m ? tk1 : tk0) * G3;
#pragma unroll
            for (int nf = 0; nf < 8; nf++) {
                const int j = ct * 64 + nf * 8 + qid * 2;
                float2 xr = *(const float2*)(gr + j);
                float2 xz = *(const float2*)(gr + 128 + j);
                float2 xn = *(const float2*)(gr + 256 + j);
                float2* hp = (float2*)(h_s + (row << 7) + SW(row, j));
                float2 ho = *hp;
                float2 hn;
                {
                    float r = sigf(xr.x + acc[0][nf][2 * m]);
                    float z = sigf(xz.x + acc[1][nf][2 * m]);
                    float n = tanha(xn.x + r * (acc[2][nf][2 * m] + bn_s[j]));
                    hn.x = (1.f - z) * n + z * ho.x;
                }
                {
                    float r = sigf(xr.y + acc[0][nf][2 * m + 1]);
                    float z = sigf(xz.y + acc[1][nf][2 * m + 1]);
                    float n = tanha(xn.y + r * (acc[2][nf][2 * m + 1] + bn_s[j + 1]));
                    hn.y = (1.f - z) * n + z * ho.y;
                }
                *hp = hn;
                if (wr) *(float2*)(&g_mix[stream][row0 + row][t][j]) = hn;
            }
        }
        __syncthreads();   // h_s writes visible before next gemm
    }
}

// --------------------------------------------------------------- kernel 3 ---
// per-batch: M = mix_a mix_a^T; col-softmax; hid = P mix_c; classifier+softmax.
#define SMX 132
__global__ __launch_bounds__(256, 2) void attn_kernel(const float* __restrict__ W_cls,
                                                      const float* __restrict__ b_cls,
                                                      float* __restrict__ out) {
    extern __shared__ float sm[];
    float* U1 = sm;                 // mix_a, later hid   [40*132]
    float* U2 = U1 + 40 * SMX;      // mix_c, later L     [40*132]
    float* E  = U2 + 40 * SMX;      // [40*40]
    float* Z  = E + 1600;           // [40]
    float* Wt = Z + 40;             // transposed W_cls [128][104]

    const int b = blockIdx.x, tid = threadIdx.x;
    const float* pma = &g_mix[0][b][0][0];
    const float* pmc = &g_mix[1][b][0][0];

    for (int i = tid; i < 40 * 128; i += 256) {
        int t = i >> 7, k = i & 127;
        U1[t * SMX + k] = pma[i];
        U2[t * SMX + k] = pmc[i];
    }
    for (int i = tid; i < 128 * 104; i += 256) {
        int k = i / 104, c = i % 104;
        Wt[i] = (c < 102) ? W_cls[c * 256 + k] : 0.f;
    }
    __syncthreads();

    // M -> E = exp(M); 2x2 register tiles, 400 tasks
    for (int task = tid; task < 400; task += 256) {
        int ib = task / 20, jb = task % 20;
        float a00 = 0, a01 = 0, a10 = 0, a11 = 0;
        const float4* A0 = (const float4*)(U1 + (2 * ib) * SMX);
        const float4* A1 = (const float4*)(U1 + (2 * ib + 1) * SMX);
        const float4* B0 = (const float4*)(U1 + (2 * jb) * SMX);
        const float4* B1 = (const float4*)(U1 + (2 * jb + 1) * SMX);
#pragma unroll 8
        for (int k4 = 0; k4 < 32; k4++) {
            float4 x0 = A0[k4], x1 = A1[k4], y0 = B0[k4], y1 = B1[k4];
            a00 += x0.x * y0.x + x0.y * y0.y + x0.z * y0.z + x0.w * y0.w;
            a01 += x0.x * y1.x + x0.y * y1.y + x0.z * y1.z + x0.w * y1.w;
            a10 += x1.x * y0.x + x1.y * y0.y + x1.z * y0.z + x1.w * y0.w;
            a11 += x1.x * y1.x + x1.y * y1.y + x1.z * y1.z + x1.w * y1.w;
        }
        E[(2 * ib)     * 40 + 2 * jb]     = __expf(a00);
        E[(2 * ib)     * 40 + 2 * jb + 1] = __expf(a01);
        E[(2 * ib + 1) * 40 + 2 * jb]     = __expf(a10);
        E[(2 * ib + 1) * 40 + 2 * jb + 1] = __expf(a11);
    }
    __syncthreads();

    if (tid < 40) {   // Z[t] = sum over rows s of E[s][t]  (softmax dim=1)
        float z = 0.f;
        for (int s = 0; s < 40; s++) z += E[s * 40 + tid];
        Z[tid] = 1.f / z;
    }
    __syncthreads();
    for (int i = tid; i < 1600; i += 256) E[i] *= Z[i % 40];
    __syncthreads();

    // hid[s][k] = sum_t P[s][t] * mix_c[t][k]  (overwrite U1)
    {
        const int k = tid & 127, s0 = tid >> 7;
        for (int s = s0; s < 40; s += 2) {
            float acc = 0.f;
            const float* Er = E + s * 40;
#pragma unroll 8
            for (int t = 0; t < 40; t++) acc += Er[t] * U2[t * SMX + k];
            U1[s * SMX + k] = acc;
        }
    }
    __syncthreads();

    // logits: 4s x 4c register tiles; L (stride 104) overwrites U2
    for (int task = tid; task < 260; task += 256) {
        int sb = task / 26, cq = task % 26;
        float acc[4][4];
#pragma unroll
        for (int i = 0; i < 4; i++)
#pragma unroll
            for (int q = 0; q < 4; q++)
                acc[i][q] = (4 * cq + q < 102) ? b_cls[4 * cq + q] : 0.f;
        const float4* W4 = (const float4*)Wt + cq;
        const float* h0 = U1 + (4 * sb)     * SMX;
        const float* h1 = U1 + (4 * sb + 1) * SMX;
        const float* h2 = U1 + (4 * sb + 2) * SMX;
        const float* h3 = U1 + (4 * sb + 3) * SMX;
#pragma unroll 4
        for (int k = 0; k < 128; k++) {
            float4 w = W4[k * 26];
            float v0 = h0[k], v1 = h1[k], v2 = h2[k], v3 = h3[k];
            acc[0][0] += v0 * w.x; acc[0][1] += v0 * w.y; acc[0][2] += v0 * w.z; acc[0][3] += v0 * w.w;
            acc[1][0] += v1 * w.x; acc[1][1] += v1 * w.y; acc[1][2] += v1 * w.z; acc[1][3] += v1 * w.w;
            acc[2][0] += v2 * w.x; acc[2][1] += v2 * w.y; acc[2][2] += v2 * w.z; acc[2][3] += v2 * w.w;
            acc[3][0] += v3 * w.x; acc[3][1] += v3 * w.y; acc[3][2] += v3 * w.z; acc[3][3] += v3 * w.w;
        }
#pragma unroll
        for (int i = 0; i < 4; i++)
#pragma unroll
            for (int q = 0; q < 4; q++) {
                int c = 4 * cq + q;
                if (c < 102) U2[(4 * sb + i) * 104 + c] = acc[i][q];
            }
    }
    __syncthreads();

    // per-row softmax over classes -> out
    {
        const int w = tid >> 5, lane = tid & 31;
        for (int s = w; s < 40; s += 8) {
            const float* L = U2 + s * 104;
            float m = -1e30f;
            for (int c = lane; c < 102; c += 32) m = fmaxf(m, L[c]);
#pragma unroll
            for (int o = 16; o; o >>= 1) m = fmaxf(m, __shfl_xor_sync(~0u, m, o));
            float e[4]; int cnt = 0; float sum = 0.f;
            for (int c = lane; c < 102; c += 32) { float v = __expf(L[c] - m); e[cnt++] = v; sum += v; }
#pragma unroll
            for (int o = 16; o; o >>= 1) sum += __shfl_xor_sync(~0u, sum, o);
            float r = 1.f / sum; cnt = 0;
            float* op = out + ((size_t)b * 40 + s) * 102;
            for (int c = lane; c < 102; c += 32) op[c] = e[cnt++] * r;
        }
    }
}

// ------------------------------------------------------------------ launch --
#define GX_SMEM   ((384 * 128 + 64 * 128 + 384) * 4)
#define SCAN_SMEM ((384 * 128 + 64 * 128 + 128) * 4)
#define ATTN_SMEM ((40 * SMX * 2 + 1600 + 40 + 128 * 104) * 4)

extern "C" void kernel_launch(void* const* d_in, const int* in_sizes, int n_in,
                              void* d_out, int out_size) {
    const int*   tokens = (const int*)  d_in[0];
    const float* emb_c  = (const float*)d_in[1];
    const float* emb_a  = (const float*)d_in[2];
    const float* W_ih   = (const float*)d_in[3];
    const float* W_hh   = (const float*)d_in[4];
    const float* b_ih   = (const float*)d_in[5];
    const float* b_hh   = (const float*)d_in[6];
    const float* W_cls  = (const float*)d_in[7];
    const float* b_cls  = (const float*)d_in[8];
    float* out = (float*)d_out;

    cudaFuncSetAttribute(tok_gx_kernel, cudaFuncAttributeMaxDynamicSharedMemorySize, GX_SMEM);
    cudaFuncSetAttribute(scan_kernel,   cudaFuncAttributeMaxDynamicSharedMemorySize, SCAN_SMEM);
    cudaFuncSetAttribute(attn_kernel,   cudaFuncAttributeMaxDynamicSharedMemorySize, ATTN_SMEM);

    tok_gx_kernel<<<dim3(70, 2), 256, GX_SMEM>>>(emb_a, emb_c, W_ih, b_ih, b_hh);
    scan_kernel  <<<128,         256, SCAN_SMEM>>>(W_hh, b_hh, tokens);
    attn_kernel  <<<B_,          256, ATTN_SMEM>>>(W_cls, b_cls, out);
}

// round 5
// speedup vs baseline: 2.2783x; 1.7452x over previous
#include <cuda_runtime.h>

#define B_  2048
#define T_  40
#define H_  128
#define V_  4450
#define VP_ 4480   // 70 * 64, padded vocab for guard-free tile stores
#define C_  102
#define G3  384    // 3H

// Scratch: __device__ globals (the sanctioned no-alloc workaround)
__device__ float g_tokG[2][VP_][G3];     // per-token input gates (b_ih + b_hh[r,z] folded), L2-resident
__device__ float g_mix [2][B_][T_][H_];  // mixed fwd/bwd states per stream

// ---------------------------------------------------------------- helpers ---
__device__ __forceinline__ unsigned f2tf(float f) {
    unsigned u; asm("cvt.rna.tf32.f32 %0, %1;" : "=r"(u) : "f"(f)); return u;
}
__device__ __forceinline__ unsigned pack_bf16(float lo, float hi) {
    unsigned r; asm("cvt.rn.bf16x2.f32 %0, %1, %2;" : "=r"(r) : "f"(hi), "f"(lo)); return r;
}
__device__ __forceinline__ float2 bf2f(unsigned u) {   // exact bf16->f32 via shifts
    float2 r;
    r.x = __uint_as_float(u << 16);
    r.y = __uint_as_float(u & 0xffff0000u);
    return r;
}
__device__ __forceinline__ float tanhfast(float x) {
    float y; asm("tanh.approx.f32 %0, %1;" : "=f"(y) : "f"(x)); return y;
}
__device__ __forceinline__ float sigfast(float x) { return 0.5f * tanhfast(0.5f * x) + 0.5f; }
__device__ __forceinline__ int SW(int r, int k) { return k ^ ((r & 7) << 2); }

__device__ __forceinline__ void mma_tf32(float* d,
                                         unsigned a0, unsigned a1, unsigned a2, unsigned a3,
                                         unsigned b0, unsigned b1) {
    asm volatile(
        "mma.sync.aligned.m16n8k8.row.col.f32.tf32.tf32.f32 "
        "{%0,%1,%2,%3},{%4,%5,%6,%7},{%8,%9},{%0,%1,%2,%3};"
        : "+f"(d[0]), "+f"(d[1]), "+f"(d[2]), "+f"(d[3])
        : "r"(a0), "r"(a1), "r"(a2), "r"(a3), "r"(b0), "r"(b1));
}
__device__ __forceinline__ void mma_bf16(float* d,
                                         unsigned a0, unsigned a1, unsigned a2, unsigned a3,
                                         unsigned b0, unsigned b1) {
    asm volatile(
        "mma.sync.aligned.m16n8k16.row.col.f32.bf16.bf16.f32 "
        "{%0,%1,%2,%3},{%4,%5,%6,%7},{%8,%9},{%0,%1,%2,%3};"
        : "+f"(d[0]), "+f"(d[1]), "+f"(d[2]), "+f"(d[3])
        : "r"(a0), "r"(a1), "r"(a2), "r"(a3), "r"(b0), "r"(b1));
}

// 64x384x128 tf32 tile GEMM (used by tok_gx only).
__device__ __forceinline__ void gemm_block(const float* __restrict__ A_s,
                                           const float* __restrict__ W_s,
                                           float acc[3][8][4],
                                           int rt, int ct, int gid, int qid) {
    const int rowa = rt * 16 + gid;
    const float* ar0 = A_s + (rowa << 7);
    const float* ar1 = A_s + ((rowa + 8) << 7);
    const int sw = gid << 2;
#pragma unroll 4
    for (int kb = 0; kb < 128; kb += 8) {
        unsigned a0 = f2tf(ar0[(kb + qid)     ^ sw]);
        unsigned a1 = f2tf(ar1[(kb + qid)     ^ sw]);
        unsigned a2 = f2tf(ar0[(kb + qid + 4) ^ sw]);
        unsigned a3 = f2tf(ar1[(kb + qid + 4) ^ sw]);
#pragma unroll
        for (int g = 0; g < 3; g++)
#pragma unroll
            for (int nf = 0; nf < 8; nf++) {
                const float* wr = W_s + ((g * 128 + ct * 64 + nf * 8 + gid) << 7);
                unsigned b0 = __float_as_uint(wr[(kb + qid)     ^ sw]);
                unsigned b1 = __float_as_uint(wr[(kb + qid + 4) ^ sw]);
                mma_tf32(acc[g][nf], a0, a1, a2, a3, b0, b1);
            }
    }
}

// --------------------------------------------------------------- kernel 1 ---
// Token-gate table: tokG[s][v] = W_ih @ emb_s[v] + b_ih (+ b_hh folded for r,z).
__global__ __launch_bounds__(256, 1) void tok_gx_kernel(const float* __restrict__ emb_a,
                                                        const float* __restrict__ emb_c,
                                                        const float* __restrict__ W_ih,
                                                        const float* __restrict__ b_ih,
                                                        const float* __restrict__ b_hh) {
    extern __shared__ float sm[];
    float* W_s    = sm;                  // 384*128 tf32 bits, swizzled
    float* A_s    = sm + 384 * 128;      // 64*128 fp32, swizzled
    float* bias_s = A_s + 64 * 128;      // 384

    const int tid = threadIdx.x;
    const int tile = blockIdx.x, stream = blockIdx.y;
    const float* emb = (stream == 0) ? emb_a : emb_c;
    const int row0 = tile * 64;

    for (int i = tid; i < 384 * 128; i += 256) {
        int n = i >> 7, k = i & 127;
        W_s[(n << 7) + SW(n, k)] = __uint_as_float(f2tf(W_ih[i]));
    }
    for (int i = tid; i < 384; i += 256)
        bias_s[i] = b_ih[i] + (i < 256 ? b_hh[i] : 0.f);
    for (int i = tid; i < 64 * 32; i += 256) {
        int r = i >> 5, c4 = i & 31;
        int vr = row0 + r; if (vr >= V_) vr = V_ - 1;
        float4 v = *(const float4*)(emb + (size_t)vr * H_ + c4 * 4);
        *(float4*)(A_s + (r << 7) + SW(r, c4 * 4)) = v;
    }
    __syncthreads();

    const int warp = tid >> 5, lane = tid & 31;
    const int rt = warp & 3, ct = warp >> 2, gid = lane >> 2, qid = lane & 3;

    float acc[3][8][4];
#pragma unroll
    for (int g = 0; g < 3; g++)
#pragma unroll
        for (int nf = 0; nf < 8; nf++)
#pragma unroll
            for (int e = 0; e < 4; e++) acc[g][nf][e] = 0.f;

    gemm_block(A_s, W_s, acc, rt, ct, gid, qid);

#pragma unroll
    for (int m = 0; m < 2; m++) {
        const int row = rt * 16 + gid + 8 * m;
        float* gp = &g_tokG[stream][row0 + row][0];
#pragma unroll
        for (int nf = 0; nf < 8; nf++) {
            const int j0 = ct * 64 + nf * 8 + qid * 2;
#pragma unroll
            for (int g = 0; g < 3; g++) {
                const int j = g * 128 + j0;
                float2 v;
                v.x = acc[g][nf][2 * m]     + bias_s[j];
                v.y = acc[g][nf][2 * m + 1] + bias_s[j + 1];
                *(float2*)(gp + j) = v;
            }
        }
    }
}

// --------------------------------------------------------------- kernel 2 ---
// 4 GRU scans, bf16 MMA (m16n8k16). Block = (scan, 32-row tile), 256 blocks,
// 2 blocks/SM. fp32 h carry lives in registers (each thread re-reads only its
// own h); smem h is the bf16 MMA A-operand. W_hh bf16-packed in smem (96 KB).
__global__ __launch_bounds__(256, 2) void scan_kernel(const float* __restrict__ W_hh,
                                                      const float* __restrict__ b_hh,
                                                      const int* __restrict__ tokens) {
    extern __shared__ unsigned smu[];
    unsigned* Ws  = smu;                      // 384 * 64 bf16x2 words, swizzled
    unsigned* Hs  = smu + 384 * 64;           // 32 * 64 bf16x2 words, swizzled
    float*    bn  = (float*)(Hs + 32 * 64);   // 128 = b_hh for n gate

    const int tid = threadIdx.x;
    const int scan = blockIdx.x >> 6, tile = blockIdx.x & 63;
    const int stream = scan >> 1, rev = scan & 1;
    const int row0 = tile * 32;

    for (int i = tid; i < 384 * 64; i += 256) {
        int n = i >> 6, w = i & 63;
        float2 v = *(const float2*)(W_hh + n * 128 + 2 * w);
        Ws[(n << 6) + (w ^ ((n & 7) << 2))] = pack_bf16(v.x, v.y);
    }
    for (int i = tid; i < 32 * 64; i += 256) Hs[i] = 0u;
    if (tid < 128) bn[tid] = b_hh[256 + tid];
    __syncthreads();

    const int warp = tid >> 5, lane = tid & 31;
    const int rt = warp & 1, ct = warp >> 1;        // rt: 16-row half, ct: 32-col slice/gate
    const int gid = lane >> 2, qid = lane & 3;
    const int gsw = gid << 2;
    const int ra0 = (rt * 16 + gid) << 6;
    const int ra1 = ra0 + (8 << 6);
    const float* tokG = &g_tokG[stream][0][0];
    const int rbase = row0 + rt * 16 + gid;

    float hreg[2][4][2];                             // fp32 h carry in registers
#pragma unroll
    for (int m = 0; m < 2; m++)
#pragma unroll
        for (int nf = 0; nf < 4; nf++) { hreg[m][nf][0] = 0.f; hreg[m][nf][1] = 0.f; }

    for (int step = 0; step < 40; step++) {
        const int t = rev ? 39 - step : step;
        const int tk0 = __ldg(&tokens[(rbase)     * T_ + t]);
        const int tk1 = __ldg(&tokens[(rbase + 8) * T_ + t]);

        float acc[3][4][4];
#pragma unroll
        for (int g = 0; g < 3; g++)
#pragma unroll
            for (int nf = 0; nf < 4; nf++)
#pragma unroll
                for (int e = 0; e < 4; e++) acc[g][nf][e] = 0.f;

#pragma unroll
        for (int kb = 0; kb < 8; kb++) {
            const int k0 = kb * 8;
            unsigned a0 = Hs[ra0 + ((k0 + qid)     ^ gsw)];
            unsigned a1 = Hs[ra1 + ((k0 + qid)     ^ gsw)];
            unsigned a2 = Hs[ra0 + ((k0 + qid + 4) ^ gsw)];
            unsigned a3 = Hs[ra1 + ((k0 + qid + 4) ^ gsw)];
#pragma unroll
            for (int g = 0; g < 3; g++)
#pragma unroll
                for (int nf = 0; nf < 4; nf++) {
                    const unsigned* wr = Ws + ((g * 128 + ct * 32 + nf * 8 + gid) << 6);
                    unsigned b0 = wr[(k0 + qid)     ^ gsw];
                    unsigned b1 = wr[(k0 + qid + 4) ^ gsw];
                    mma_bf16(acc[g][nf], a0, a1, a2, a3, b0, b1);
                }
        }
        __syncthreads();   // all Hs reads done before overwrite

        const bool wmix = (step >= 20);   // fwd: t>=20; rev: t<20 -> both step>=20
#pragma unroll
        for (int m = 0; m < 2; m++) {
            const int row = rt * 16 + gid + 8 * m;
            const float* gr = tokG + (size_t)(m ? tk1 : tk0) * G3;
#pragma unroll
            for (int nf = 0; nf < 4; nf++) {
                const int j = ct * 32 + nf * 8 + 2 * qid;
                float2 xr = *(const float2*)(gr + j);
                float2 xz = *(const float2*)(gr + 128 + j);
                float2 xn = *(const float2*)(gr + 256 + j);
                float r0 = sigfast(xr.x + acc[0][nf][2 * m]);
                float z0 = sigfast(xz.x + acc[1][nf][2 * m]);
                float n0 = tanhfast(xn.x + r0 * (acc[2][nf][2 * m] + bn[j]));
                float h0 = (1.f - z0) * n0 + z0 * hreg[m][nf][0];
                float r1 = sigfast(xr.y + acc[0][nf][2 * m + 1]);
                float z1 = sigfast(xz.y + acc[1][nf][2 * m + 1]);
                float n1 = tanhfast(xn.y + r1 * (acc[2][nf][2 * m + 1] + bn[j + 1]));
                float h1 = (1.f - z1) * n1 + z1 * hreg[m][nf][1];
                hreg[m][nf][0] = h0; hreg[m][nf][1] = h1;
                Hs[(row << 6) + ((ct * 16 + nf * 4 + qid) ^ gsw)] = pack_bf16(h0, h1);
                if (wmix) *(float2*)(&g_mix[stream][row0 + row][t][j]) = make_float2(h0, h1);
            }
        }
        __syncthreads();   // Hs writes visible before next gemm
    }
}

// --------------------------------------------------------------- kernel 3 ---
// per-batch: M = mix_a mix_a^T; col-softmax; hid = P mix_c; classifier+softmax.
// W_cls bf16-packed in smem -> 74 KB total -> 3 blocks/SM.
#define SMX 132
__global__ __launch_bounds__(256, 3) void attn_kernel(const float* __restrict__ W_cls,
                                                      const float* __restrict__ b_cls,
                                                      float* __restrict__ out) {
    extern __shared__ float sm[];
    float*    U1   = sm;                   // mix_a, later hid   [40*132]
    float*    U2   = U1 + 40 * SMX;        // mix_c, later L     [40*132]
    float*    E    = U2 + 40 * SMX;        // [40*40]
    float*    Z    = E + 1600;             // [40]
    float*    bs   = Z + 40;               // [104] classifier bias
    unsigned* Wtb  = (unsigned*)(bs + 104);// [128][52] bf16x2: classes (2c,2c+1) per word

    const int b = blockIdx.x, tid = threadIdx.x;
    const float* pma = &g_mix[0][b][0][0];
    const float* pmc = &g_mix[1][b][0][0];

    for (int i = tid; i < 40 * 128; i += 256) {
        int t = i >> 7, k = i & 127;
        U1[t * SMX + k] = pma[i];
        U2[t * SMX + k] = pmc[i];
    }
    for (int i = tid; i < 128 * 52; i += 256) {
        int k = i / 52, cp = i % 52;
        int c0 = 2 * cp, c1 = 2 * cp + 1;
        float f0 = (c0 < C_) ? W_cls[c0 * 256 + k] : 0.f;
        float f1 = (c1 < C_) ? W_cls[c1 * 256 + k] : 0.f;
        Wtb[i] = pack_bf16(f0, f1);
    }
    for (int i = tid; i < 104; i += 256) bs[i] = (i < C_) ? b_cls[i] : 0.f;
    __syncthreads();

    // M -> E = exp(M); 2x2 register tiles, 400 tasks
    for (int task = tid; task < 400; task += 256) {
        int ib = task / 20, jb = task % 20;
        float a00 = 0, a01 = 0, a10 = 0, a11 = 0;
        const float4* A0 = (const float4*)(U1 + (2 * ib) * SMX);
        const float4* A1 = (const float4*)(U1 + (2 * ib + 1) * SMX);
        const float4* B0 = (const float4*)(U1 + (2 * jb) * SMX);
        const float4* B1 = (const float4*)(U1 + (2 * jb + 1) * SMX);
#pragma unroll 8
        for (int k4 = 0; k4 < 32; k4++) {
            float4 x0 = A0[k4], x1 = A1[k4], y0 = B0[k4], y1 = B1[k4];
            a00 += x0.x * y0.x + x0.y * y0.y + x0.z * y0.z + x0.w * y0.w;
            a01 += x0.x * y1.x + x0.y * y1.y + x0.z * y1.z + x0.w * y1.w;
            a10 += x1.x * y0.x + x1.y * y0.y + x1.z * y0.z + x1.w * y0.w;
            a11 += x1.x * y1.x + x1.y * y1.y + x1.z * y1.z + x1.w * y1.w;
        }
        E[(2 * ib)     * 40 + 2 * jb]     = __expf(a00);
        E[(2 * ib)     * 40 + 2 * jb + 1] = __expf(a01);
        E[(2 * ib + 1) * 40 + 2 * jb]     = __expf(a10);
        E[(2 * ib + 1) * 40 + 2 * jb + 1] = __expf(a11);
    }
    __syncthreads();

    if (tid < 40) {   // Z[t] = sum over rows s of E[s][t]  (softmax dim=1)
        float z = 0.f;
        for (int s = 0; s < 40; s++) z += E[s * 40 + tid];
        Z[tid] = 1.f / z;
    }
    __syncthreads();
    for (int i = tid; i < 1600; i += 256) E[i] *= Z[i % 40];
    __syncthreads();

    // hid[s][k] = sum_t P[s][t] * mix_c[t][k]  (overwrite U1)
    {
        const int k = tid & 127, s0 = tid >> 7;
        for (int s = s0; s < 40; s += 2) {
            float acc = 0.f;
            const float* Er = E + s * 40;
#pragma unroll 8
            for (int t = 0; t < 40; t++) acc += Er[t] * U2[t * SMX + k];
            U1[s * SMX + k] = acc;
        }
    }
    __syncthreads();

    // logits: 4s x 4c register tiles; L (stride 104) overwrites U2
    for (int task = tid; task < 260; task += 256) {
        int sb = task / 26, cq = task % 26;
        float acc[4][4];
#pragma unroll
        for (int i = 0; i < 4; i++)
#pragma unroll
            for (int q = 0; q < 4; q++) acc[i][q] = bs[4 * cq + q];
        const float* h0 = U1 + (4 * sb)     * SMX;
        const float* h1 = U1 + (4 * sb + 1) * SMX;
        const float* h2 = U1 + (4 * sb + 2) * SMX;
        const float* h3 = U1 + (4 * sb + 3) * SMX;
#pragma unroll 4
        for (int k = 0; k < 128; k++) {
            float2 wa = bf2f(Wtb[k * 52 + 2 * cq]);
            float2 wb = bf2f(Wtb[k * 52 + 2 * cq + 1]);
            float v0 = h0[k], v1 = h1[k], v2 = h2[k], v3 = h3[k];
            acc[0][0] += v0 * wa.x; acc[0][1] += v0 * wa.y; acc[0][2] += v0 * wb.x; acc[0][3] += v0 * wb.y;
            acc[1][0] += v1 * wa.x; acc[1][1] += v1 * wa.y; acc[1][2] += v1 * wb.x; acc[1][3] += v1 * wb.y;
            acc[2][0] += v2 * wa.x; acc[2][1] += v2 * wa.y; acc[2][2] += v2 * wb.x; acc[2][3] += v2 * wb.y;
            acc[3][0] += v3 * wa.x; acc[3][1] += v3 * wa.y; acc[3][2] += v3 * wb.x; acc[3][3] += v3 * wb.y;
        }
#pragma unroll
        for (int i = 0; i < 4; i++)
#pragma unroll
            for (int q = 0; q < 4; q++) {
                int c = 4 * cq + q;
                if (c < C_) U2[(4 * sb + i) * 104 + c] = acc[i][q];
            }
    }
    __syncthreads();

    // per-row softmax over classes -> out
    {
        const int w = tid >> 5, lane = tid & 31;
        for (int s = w; s < 40; s += 8) {
            const float* L = U2 + s * 104;
            float m = -1e30f;
            for (int c = lane; c < C_; c += 32) m = fmaxf(m, L[c]);
#pragma unroll
            for (int o = 16; o; o >>= 1) m = fmaxf(m, __shfl_xor_sync(~0u, m, o));
            float e[4]; int cnt = 0; float sum = 0.f;
            for (int c = lane; c < C_; c += 32) { float v = __expf(L[c] - m); e[cnt++] = v; sum += v; }
#pragma unroll
            for (int o = 16; o; o >>= 1) sum += __shfl_xor_sync(~0u, sum, o);
            float r = 1.f / sum; cnt = 0;
            float* op = out + ((size_t)b * 40 + s) * C_;
            for (int c = lane; c < C_; c += 32) op[c] = e[cnt++] * r;
        }
    }
}

// ------------------------------------------------------------------ launch --
#define GX_SMEM   ((384 * 128 + 64 * 128 + 384) * 4)
#define SCAN_SMEM ((384 * 64 + 32 * 64 + 128) * 4)
#define ATTN_SMEM ((40 * SMX * 2 + 1600 + 40 + 104 + 128 * 52) * 4)

extern "C" void kernel_launch(void* const* d_in, const int* in_sizes, int n_in,
                              void* d_out, int out_size) {
    const int*   tokens = (const int*)  d_in[0];
    const float* emb_c  = (const float*)d_in[1];
    const float* emb_a  = (const float*)d_in[2];
    const float* W_ih   = (const float*)d_in[3];
    const float* W_hh   = (const float*)d_in[4];
    const float* b_ih   = (const float*)d_in[5];
    const float* b_hh   = (const float*)d_in[6];
    const float* W_cls  = (const float*)d_in[7];
    const float* b_cls  = (const float*)d_in[8];
    float* out = (float*)d_out;

    cudaFuncSetAttribute(tok_gx_kernel, cudaFuncAttributeMaxDynamicSharedMemorySize, GX_SMEM);
    cudaFuncSetAttribute(scan_kernel,   cudaFuncAttributeMaxDynamicSharedMemorySize, SCAN_SMEM);
    cudaFuncSetAttribute(attn_kernel,   cudaFuncAttributeMaxDynamicSharedMemorySize, ATTN_SMEM);

    tok_gx_kernel<<<dim3(70, 2), 256, GX_SMEM>>>(emb_a, emb_c, W_ih, b_ih, b_hh);
    scan_kernel  <<<256,         256, SCAN_SMEM>>>(W_hh, b_hh, tokens);
    attn_kernel  <<<B_,          256, ATTN_SMEM>>>(W_cls, b_cls, out);
}

// round 6
// speedup vs baseline: 3.2404x; 1.4223x over previous
#include <cuda_runtime.h>

#define B_  2048
#define T_  40
#define H_  128
#define V_  4450
#define VP_ 4480   // 70 * 64, padded vocab
#define C_  102
#define CP_ 104    // padded classes (13 * 8)
#define G3  384    // 3H
#define BT_ (B_ * T_)

// Scratch: __device__ globals (the sanctioned no-alloc workaround)
__device__ float g_tokG[2][VP_][G3];     // per-token input gates (b_ih + b_hh[r,z] folded)
__device__ float g_mix [2][B_][T_][H_];  // mixed fwd/bwd states per stream
__device__ float g_C1  [BT_][CP_];       // mix_c @ W_cls^T (no bias)

// ---------------------------------------------------------------- helpers ---
__device__ __forceinline__ unsigned pack_bf16(float lo, float hi) {
    unsigned r; asm("cvt.rn.bf16x2.f32 %0, %1, %2;" : "=r"(r) : "f"(hi), "f"(lo)); return r;
}
__device__ __forceinline__ float tanhfast(float x) {
    float y; asm("tanh.approx.f32 %0, %1;" : "=f"(y) : "f"(x)); return y;
}
__device__ __forceinline__ float sigfast(float x) { return 0.5f * tanhfast(0.5f * x) + 0.5f; }

__device__ __forceinline__ void mma_bf16(float* d,
                                         unsigned a0, unsigned a1, unsigned a2, unsigned a3,
                                         unsigned b0, unsigned b1) {
    asm volatile(
        "mma.sync.aligned.m16n8k16.row.col.f32.bf16.bf16.f32 "
        "{%0,%1,%2,%3},{%4,%5,%6,%7},{%8,%9},{%0,%1,%2,%3};"
        : "+f"(d[0]), "+f"(d[1]), "+f"(d[2]), "+f"(d[3])
        : "r"(a0), "r"(a1), "r"(a2), "r"(a3), "r"(b0), "r"(b1));
}

// --------------------------------------------------------------- kernel 1 ---
// Token-gate table via bf16 MMA. Each block: 64 vocab rows x 192 gate-cols
// (half the 384). grid (70 tiles, 2 streams, 2 halves) = 280 blocks, 2/SM.
__global__ __launch_bounds__(256, 2) void tok_gx_kernel(const float* __restrict__ emb_a,
                                                        const float* __restrict__ emb_c,
                                                        const float* __restrict__ W_ih,
                                                        const float* __restrict__ b_ih,
                                                        const float* __restrict__ b_hh) {
    extern __shared__ unsigned smu[];
    unsigned* Wb  = smu;                     // [192][64] bf16x2 words, swizzled
    unsigned* Ab  = smu + 192 * 64;          // [64][64] bf16x2 words, swizzled
    float*    bias = (float*)(Ab + 64 * 64); // [192]

    const int tid = threadIdx.x;
    const int tile = blockIdx.x, stream = blockIdx.y, half = blockIdx.z;
    const float* emb = (stream == 0) ? emb_a : emb_c;
    const int row0 = tile * 64;
    const int nbase = half * 192;

    for (int i = tid; i < 192 * 64; i += 256) {
        int n = i >> 6, w = i & 63;
        float2 v = *(const float2*)(W_ih + (size_t)(nbase + n) * 128 + 2 * w);
        Wb[(n << 6) + (w ^ ((n & 7) << 2))] = pack_bf16(v.x, v.y);
    }
    for (int i = tid; i < 192; i += 256) {
        int n = nbase + i;
        bias[i] = b_ih[n] + (n < 256 ? b_hh[n] : 0.f);
    }
    for (int i = tid; i < 64 * 64; i += 256) {
        int r = i >> 6, w = i & 63;
        int vr = row0 + r; if (vr >= V_) vr = V_ - 1;
        float2 v = *(const float2*)(emb + (size_t)vr * H_ + 2 * w);
        Ab[(r << 6) + (w ^ ((r & 7) << 2))] = pack_bf16(v.x, v.y);
    }
    __syncthreads();

    const int warp = tid >> 5, lane = tid & 31;
    const int rt = warp & 3, ct = warp >> 2;      // rt: 16-row tile, ct: 96-col half
    const int gid = lane >> 2, qid = lane & 3;
    const int gsw = gid << 2;
    const int ra0 = (rt * 16 + gid) << 6;
    const int ra1 = ra0 + (8 << 6);

    float acc[12][4];
#pragma unroll
    for (int nt = 0; nt < 12; nt++)
#pragma unroll
        for (int e = 0; e < 4; e++) acc[nt][e] = 0.f;

#pragma unroll
    for (int kb = 0; kb < 8; kb++) {
        const int k0 = kb * 8;
        unsigned a0 = Ab[ra0 + ((k0 + qid)     ^ gsw)];
        unsigned a1 = Ab[ra1 + ((k0 + qid)     ^ gsw)];
        unsigned a2 = Ab[ra0 + ((k0 + qid + 4) ^ gsw)];
        unsigned a3 = Ab[ra1 + ((k0 + qid + 4) ^ gsw)];
#pragma unroll
        for (int nt = 0; nt < 12; nt++) {
            const unsigned* wr = Wb + ((ct * 96 + nt * 8 + gid) << 6);
            unsigned b0 = wr[(k0 + qid)     ^ gsw];
            unsigned b1 = wr[(k0 + qid + 4) ^ gsw];
            mma_bf16(acc[nt], a0, a1, a2, a3, b0, b1);
        }
    }

#pragma unroll
    for (int m = 0; m < 2; m++) {
        const int row = rt * 16 + gid + 8 * m;
        float* gp = &g_tokG[stream][row0 + row][0];
#pragma unroll
        for (int nt = 0; nt < 12; nt++) {
            const int nl = ct * 96 + nt * 8 + qid * 2;
            float2 v;
            v.x = acc[nt][2 * m]     + bias[nl];
            v.y = acc[nt][2 * m + 1] + bias[nl + 1];
            *(float2*)(gp + nbase + nl) = v;
        }
    }
}

// --------------------------------------------------------------- kernel 2 ---
// 4 GRU scans, bf16 MMA (m16n8k16). Block = (scan, 32-row tile), 256 blocks,
// 2 blocks/SM. fp32 h carry in registers; smem h is the bf16 MMA A-operand.
__global__ __launch_bounds__(256, 2) void scan_kernel(const float* __restrict__ W_hh,
                                                      const float* __restrict__ b_hh,
                                                      const int* __restrict__ tokens) {
    extern __shared__ unsigned smu[];
    unsigned* Ws  = smu;                      // 384 * 64 bf16x2 words, swizzled
    unsigned* Hs  = smu + 384 * 64;           // 32 * 64 bf16x2 words, swizzled
    float*    bn  = (float*)(Hs + 32 * 64);   // 128 = b_hh for n gate

    const int tid = threadIdx.x;
    const int scan = blockIdx.x >> 6, tile = blockIdx.x & 63;
    const int stream = scan >> 1, rev = scan & 1;
    const int row0 = tile * 32;

    for (int i = tid; i < 384 * 64; i += 256) {
        int n = i >> 6, w = i & 63;
        float2 v = *(const float2*)(W_hh + n * 128 + 2 * w);
        Ws[(n << 6) + (w ^ ((n & 7) << 2))] = pack_bf16(v.x, v.y);
    }
    for (int i = tid; i < 32 * 64; i += 256) Hs[i] = 0u;
    if (tid < 128) bn[tid] = b_hh[256 + tid];
    __syncthreads();

    const int warp = tid >> 5, lane = tid & 31;
    const int rt = warp & 1, ct = warp >> 1;        // rt: 16-row half, ct: 32-col slice
    const int gid = lane >> 2, qid = lane & 3;
    const int gsw = gid << 2;
    const int ra0 = (rt * 16 + gid) << 6;
    const int ra1 = ra0 + (8 << 6);
    const float* tokG = &g_tokG[stream][0][0];
    const int rbase = row0 + rt * 16 + gid;

    float hreg[2][4][2];
#pragma unroll
    for (int m = 0; m < 2; m++)
#pragma unroll
        for (int nf = 0; nf < 4; nf++) { hreg[m][nf][0] = 0.f; hreg[m][nf][1] = 0.f; }

    for (int step = 0; step < 40; step++) {
        const int t = rev ? 39 - step : step;
        const int tk0 = __ldg(&tokens[(rbase)     * T_ + t]);
        const int tk1 = __ldg(&tokens[(rbase + 8) * T_ + t]);

        float acc[3][4][4];
#pragma unroll
        for (int g = 0; g < 3; g++)
#pragma unroll
            for (int nf = 0; nf < 4; nf++)
#pragma unroll
                for (int e = 0; e < 4; e++) acc[g][nf][e] = 0.f;

#pragma unroll
        for (int kb = 0; kb < 8; kb++) {
            const int k0 = kb * 8;
            unsigned a0 = Hs[ra0 + ((k0 + qid)     ^ gsw)];
            unsigned a1 = Hs[ra1 + ((k0 + qid)     ^ gsw)];
            unsigned a2 = Hs[ra0 + ((k0 + qid + 4) ^ gsw)];
            unsigned a3 = Hs[ra1 + ((k0 + qid + 4) ^ gsw)];
#pragma unroll
            for (int g = 0; g < 3; g++)
#pragma unroll
                for (int nf = 0; nf < 4; nf++) {
                    const unsigned* wr = Ws + ((g * 128 + ct * 32 + nf * 8 + gid) << 6);
                    unsigned b0 = wr[(k0 + qid)     ^ gsw];
                    unsigned b1 = wr[(k0 + qid + 4) ^ gsw];
                    mma_bf16(acc[g][nf], a0, a1, a2, a3, b0, b1);
                }
        }
        __syncthreads();

        const bool wmix = (step >= 20);
#pragma unroll
        for (int m = 0; m < 2; m++) {
            const int row = rt * 16 + gid + 8 * m;
            const float* gr = tokG + (size_t)(m ? tk1 : tk0) * G3;
#pragma unroll
            for (int nf = 0; nf < 4; nf++) {
                const int j = ct * 32 + nf * 8 + 2 * qid;
                float2 xr = *(const float2*)(gr + j);
                float2 xz = *(const float2*)(gr + 128 + j);
                float2 xn = *(const float2*)(gr + 256 + j);
                float r0 = sigfast(xr.x + acc[0][nf][2 * m]);
                float z0 = sigfast(xz.x + acc[1][nf][2 * m]);
                float n0 = tanhfast(xn.x + r0 * (acc[2][nf][2 * m] + bn[j]));
                float h0 = (1.f - z0) * n0 + z0 * hreg[m][nf][0];
                float r1 = sigfast(xr.y + acc[0][nf][2 * m + 1]);
                float z1 = sigfast(xz.y + acc[1][nf][2 * m + 1]);
                float n1 = tanhfast(xn.y + r1 * (acc[2][nf][2 * m + 1] + bn[j + 1]));
                float h1 = (1.f - z1) * n1 + z1 * hreg[m][nf][1];
                hreg[m][nf][0] = h0; hreg[m][nf][1] = h1;
                Hs[(row << 6) + ((ct * 16 + nf * 4 + qid) ^ gsw)] = pack_bf16(h0, h1);
                if (wmix) *(float2*)(&g_mix[stream][row0 + row][t][j]) = make_float2(h0, h1);
            }
        }
        __syncthreads();
    }
}

// --------------------------------------------------------------- kernel 3 ---
// C1 = mix_c @ W_cls^T (no bias), bf16 MMA. Block = 128 flattened (b,t) rows
// x 104 classes. 640 blocks, 3/SM.
__global__ __launch_bounds__(256, 3) void cls_kernel(const float* __restrict__ W_cls) {
    extern __shared__ unsigned smu[];
    unsigned* Wb = smu;              // [104][64] bf16x2 words, swizzled
    unsigned* Ab = smu + 104 * 64;   // [128][64] bf16x2 words, swizzled

    const int tid = threadIdx.x;
    const int row0 = blockIdx.x * 128;
    const float* mixc = &g_mix[1][0][0][0];

    for (int i = tid; i < 104 * 64; i += 256) {
        int c = i >> 6, w = i & 63;
        float2 v;
        if (c < C_) v = *(const float2*)(W_cls + (size_t)c * 256 + 2 * w);
        else        v = make_float2(0.f, 0.f);
        Wb[(c << 6) + (w ^ ((c & 7) << 2))] = pack_bf16(v.x, v.y);
    }
    for (int i = tid; i < 128 * 64; i += 256) {
        int r = i >> 6, w = i & 63;
        float2 v = *(const float2*)(mixc + (size_t)(row0 + r) * 128 + 2 * w);
        Ab[(r << 6) + (w ^ ((r & 7) << 2))] = pack_bf16(v.x, v.y);
    }
    __syncthreads();

    const int warp = tid >> 5, lane = tid & 31;
    const int gid = lane >> 2, qid = lane & 3;
    const int gsw = gid << 2;
    const int ra0 = (warp * 16 + gid) << 6;
    const int ra1 = ra0 + (8 << 6);

    float acc[13][4];
#pragma unroll
    for (int nt = 0; nt < 13; nt++)
#pragma unroll
        for (int e = 0; e < 4; e++) acc[nt][e] = 0.f;

#pragma unroll
    for (int kb = 0; kb < 8; kb++) {
        const int k0 = kb * 8;
        unsigned a0 = Ab[ra0 + ((k0 + qid)     ^ gsw)];
        unsigned a1 = Ab[ra1 + ((k0 + qid)     ^ gsw)];
        unsigned a2 = Ab[ra0 + ((k0 + qid + 4) ^ gsw)];
        unsigned a3 = Ab[ra1 + ((k0 + qid + 4) ^ gsw)];
#pragma unroll
        for (int nt = 0; nt < 13; nt++) {
            const unsigned* wr = Wb + ((nt * 8 + gid) << 6);
            unsigned b0 = wr[(k0 + qid)     ^ gsw];
            unsigned b1 = wr[(k0 + qid + 4) ^ gsw];
            mma_bf16(acc[nt], a0, a1, a2, a3, b0, b1);
        }
    }

#pragma unroll
    for (int m = 0; m < 2; m++) {
        const int row = warp * 16 + gid + 8 * m;
        float* cp = &g_C1[row0 + row][0];
#pragma unroll
        for (int nt = 0; nt < 13; nt++) {
            float2 v = make_float2(acc[nt][2 * m], acc[nt][2 * m + 1]);
            *(float2*)(cp + nt * 8 + qid * 2) = v;
        }
    }
}

// --------------------------------------------------------------- kernel 4 ---
// per-batch: symmetric Gram (triangle, 2x2 tiles), col-softmax, logits = P*C1
// (+bias), row-softmax. 44.7 KB smem -> 4 blocks/SM.
#define SMX 132
__global__ __launch_bounds__(256, 4) void attn_kernel(const float* __restrict__ b_cls,
                                                      float* __restrict__ out) {
    extern __shared__ float sm[];
    float* Ua  = sm;                // mix_a [40][132]; later logits L [40][104]
    float* E   = Ua + 40 * SMX;     // [40*40]
    float* Z   = E + 1600;          // [40]
    float* C1s = Z + 40;            // [40][104]
    float* bs  = C1s + 40 * CP_;    // [104]

    const int b = blockIdx.x, tid = threadIdx.x;
    const float* pma = &g_mix[0][b][0][0];
    const float* pc1 = &g_C1[b * T_][0];

    for (int i = tid; i < 40 * 128; i += 256) {
        int t = i >> 7, k = i & 127;
        Ua[t * SMX + k] = pma[i];
    }
    for (int i = tid; i < 40 * CP_ / 4; i += 256)
        *(float4*)(C1s + 4 * i) = *(const float4*)(pc1 + 4 * i);
    for (int i = tid; i < CP_; i += 256) bs[i] = (i < C_) ? b_cls[i] : 0.f;
    __syncthreads();

    // Symmetric Gram: 210 upper-triangle 2x2 tile tasks; write both mirrors.
    if (tid < 210) {
        int ib = 0, tk = tid;
        while (tk >= 20 - ib) { tk -= 20 - ib; ib++; }
        int jb = ib + tk;
        float a00 = 0, a01 = 0, a10 = 0, a11 = 0;
        const float4* A0 = (const float4*)(Ua + (2 * ib) * SMX);
        const float4* A1 = (const float4*)(Ua + (2 * ib + 1) * SMX);
        const float4* B0 = (const float4*)(Ua + (2 * jb) * SMX);
        const float4* B1 = (const float4*)(Ua + (2 * jb + 1) * SMX);
#pragma unroll 8
        for (int k4 = 0; k4 < 32; k4++) {
            float4 x0 = A0[k4], x1 = A1[k4], y0 = B0[k4], y1 = B1[k4];
            a00 += x0.x * y0.x + x0.y * y0.y + x0.z * y0.z + x0.w * y0.w;
            a01 += x0.x * y1.x + x0.y * y1.y + x0.z * y1.z + x0.w * y1.w;
            a10 += x1.x * y0.x + x1.y * y0.y + x1.z * y0.z + x1.w * y0.w;
            a11 += x1.x * y1.x + x1.y * y1.y + x1.z * y1.z + x1.w * y1.w;
        }
        float e00 = __expf(a00), e01 = __expf(a01);
        float e10 = __expf(a10), e11 = __expf(a11);
        E[(2 * ib)     * 40 + 2 * jb]     = e00;
        E[(2 * ib)     * 40 + 2 * jb + 1] = e01;
        E[(2 * ib + 1) * 40 + 2 * jb]     = e10;
        E[(2 * ib + 1) * 40 + 2 * jb + 1] = e11;
        E[(2 * jb)     * 40 + 2 * ib]     = e00;
        E[(2 * jb + 1) * 40 + 2 * ib]     = e01;
        E[(2 * jb)     * 40 + 2 * ib + 1] = e10;
        E[(2 * jb + 1) * 40 + 2 * ib + 1] = e11;
    }
    __syncthreads();

    if (tid < 40) {   // Z[t] = column sums (softmax dim=1)
        float z = 0.f;
        for (int s = 0; s < 40; s++) z += E[s * 40 + tid];
        Z[tid] = 1.f / z;
    }
    __syncthreads();
    for (int i = tid; i < 1600; i += 256) E[i] *= Z[i % 40];
    __syncthreads();

    // logits[s][c] = sum_t P[s][t] * C1[t][c] + b[c]; 4s x 4c tiles; L -> Ua
    float* L = Ua;
    for (int task = tid; task < 260; task += 256) {
        int sb = task / 26, cq = task % 26;
        float acc[4][4];
#pragma unroll
        for (int i = 0; i < 4; i++)
#pragma unroll
            for (int q = 0; q < 4; q++) acc[i][q] = 0.f;
        const float* E0 = E + (4 * sb) * 40;
#pragma unroll 4
        for (int t = 0; t < 40; t++) {
            float4 c1 = *(const float4*)(C1s + t * CP_ + 4 * cq);
            float p0 = E0[t], p1 = E0[40 + t], p2 = E0[80 + t], p3 = E0[120 + t];
            acc[0][0] += p0 * c1.x; acc[0][1] += p0 * c1.y; acc[0][2] += p0 * c1.z; acc[0][3] += p0 * c1.w;
            acc[1][0] += p1 * c1.x; acc[1][1] += p1 * c1.y; acc[1][2] += p1 * c1.z; acc[1][3] += p1 * c1.w;
            acc[2][0] += p2 * c1.x; acc[2][1] += p2 * c1.y; acc[2][2] += p2 * c1.z; acc[2][3] += p2 * c1.w;
            acc[3][0] += p3 * c1.x; acc[3][1] += p3 * c1.y; acc[3][2] += p3 * c1.z; acc[3][3] += p3 * c1.w;
        }
#pragma unroll
        for (int i = 0; i < 4; i++)
#pragma unroll
            for (int q = 0; q < 4; q++)
                L[(4 * sb + i) * CP_ + 4 * cq + q] = acc[i][q] + bs[4 * cq + q];
    }
    __syncthreads();

    // per-row softmax over classes -> out
    {
        const int w = tid >> 5, lane = tid & 31;
        for (int s = w; s < 40; s += 8) {
            const float* Lr = L + s * CP_;
            float m = -1e30f;
            for (int c = lane; c < C_; c += 32) m = fmaxf(m, Lr[c]);
#pragma unroll
            for (int o = 16; o; o >>= 1) m = fmaxf(m, __shfl_xor_sync(~0u, m, o));
            float e[4]; int cnt = 0; float sum = 0.f;
            for (int c = lane; c < C_; c += 32) { float v = __expf(Lr[c] - m); e[cnt++] = v; sum += v; }
#pragma unroll
            for (int o = 16; o; o >>= 1) sum += __shfl_xor_sync(~0u, sum, o);
            float r = 1.f / sum; cnt = 0;
            float* op = out + ((size_t)b * T_ + s) * C_;
            for (int c = lane; c < C_; c += 32) op[c] = e[cnt++] * r;
        }
    }
}

// ------------------------------------------------------------------ launch --
#define GX_SMEM   ((192 * 64 + 64 * 64 + 192) * 4)
#define SCAN_SMEM ((384 * 64 + 32 * 64 + 128) * 4)
#define CLS_SMEM  ((104 * 64 + 128 * 64) * 4)
#define ATTN_SMEM ((40 * SMX + 1600 + 40 + 40 * CP_ + CP_) * 4)

extern "C" void kernel_launch(void* const* d_in, const int* in_sizes, int n_in,
                              void* d_out, int out_size) {
    const int*   tokens = (const int*)  d_in[0];
    const float* emb_c  = (const float*)d_in[1];
    const float* emb_a  = (const float*)d_in[2];
    const float* W_ih   = (const float*)d_in[3];
    const float* W_hh   = (const float*)d_in[4];
    const float* b_ih   = (const float*)d_in[5];
    const float* b_hh   = (const float*)d_in[6];
    const float* W_cls  = (const float*)d_in[7];
    const float* b_cls  = (const float*)d_in[8];
    float* out = (float*)d_out;

    cudaFuncSetAttribute(tok_gx_kernel, cudaFuncAttributeMaxDynamicSharedMemorySize, GX_SMEM);
    cudaFuncSetAttribute(scan_kernel,   cudaFuncAttributeMaxDynamicSharedMemorySize, SCAN_SMEM);
    cudaFuncSetAttribute(cls_kernel,    cudaFuncAttributeMaxDynamicSharedMemorySize, CLS_SMEM);
    cudaFuncSetAttribute(attn_kernel,   cudaFuncAttributeMaxDynamicSharedMemorySize, ATTN_SMEM);

    tok_gx_kernel<<<dim3(70, 2, 2), 256, GX_SMEM>>>(emb_a, emb_c, W_ih, b_ih, b_hh);
    scan_kernel  <<<256,            256, SCAN_SMEM>>>(W_hh, b_hh, tokens);
    cls_kernel   <<<BT_ / 128,      256, CLS_SMEM>>>(W_cls);
    attn_kernel  <<<B_,             256, ATTN_SMEM>>>(b_cls, out);
}

// round 7
// speedup vs baseline: 3.9400x; 1.2159x over previous
#include <cuda_runtime.h>

#define B_  2048
#define T_  40
#define H_  128
#define V_  4450
#define VP_ 4480   // 70 * 64, padded vocab
#define C_  102
#define CP_ 104    // padded classes (13 * 8)
#define CW_ 52     // CP_/2 bf16x2 words
#define G3  384    // 3H
#define BT_ (B_ * T_)

// Scratch: __device__ globals (the sanctioned no-alloc workaround)
__device__ float    g_tokG[2][VP_][G3];    // per-token input gates (b_ih + b_hh[r,z] folded)
__device__ unsigned g_mix [2][B_][T_][64]; // mixed fwd/bwd states, bf16x2 words
__device__ unsigned g_C1  [BT_][CW_];      // mix_c @ W_cls^T (no bias), bf16x2 words

// ---------------------------------------------------------------- helpers ---
__device__ __forceinline__ unsigned pack_bf16(float lo, float hi) {
    unsigned r; asm("cvt.rn.bf16x2.f32 %0, %1, %2;" : "=r"(r) : "f"(hi), "f"(lo)); return r;
}
__device__ __forceinline__ float bflo(unsigned u) { return __uint_as_float(u << 16); }
__device__ __forceinline__ float bfhi(unsigned u) { return __uint_as_float(u & 0xffff0000u); }
__device__ __forceinline__ void unp8(float* f, uint4 v) {
    f[0] = bflo(v.x); f[1] = bfhi(v.x); f[2] = bflo(v.y); f[3] = bfhi(v.y);
    f[4] = bflo(v.z); f[5] = bfhi(v.z); f[6] = bflo(v.w); f[7] = bfhi(v.w);
}
__device__ __forceinline__ float tanhfast(float x) {
    float y; asm("tanh.approx.f32 %0, %1;" : "=f"(y) : "f"(x)); return y;
}
__device__ __forceinline__ float sigfast(float x) { return 0.5f * tanhfast(0.5f * x) + 0.5f; }

__device__ __forceinline__ void mma_bf16(float* d,
                                         unsigned a0, unsigned a1, unsigned a2, unsigned a3,
                                         unsigned b0, unsigned b1) {
    asm volatile(
        "mma.sync.aligned.m16n8k16.row.col.f32.bf16.bf16.f32 "
        "{%0,%1,%2,%3},{%4,%5,%6,%7},{%8,%9},{%0,%1,%2,%3};"
        : "+f"(d[0]), "+f"(d[1]), "+f"(d[2]), "+f"(d[3])
        : "r"(a0), "r"(a1), "r"(a2), "r"(a3), "r"(b0), "r"(b1));
}

// --------------------------------------------------------------- kernel 1 ---
// Token-gate table via bf16 MMA. 64 vocab rows x 192 gate-cols per block.
// grid (70, 2 streams, 2 halves) = 280 blocks, 2/SM.
__global__ __launch_bounds__(256, 2) void tok_gx_kernel(const float* __restrict__ emb_a,
                                                        const float* __restrict__ emb_c,
                                                        const float* __restrict__ W_ih,
                                                        const float* __restrict__ b_ih,
                                                        const float* __restrict__ b_hh) {
    extern __shared__ unsigned smu[];
    unsigned* Wb  = smu;                     // [192][64] bf16x2 words, swizzled
    unsigned* Ab  = smu + 192 * 64;          // [64][64] bf16x2 words, swizzled
    float*    bias = (float*)(Ab + 64 * 64); // [192]

    const int tid = threadIdx.x;
    const int tile = blockIdx.x, stream = blockIdx.y, half = blockIdx.z;
    const float* emb = (stream == 0) ? emb_a : emb_c;
    const int row0 = tile * 64;
    const int nbase = half * 192;

    for (int i = tid; i < 192 * 64; i += 256) {
        int n = i >> 6, w = i & 63;
        float2 v = *(const float2*)(W_ih + (size_t)(nbase + n) * 128 + 2 * w);
        Wb[(n << 6) + (w ^ ((n & 7) << 2))] = pack_bf16(v.x, v.y);
    }
    for (int i = tid; i < 192; i += 256) {
        int n = nbase + i;
        bias[i] = b_ih[n] + (n < 256 ? b_hh[n] : 0.f);
    }
    for (int i = tid; i < 64 * 64; i += 256) {
        int r = i >> 6, w = i & 63;
        int vr = row0 + r; if (vr >= V_) vr = V_ - 1;
        float2 v = *(const float2*)(emb + (size_t)vr * H_ + 2 * w);
        Ab[(r << 6) + (w ^ ((r & 7) << 2))] = pack_bf16(v.x, v.y);
    }
    __syncthreads();

    const int warp = tid >> 5, lane = tid & 31;
    const int rt = warp & 3, ct = warp >> 2;
    const int gid = lane >> 2, qid = lane & 3;
    const int gsw = gid << 2;
    const int ra0 = (rt * 16 + gid) << 6;
    const int ra1 = ra0 + (8 << 6);

    float acc[12][4];
#pragma unroll
    for (int nt = 0; nt < 12; nt++)
#pragma unroll
        for (int e = 0; e < 4; e++) acc[nt][e] = 0.f;

#pragma unroll
    for (int kb = 0; kb < 8; kb++) {
        const int k0 = kb * 8;
        unsigned a0 = Ab[ra0 + ((k0 + qid)     ^ gsw)];
        unsigned a1 = Ab[ra1 + ((k0 + qid)     ^ gsw)];
        unsigned a2 = Ab[ra0 + ((k0 + qid + 4) ^ gsw)];
        unsigned a3 = Ab[ra1 + ((k0 + qid + 4) ^ gsw)];
#pragma unroll
        for (int nt = 0; nt < 12; nt++) {
            const unsigned* wr = Wb + ((ct * 96 + nt * 8 + gid) << 6);
            unsigned b0 = wr[(k0 + qid)     ^ gsw];
            unsigned b1 = wr[(k0 + qid + 4) ^ gsw];
            mma_bf16(acc[nt], a0, a1, a2, a3, b0, b1);
        }
    }

#pragma unroll
    for (int m = 0; m < 2; m++) {
        const int row = rt * 16 + gid + 8 * m;
        float* gp = &g_tokG[stream][row0 + row][0];
#pragma unroll
        for (int nt = 0; nt < 12; nt++) {
            const int nl = ct * 96 + nt * 8 + qid * 2;
            float2 v;
            v.x = acc[nt][2 * m]     + bias[nl];
            v.y = acc[nt][2 * m + 1] + bias[nl + 1];
            *(float2*)(gp + nbase + nl) = v;
        }
    }
}

// --------------------------------------------------------------- kernel 2 ---
// 4 GRU scans, bf16 MMA. Block = (scan, 32-row tile), 256 blocks, 2/SM.
// fp32 h carry in registers; double-buffered bf16 Hs -> ONE barrier per step.
// g_mix written as the already-packed bf16x2 words (free).
__global__ __launch_bounds__(256, 2) void scan_kernel(const float* __restrict__ W_hh,
                                                      const float* __restrict__ b_hh,
                                                      const int* __restrict__ tokens) {
    extern __shared__ unsigned smu[];
    unsigned* Ws   = smu;                       // 384 * 64 bf16x2 words, swizzled
    unsigned* Hbuf = smu + 384 * 64;            // 2 x [32*64] words
    float*    bn   = (float*)(Hbuf + 2 * 32 * 64);  // 128 = b_hh for n gate

    const int tid = threadIdx.x;
    const int scan = blockIdx.x >> 6, tile = blockIdx.x & 63;
    const int stream = scan >> 1, rev = scan & 1;
    const int row0 = tile * 32;

    for (int i = tid; i < 384 * 64; i += 256) {
        int n = i >> 6, w = i & 63;
        float2 v = *(const float2*)(W_hh + n * 128 + 2 * w);
        Ws[(n << 6) + (w ^ ((n & 7) << 2))] = pack_bf16(v.x, v.y);
    }
    for (int i = tid; i < 32 * 64; i += 256) Hbuf[i] = 0u;   // buffer 0 only
    if (tid < 128) bn[tid] = b_hh[256 + tid];
    __syncthreads();

    const int warp = tid >> 5, lane = tid & 31;
    const int rt = warp & 1, ct = warp >> 1;
    const int gid = lane >> 2, qid = lane & 3;
    const int gsw = gid << 2;
    const int raA = (rt * 16 + gid) << 6;
    const int raB = raA + (8 << 6);
    const float* tokG = &g_tokG[stream][0][0];
    const int rbase = row0 + rt * 16 + gid;

    float hreg[2][4][2];
#pragma unroll
    for (int m = 0; m < 2; m++)
#pragma unroll
        for (int nf = 0; nf < 4; nf++) { hreg[m][nf][0] = 0.f; hreg[m][nf][1] = 0.f; }

    for (int step = 0; step < 40; step++) {
        const int t = rev ? 39 - step : step;
        const int tk0 = __ldg(&tokens[(rbase)     * T_ + t]);
        const int tk1 = __ldg(&tokens[(rbase + 8) * T_ + t]);
        unsigned* Hcur = Hbuf + ((step & 1) ? 32 * 64 : 0);
        unsigned* Hnxt = Hbuf + ((step & 1) ? 0 : 32 * 64);

        float acc[3][4][4];
#pragma unroll
        for (int g = 0; g < 3; g++)
#pragma unroll
            for (int nf = 0; nf < 4; nf++)
#pragma unroll
                for (int e = 0; e < 4; e++) acc[g][nf][e] = 0.f;

#pragma unroll
        for (int kb = 0; kb < 8; kb++) {
            const int k0 = kb * 8;
            unsigned a0 = Hcur[raA + ((k0 + qid)     ^ gsw)];
            unsigned a1 = Hcur[raB + ((k0 + qid)     ^ gsw)];
            unsigned a2 = Hcur[raA + ((k0 + qid + 4) ^ gsw)];
            unsigned a3 = Hcur[raB + ((k0 + qid + 4) ^ gsw)];
#pragma unroll
            for (int g = 0; g < 3; g++)
#pragma unroll
                for (int nf = 0; nf < 4; nf++) {
                    const unsigned* wr = Ws + ((g * 128 + ct * 32 + nf * 8 + gid) << 6);
                    unsigned b0 = wr[(k0 + qid)     ^ gsw];
                    unsigned b1 = wr[(k0 + qid + 4) ^ gsw];
                    mma_bf16(acc[g][nf], a0, a1, a2, a3, b0, b1);
                }
        }

        const bool wmix = (step >= 20);   // fwd: t>=20; rev: t<20 -> both step>=20
#pragma unroll
        for (int m = 0; m < 2; m++) {
            const int row = rt * 16 + gid + 8 * m;
            const float* gr = tokG + (size_t)(m ? tk1 : tk0) * G3;
#pragma unroll
            for (int nf = 0; nf < 4; nf++) {
                const int j = ct * 32 + nf * 8 + 2 * qid;
                float2 xr = *(const float2*)(gr + j);
                float2 xz = *(const float2*)(gr + 128 + j);
                float2 xn = *(const float2*)(gr + 256 + j);
                float r0 = sigfast(xr.x + acc[0][nf][2 * m]);
                float z0 = sigfast(xz.x + acc[1][nf][2 * m]);
                float n0 = tanhfast(xn.x + r0 * (acc[2][nf][2 * m] + bn[j]));
                float h0 = (1.f - z0) * n0 + z0 * hreg[m][nf][0];
                float r1 = sigfast(xr.y + acc[0][nf][2 * m + 1]);
                float z1 = sigfast(xz.y + acc[1][nf][2 * m + 1]);
                float n1 = tanhfast(xn.y + r1 * (acc[2][nf][2 * m + 1] + bn[j + 1]));
                float h1 = (1.f - z1) * n1 + z1 * hreg[m][nf][1];
                hreg[m][nf][0] = h0; hreg[m][nf][1] = h1;
                unsigned hw = pack_bf16(h0, h1);
                Hnxt[(row << 6) + ((ct * 16 + nf * 4 + qid) ^ gsw)] = hw;
                if (wmix) g_mix[stream][row0 + row][t][ct * 16 + nf * 4 + qid] = hw;
            }
        }
        __syncthreads();   // Hnxt visible before next step's GEMM reads it
    }
}

// --------------------------------------------------------------- kernel 3 ---
// C1 = mix_c @ W_cls^T (no bias), bf16 in / bf16 out. 640 blocks, 3/SM.
__global__ __launch_bounds__(256, 3) void cls_kernel(const float* __restrict__ W_cls) {
    extern __shared__ unsigned smu[];
    unsigned* Wb = smu;              // [104][64] bf16x2 words, swizzled
    unsigned* Ab = smu + 104 * 64;   // [128][64] bf16x2 words, swizzled

    const int tid = threadIdx.x;
    const int row0 = blockIdx.x * 128;
    const unsigned* mixc = &g_mix[1][0][0][0];

    for (int i = tid; i < 104 * 64; i += 256) {
        int c = i >> 6, w = i & 63;
        float2 v;
        if (c < C_) v = *(const float2*)(W_cls + (size_t)c * 256 + 2 * w);
        else        v = make_float2(0.f, 0.f);
        Wb[(c << 6) + (w ^ ((c & 7) << 2))] = pack_bf16(v.x, v.y);
    }
    for (int i = tid; i < 128 * 64; i += 256) {
        int r = i >> 6, w = i & 63;
        Ab[(r << 6) + (w ^ ((r & 7) << 2))] = mixc[(size_t)(row0 + r) * 64 + w];
    }
    __syncthreads();

    const int warp = tid >> 5, lane = tid & 31;
    const int gid = lane >> 2, qid = lane & 3;
    const int gsw = gid << 2;
    const int ra0 = (warp * 16 + gid) << 6;
    const int ra1 = ra0 + (8 << 6);

    float acc[13][4];
#pragma unroll
    for (int nt = 0; nt < 13; nt++)
#pragma unroll
        for (int e = 0; e < 4; e++) acc[nt][e] = 0.f;

#pragma unroll
    for (int kb = 0; kb < 8; kb++) {
        const int k0 = kb * 8;
        unsigned a0 = Ab[ra0 + ((k0 + qid)     ^ gsw)];
        unsigned a1 = Ab[ra1 + ((k0 + qid)     ^ gsw)];
        unsigned a2 = Ab[ra0 + ((k0 + qid + 4) ^ gsw)];
        unsigned a3 = Ab[ra1 + ((k0 + qid + 4) ^ gsw)];
#pragma unroll
        for (int nt = 0; nt < 13; nt++) {
            const unsigned* wr = Wb + ((nt * 8 + gid) << 6);
            unsigned b0 = wr[(k0 + qid)     ^ gsw];
            unsigned b1 = wr[(k0 + qid + 4) ^ gsw];
            mma_bf16(acc[nt], a0, a1, a2, a3, b0, b1);
        }
    }

#pragma unroll
    for (int m = 0; m < 2; m++) {
        const int row = warp * 16 + gid + 8 * m;
        unsigned* cp = &g_C1[row0 + row][0];
#pragma unroll
        for (int nt = 0; nt < 13; nt++)
            cp[nt * 4 + qid] = pack_bf16(acc[nt][2 * m], acc[nt][2 * m + 1]);
    }
}

// --------------------------------------------------------------- kernel 4 ---
// per-batch: symmetric Gram on packed bf16 (8 vals per LDS.128), col-softmax,
// logits = P*C1(bf16) + bias, row-softmax. ~42.8 KB smem -> 4/SM.
#define UAW 68   // padded word stride for Uab (68 % 4 == 0)
__global__ __launch_bounds__(256, 4) void attn_kernel(const float* __restrict__ b_cls,
                                                      float* __restrict__ out) {
    extern __shared__ float sm[];
    unsigned* Uab = (unsigned*)sm;          // mix_a packed [40][UAW]
    float*    E   = sm + 40 * UAW;          // [40*40]
    float*    Z   = E + 1600;               // [40]
    unsigned* C1s = (unsigned*)(Z + 40);    // [40][52] packed
    float*    bs  = (float*)(C1s + 40 * CW_);   // [104]
    float*    L   = bs + CP_;               // logits [40][104]

    const int b = blockIdx.x, tid = threadIdx.x;
    const unsigned* pma = &g_mix[0][b][0][0];
    const unsigned* pc1 = &g_C1[b * T_][0];

    for (int i = tid; i < 40 * 64; i += 256) {
        int t = i >> 6, w = i & 63;
        Uab[t * UAW + w] = pma[i];
    }
    for (int i = tid; i < 40 * CW_ / 4; i += 256)
        *(uint4*)(C1s + 4 * i) = *(const uint4*)(pc1 + 4 * i);
    for (int i = tid; i < CP_; i += 256) bs[i] = (i < C_) ? b_cls[i] : 0.f;
    __syncthreads();

    // Symmetric Gram: 210 upper-triangle 2x2 tile tasks; write both mirrors.
    if (tid < 210) {
        int ib = 0, tk = tid;
        while (tk >= 20 - ib) { tk -= 20 - ib; ib++; }
        int jb = ib + tk;
        float a00 = 0, a01 = 0, a10 = 0, a11 = 0;
        const uint4* A0 = (const uint4*)(Uab + (2 * ib) * UAW);
        const uint4* A1 = (const uint4*)(Uab + (2 * ib + 1) * UAW);
        const uint4* B0 = (const uint4*)(Uab + (2 * jb) * UAW);
        const uint4* B1 = (const uint4*)(Uab + (2 * jb + 1) * UAW);
#pragma unroll 4
        for (int k8 = 0; k8 < 16; k8++) {
            float x0[8], x1[8], y0[8], y1[8];
            unp8(x0, A0[k8]); unp8(x1, A1[k8]);
            unp8(y0, B0[k8]); unp8(y1, B1[k8]);
#pragma unroll
            for (int i = 0; i < 8; i++) {
                a00 += x0[i] * y0[i];
                a01 += x0[i] * y1[i];
                a10 += x1[i] * y0[i];
                a11 += x1[i] * y1[i];
            }
        }
        float e00 = __expf(a00), e01 = __expf(a01);
        float e10 = __expf(a10), e11 = __expf(a11);
        E[(2 * ib)     * 40 + 2 * jb]     = e00;
        E[(2 * ib)     * 40 + 2 * jb + 1] = e01;
        E[(2 * ib + 1) * 40 + 2 * jb]     = e10;
        E[(2 * ib + 1) * 40 + 2 * jb + 1] = e11;
        E[(2 * jb)     * 40 + 2 * ib]     = e00;
        E[(2 * jb + 1) * 40 + 2 * ib]     = e01;
        E[(2 * jb)     * 40 + 2 * ib + 1] = e10;
        E[(2 * jb + 1) * 40 + 2 * ib + 1] = e11;
    }
    __syncthreads();

    if (tid < 40) {   // Z[t] = column sums (softmax dim=1)
        float z = 0.f;
        for (int s = 0; s < 40; s++) z += E[s * 40 + tid];
        Z[tid] = 1.f / z;
    }
    __syncthreads();
    for (int i = tid; i < 1600; i += 256) E[i] *= Z[i % 40];
    __syncthreads();

    // logits[s][c] = sum_t P[s][t] * C1[t][c] + b[c]; 4s x 4c tiles
    for (int task = tid; task < 260; task += 256) {
        int sb = task / 26, cq = task % 26;
        float acc[4][4];
#pragma unroll
        for (int i = 0; i < 4; i++)
#pragma unroll
            for (int q = 0; q < 4; q++) acc[i][q] = 0.f;
        const float* E0 = E + (4 * sb) * 40;
#pragma unroll 4
        for (int t = 0; t < 40; t++) {
            uint2 cw = *(const uint2*)(C1s + t * CW_ + 2 * cq);
            float c0 = bflo(cw.x), c1 = bfhi(cw.x), c2 = bflo(cw.y), c3 = bfhi(cw.y);
            float p0 = E0[t], p1 = E0[40 + t], p2 = E0[80 + t], p3 = E0[120 + t];
            acc[0][0] += p0 * c0; acc[0][1] += p0 * c1; acc[0][2] += p0 * c2; acc[0][3] += p0 * c3;
            acc[1][0] += p1 * c0; acc[1][1] += p1 * c1; acc[1][2] += p1 * c2; acc[1][3] += p1 * c3;
            acc[2][0] += p2 * c0; acc[2][1] += p2 * c1; acc[2][2] += p2 * c2; acc[2][3] += p2 * c3;
            acc[3][0] += p3 * c0; acc[3][1] += p3 * c1; acc[3][2] += p3 * c2; acc[3][3] += p3 * c3;
        }
#pragma unroll
        for (int i = 0; i < 4; i++)
#pragma unroll
            for (int q = 0; q < 4; q++)
                L[(4 * sb + i) * CP_ + 4 * cq + q] = acc[i][q] + bs[4 * cq + q];
    }
    __syncthreads();

    // per-row softmax over classes -> out
    {
        const int w = tid >> 5, lane = tid & 31;
        for (int s = w; s < 40; s += 8) {
            const float* Lr = L + s * CP_;
            float m = -1e30f;
            for (int c = lane; c < C_; c += 32) m = fmaxf(m, Lr[c]);
#pragma unroll
            for (int o = 16; o; o >>= 1) m = fmaxf(m, __shfl_xor_sync(~0u, m, o));
            float e[4]; int cnt = 0; float sum = 0.f;
            for (int c = lane; c < C_; c += 32) { float v = __expf(Lr[c] - m); e[cnt++] = v; sum += v; }
#pragma unroll
            for (int o = 16; o; o >>= 1) sum += __shfl_xor_sync(~0u, sum, o);
            float r = 1.f / sum; cnt = 0;
            float* op = out + ((size_t)b * T_ + s) * C_;
            for (int c = lane; c < C_; c += 32) op[c] = e[cnt++] * r;
        }
    }
}

// ------------------------------------------------------------------ launch --
#define GX_SMEM   ((192 * 64 + 64 * 64 + 192) * 4)
#define SCAN_SMEM ((384 * 64 + 2 * 32 * 64 + 128) * 4)
#define CLS_SMEM  ((104 * 64 + 128 * 64) * 4)
#define ATTN_SMEM ((40 * UAW + 1600 + 40 + 40 * CW_ + CP_ + 40 * CP_) * 4)

extern "C" void kernel_launch(void* const* d_in, const int* in_sizes, int n_in,
                              void* d_out, int out_size) {
    const int*   tokens = (const int*)  d_in[0];
    const float* emb_c  = (const float*)d_in[1];
    const float* emb_a  = (const float*)d_in[2];
    const float* W_ih   = (const float*)d_in[3];
    const float* W_hh   = (const float*)d_in[4];
    const float* b_ih   = (const float*)d_in[5];
    const float* b_hh   = (const float*)d_in[6];
    const float* W_cls  = (const float*)d_in[7];
    const float* b_cls  = (const float*)d_in[8];
    float* out = (float*)d_out;

    cudaFuncSetAttribute(tok_gx_kernel, cudaFuncAttributeMaxDynamicSharedMemorySize, GX_SMEM);
    cudaFuncSetAttribute(scan_kernel,   cudaFuncAttributeMaxDynamicSharedMemorySize, SCAN_SMEM);
    cudaFuncSetAttribute(cls_kernel,    cudaFuncAttributeMaxDynamicSharedMemorySize, CLS_SMEM);
    cudaFuncSetAttribute(attn_kernel,   cudaFuncAttributeMaxDynamicSharedMemorySize, ATTN_SMEM);

    tok_gx_kernel<<<dim3(70, 2, 2), 256, GX_SMEM>>>(emb_a, emb_c, W_ih, b_ih, b_hh);
    scan_kernel  <<<256,            256, SCAN_SMEM>>>(W_hh, b_hh, tokens);
    cls_kernel   <<<BT_ / 128,      256, CLS_SMEM>>>(W_cls);
    attn_kernel  <<<B_,             256, ATTN_SMEM>>>(b_cls, out);
}

// round 8
// speedup vs baseline: 4.1594x; 1.0557x over previous
#include <cuda_runtime.h>
#include <cuda_fp16.h>

#define B_  2048
#define T_  40
#define H_  128
#define V_  4450
#define VP_ 4480   // 70 * 64, padded vocab
#define C_  102
#define CP_ 104    // padded classes (13 * 8)
#define CW_ 52     // CP_/2 bf16x2 words
#define G3  384    // 3H
#define GW_ 192    // G3/2 fp16x2 words
#define BT_ (B_ * T_)

// Scratch: __device__ globals (the sanctioned no-alloc workaround)
__device__ unsigned g_tokG[2][VP_][GW_];   // per-token input gates, fp16x2 (b_ih + b_hh[r,z] folded)
__device__ unsigned g_mix [2][B_][T_][64]; // mixed fwd/bwd states, bf16x2 words
__device__ unsigned g_C1  [BT_][CW_];      // mix_c @ W_cls^T (no bias), bf16x2 words

// ---------------------------------------------------------------- helpers ---
__device__ __forceinline__ unsigned pack_bf16(float lo, float hi) {
    unsigned r; asm("cvt.rn.bf16x2.f32 %0, %1, %2;" : "=r"(r) : "f"(hi), "f"(lo)); return r;
}
__device__ __forceinline__ unsigned pack_f16(float lo, float hi) {
    unsigned r; asm("cvt.rn.f16x2.f32 %0, %1, %2;" : "=r"(r) : "f"(hi), "f"(lo)); return r;
}
__device__ __forceinline__ float2 h2f(unsigned u) {
    __half2 h = *reinterpret_cast<__half2*>(&u);
    return __half22float2(h);
}
__device__ __forceinline__ float bflo(unsigned u) { return __uint_as_float(u << 16); }
__device__ __forceinline__ float bfhi(unsigned u) { return __uint_as_float(u & 0xffff0000u); }
__device__ __forceinline__ void unp8(float* f, uint4 v) {
    f[0] = bflo(v.x); f[1] = bfhi(v.x); f[2] = bflo(v.y); f[3] = bfhi(v.y);
    f[4] = bflo(v.z); f[5] = bfhi(v.z); f[6] = bflo(v.w); f[7] = bfhi(v.w);
}
__device__ __forceinline__ float tanhfast(float x) {
    float y; asm("tanh.approx.f32 %0, %1;" : "=f"(y) : "f"(x)); return y;
}
__device__ __forceinline__ float sigfast(float x) { return 0.5f * tanhfast(0.5f * x) + 0.5f; }

__device__ __forceinline__ void mma_bf16(float* d,
                                         unsigned a0, unsigned a1, unsigned a2, unsigned a3,
                                         unsigned b0, unsigned b1) {
    asm volatile(
        "mma.sync.aligned.m16n8k16.row.col.f32.bf16.bf16.f32 "
        "{%0,%1,%2,%3},{%4,%5,%6,%7},{%8,%9},{%0,%1,%2,%3};"
        : "+f"(d[0]), "+f"(d[1]), "+f"(d[2]), "+f"(d[3])
        : "r"(a0), "r"(a1), "r"(a2), "r"(a3), "r"(b0), "r"(b1));
}

// --------------------------------------------------------------- kernel 1 ---
// Token-gate table via bf16 MMA, fp16x2 output. 64 vocab rows x 192 gate-cols
// per block. grid (70, 2 streams, 2 halves) = 280 blocks, 2/SM.
__global__ __launch_bounds__(256, 2) void tok_gx_kernel(const float* __restrict__ emb_a,
                                                        const float* __restrict__ emb_c,
                                                        const float* __restrict__ W_ih,
                                                        const float* __restrict__ b_ih,
                                                        const float* __restrict__ b_hh) {
    extern __shared__ unsigned smu[];
    unsigned* Wb  = smu;                     // [192][64] bf16x2 words, swizzled
    unsigned* Ab  = smu + 192 * 64;          // [64][64] bf16x2 words, swizzled
    float*    bias = (float*)(Ab + 64 * 64); // [192]

    const int tid = threadIdx.x;
    const int tile = blockIdx.x, stream = blockIdx.y, half = blockIdx.z;
    const float* emb = (stream == 0) ? emb_a : emb_c;
    const int row0 = tile * 64;
    const int nbase = half * 192;

    for (int i = tid; i < 192 * 64; i += 256) {
        int n = i >> 6, w = i & 63;
        float2 v = *(const float2*)(W_ih + (size_t)(nbase + n) * 128 + 2 * w);
        Wb[(n << 6) + (w ^ ((n & 7) << 2))] = pack_bf16(v.x, v.y);
    }
    for (int i = tid; i < 192; i += 256) {
        int n = nbase + i;
        bias[i] = b_ih[n] + (n < 256 ? b_hh[n] : 0.f);
    }
    for (int i = tid; i < 64 * 64; i += 256) {
        int r = i >> 6, w = i & 63;
        int vr = row0 + r; if (vr >= V_) vr = V_ - 1;
        float2 v = *(const float2*)(emb + (size_t)vr * H_ + 2 * w);
        Ab[(r << 6) + (w ^ ((r & 7) << 2))] = pack_bf16(v.x, v.y);
    }
    __syncthreads();

    const int warp = tid >> 5, lane = tid & 31;
    const int rt = warp & 3, ct = warp >> 2;
    const int gid = lane >> 2, qid = lane & 3;
    const int gsw = gid << 2;
    const int ra0 = (rt * 16 + gid) << 6;
    const int ra1 = ra0 + (8 << 6);

    float acc[12][4];
#pragma unroll
    for (int nt = 0; nt < 12; nt++)
#pragma unroll
        for (int e = 0; e < 4; e++) acc[nt][e] = 0.f;

#pragma unroll
    for (int kb = 0; kb < 8; kb++) {
        const int k0 = kb * 8;
        unsigned a0 = Ab[ra0 + ((k0 + qid)     ^ gsw)];
        unsigned a1 = Ab[ra1 + ((k0 + qid)     ^ gsw)];
        unsigned a2 = Ab[ra0 + ((k0 + qid + 4) ^ gsw)];
        unsigned a3 = Ab[ra1 + ((k0 + qid + 4) ^ gsw)];
#pragma unroll
        for (int nt = 0; nt < 12; nt++) {
            const unsigned* wr = Wb + ((ct * 96 + nt * 8 + gid) << 6);
            unsigned b0 = wr[(k0 + qid)     ^ gsw];
            unsigned b1 = wr[(k0 + qid + 4) ^ gsw];
            mma_bf16(acc[nt], a0, a1, a2, a3, b0, b1);
        }
    }

#pragma unroll
    for (int m = 0; m < 2; m++) {
        const int row = rt * 16 + gid + 8 * m;
        unsigned* gp = &g_tokG[stream][row0 + row][half * 96];
#pragma unroll
        for (int nt = 0; nt < 12; nt++) {
            const int nl = ct * 96 + nt * 8 + qid * 2;  // local col (0..191)
            gp[ct * 48 + nt * 4 + qid] =
                pack_f16(acc[nt][2 * m] + bias[nl], acc[nt][2 * m + 1] + bias[nl + 1]);
        }
    }
}

// --------------------------------------------------------------- kernel 2 ---
// 4 GRU scans, bf16 MMA. Block = (scan, 32-row tile), 256 blocks, 2/SM.
// fp32 h carry in registers; double-buffered bf16 Hs -> ONE barrier per step.
// Gate words (fp16x2) PREFETCHED from the L2-resident table BEFORE the GEMM so
// their latency hides under the MMA work.
__global__ __launch_bounds__(256, 2) void scan_kernel(const float* __restrict__ W_hh,
                                                      const float* __restrict__ b_hh,
                                                      const int* __restrict__ tokens) {
    extern __shared__ unsigned smu[];
    unsigned* Ws   = smu;                       // 384 * 64 bf16x2 words, swizzled
    unsigned* Hbuf = smu + 384 * 64;            // 2 x [32*64] words
    float*    bn   = (float*)(Hbuf + 2 * 32 * 64);  // 128 = b_hh for n gate

    const int tid = threadIdx.x;
    const int scan = blockIdx.x >> 6, tile = blockIdx.x & 63;
    const int stream = scan >> 1, rev = scan & 1;
    const int row0 = tile * 32;

    for (int i = tid; i < 384 * 64; i += 256) {
        int n = i >> 6, w = i & 63;
        float2 v = *(const float2*)(W_hh + n * 128 + 2 * w);
        Ws[(n << 6) + (w ^ ((n & 7) << 2))] = pack_bf16(v.x, v.y);
    }
    for (int i = tid; i < 32 * 64; i += 256) Hbuf[i] = 0u;   // buffer 0 only
    if (tid < 128) bn[tid] = b_hh[256 + tid];
    __syncthreads();

    const int warp = tid >> 5, lane = tid & 31;
    const int rt = warp & 1, ct = warp >> 1;
    const int gid = lane >> 2, qid = lane & 3;
    const int gsw = gid << 2;
    const int raA = (rt * 16 + gid) << 6;
    const int raB = raA + (8 << 6);
    const unsigned* tokG = &g_tokG[stream][0][0];
    const int rbase = row0 + rt * 16 + gid;
    const int wbase = ct * 16 + qid;    // word offset of this thread's col pair per nf=0

    float hreg[2][4][2];
#pragma unroll
    for (int m = 0; m < 2; m++)
#pragma unroll
        for (int nf = 0; nf < 4; nf++) { hreg[m][nf][0] = 0.f; hreg[m][nf][1] = 0.f; }

    for (int step = 0; step < 40; step++) {
        const int t = rev ? 39 - step : step;
        const int tk0 = __ldg(&tokens[(rbase)     * T_ + t]);
        const int tk1 = __ldg(&tokens[(rbase + 8) * T_ + t]);
        unsigned* Hcur = Hbuf + ((step & 1) ? 32 * 64 : 0);
        unsigned* Hnxt = Hbuf + ((step & 1) ? 0 : 32 * 64);

        // PREFETCH all gate words for this step (independent of the GEMM)
        const unsigned* gr0 = tokG + (size_t)tk0 * GW_ + wbase;
        const unsigned* gr1 = tokG + (size_t)tk1 * GW_ + wbase;
        unsigned gw[2][4][3];
#pragma unroll
        for (int nf = 0; nf < 4; nf++)
#pragma unroll
            for (int g = 0; g < 3; g++) {
                gw[0][nf][g] = __ldg(gr0 + nf * 4 + g * 64);
                gw[1][nf][g] = __ldg(gr1 + nf * 4 + g * 64);
            }

        float acc[3][4][4];
#pragma unroll
        for (int g = 0; g < 3; g++)
#pragma unroll
            for (int nf = 0; nf < 4; nf++)
#pragma unroll
                for (int e = 0; e < 4; e++) acc[g][nf][e] = 0.f;

#pragma unroll
        for (int kb = 0; kb < 8; kb++) {
            const int k0 = kb * 8;
            unsigned a0 = Hcur[raA + ((k0 + qid)     ^ gsw)];
            unsigned a1 = Hcur[raB + ((k0 + qid)     ^ gsw)];
            unsigned a2 = Hcur[raA + ((k0 + qid + 4) ^ gsw)];
            unsigned a3 = Hcur[raB + ((k0 + qid + 4) ^ gsw)];
#pragma unroll
            for (int g = 0; g < 3; g++)
#pragma unroll
                for (int nf = 0; nf < 4; nf++) {
                    const unsigned* wr = Ws + ((g * 128 + ct * 32 + nf * 8 + gid) << 6);
                    unsigned b0 = wr[(k0 + qid)     ^ gsw];
                    unsigned b1 = wr[(k0 + qid + 4) ^ gsw];
                    mma_bf16(acc[g][nf], a0, a1, a2, a3, b0, b1);
                }
        }

        const bool wmix = (step >= 20);   // fwd: t>=20; rev: t<20 -> both step>=20
#pragma unroll
        for (int m = 0; m < 2; m++) {
            const int row = rt * 16 + gid + 8 * m;
#pragma unroll
            for (int nf = 0; nf < 4; nf++) {
                const int j = ct * 32 + nf * 8 + 2 * qid;
                float2 xr = h2f(gw[m][nf][0]);
                float2 xz = h2f(gw[m][nf][1]);
                float2 xn = h2f(gw[m][nf][2]);
                float r0 = sigfast(xr.x + acc[0][nf][2 * m]);
                float z0 = sigfast(xz.x + acc[1][nf][2 * m]);
                float n0 = tanhfast(xn.x + r0 * (acc[2][nf][2 * m] + bn[j]));
                float h0 = (1.f - z0) * n0 + z0 * hreg[m][nf][0];
                float r1 = sigfast(xr.y + acc[0][nf][2 * m + 1]);
                float z1 = sigfast(xz.y + acc[1][nf][2 * m + 1]);
                float n1 = tanhfast(xn.y + r1 * (acc[2][nf][2 * m + 1] + bn[j + 1]));
                float h1 = (1.f - z1) * n1 + z1 * hreg[m][nf][1];
                hreg[m][nf][0] = h0; hreg[m][nf][1] = h1;
                unsigned hw = pack_bf16(h0, h1);
                Hnxt[(row << 6) + ((ct * 16 + nf * 4 + qid) ^ gsw)] = hw;
                if (wmix) g_mix[stream][row0 + row][t][ct * 16 + nf * 4 + qid] = hw;
            }
        }
        __syncthreads();   // Hnxt visible before next step's GEMM reads it
    }
}

// --------------------------------------------------------------- kernel 3 ---
// C1 = mix_c @ W_cls^T (no bias), bf16 in / bf16 out. 640 blocks, 3/SM.
__global__ __launch_bounds__(256, 3) void cls_kernel(const float* __restrict__ W_cls) {
    extern __shared__ unsigned smu[];
    unsigned* Wb = smu;              // [104][64] bf16x2 words, swizzled
    unsigned* Ab = smu + 104 * 64;   // [128][64] bf16x2 words, swizzled

    const int tid = threadIdx.x;
    const int row0 = blockIdx.x * 128;
    const unsigned* mixc = &g_mix[1][0][0][0];

    for (int i = tid; i < 104 * 64; i += 256) {
        int c = i >> 6, w = i & 63;
        float2 v;
        if (c < C_) v = *(const float2*)(W_cls + (size_t)c * 256 + 2 * w);
        else        v = make_float2(0.f, 0.f);
        Wb[(c << 6) + (w ^ ((c & 7) << 2))] = pack_bf16(v.x, v.y);
    }
    for (int i = tid; i < 128 * 64; i += 256) {
        int r = i >> 6, w = i & 63;
        Ab[(r << 6) + (w ^ ((r & 7) << 2))] = mixc[(size_t)(row0 + r) * 64 + w];
    }
    __syncthreads();

    const int warp = tid >> 5, lane = tid & 31;
    const int gid = lane >> 2, qid = lane & 3;
    const int gsw = gid << 2;
    const int ra0 = (warp * 16 + gid) << 6;
    const int ra1 = ra0 + (8 << 6);

    float acc[13][4];
#pragma unroll
    for (int nt = 0; nt < 13; nt++)
#pragma unroll
        for (int e = 0; e < 4; e++) acc[nt][e] = 0.f;

#pragma unroll
    for (int kb = 0; kb < 8; kb++) {
        const int k0 = kb * 8;
        unsigned a0 = Ab[ra0 + ((k0 + qid)     ^ gsw)];
        unsigned a1 = Ab[ra1 + ((k0 + qid)     ^ gsw)];
        unsigned a2 = Ab[ra0 + ((k0 + qid + 4) ^ gsw)];
        unsigned a3 = Ab[ra1 + ((k0 + qid + 4) ^ gsw)];
#pragma unroll
        for (int nt = 0; nt < 13; nt++) {
            const unsigned* wr = Wb + ((nt * 8 + gid) << 6);
            unsigned b0 = wr[(k0 + qid)     ^ gsw];
            unsigned b1 = wr[(k0 + qid + 4) ^ gsw];
            mma_bf16(acc[nt], a0, a1, a2, a3, b0, b1);
        }
    }

#pragma unroll
    for (int m = 0; m < 2; m++) {
        const int row = warp * 16 + gid + 8 * m;
        unsigned* cp = &g_C1[row0 + row][0];
#pragma unroll
        for (int nt = 0; nt < 13; nt++)
            cp[nt * 4 + qid] = pack_bf16(acc[nt][2 * m], acc[nt][2 * m + 1]);
    }
}

// --------------------------------------------------------------- kernel 4 ---
// per-batch: symmetric Gram on packed bf16 (8 vals per LDS.128), col-softmax,
// logits = P*C1(bf16) + bias, row-softmax. ~42.8 KB smem -> 4/SM.
#define UAW 68   // padded word stride for Uab (68 % 4 == 0)
__global__ __launch_bounds__(256, 4) void attn_kernel(const float* __restrict__ b_cls,
                                                      float* __restrict__ out) {
    extern __shared__ float sm[];
    unsigned* Uab = (unsigned*)sm;          // mix_a packed [40][UAW]
    float*    E   = sm + 40 * UAW;          // [40*40]
    float*    Z   = E + 1600;               // [40]
    unsigned* C1s = (unsigned*)(Z + 40);    // [40][52] packed
    float*    bs  = (float*)(C1s + 40 * CW_);   // [104]
    float*    L   = bs + CP_;               // logits [40][104]

    const int b = blockIdx.x, tid = threadIdx.x;
    const unsigned* pma = &g_mix[0][b][0][0];
    const unsigned* pc1 = &g_C1[b * T_][0];

    for (int i = tid; i < 40 * 64; i += 256) {
        int t = i >> 6, w = i & 63;
        Uab[t * UAW + w] = pma[i];
    }
    for (int i = tid; i < 40 * CW_ / 4; i += 256)
        *(uint4*)(C1s + 4 * i) = *(const uint4*)(pc1 + 4 * i);
    for (int i = tid; i < CP_; i += 256) bs[i] = (i < C_) ? b_cls[i] : 0.f;
    __syncthreads();

    // Symmetric Gram: 210 upper-triangle 2x2 tile tasks; write both mirrors.
    if (tid < 210) {
        int ib = 0, tk = tid;
        while (tk >= 20 - ib) { tk -= 20 - ib; ib++; }
        int jb = ib + tk;
        float a00 = 0, a01 = 0, a10 = 0, a11 = 0;
        const uint4* A0 = (const uint4*)(Uab + (2 * ib) * UAW);
        const uint4* A1 = (const uint4*)(Uab + (2 * ib + 1) * UAW);
        const uint4* B0 = (const uint4*)(Uab + (2 * jb) * UAW);
        const uint4* B1 = (const uint4*)(Uab + (2 * jb + 1) * UAW);
#pragma unroll 4
        for (int k8 = 0; k8 < 16; k8++) {
            float x0[8], x1[8], y0[8], y1[8];
            unp8(x0, A0[k8]); unp8(x1, A1[k8]);
            unp8(y0, B0[k8]); unp8(y1, B1[k8]);
#pragma unroll
            for (int i = 0; i < 8; i++) {
                a00 += x0[i] * y0[i];
                a01 += x0[i] * y1[i];
                a10 += x1[i] * y0[i];
                a11 += x1[i] * y1[i];
            }
        }
        float e00 = __expf(a00), e01 = __expf(a01);
        float e10 = __expf(a10), e11 = __expf(a11);
        E[(2 * ib)     * 40 + 2 * jb]     = e00;
        E[(2 * ib)     * 40 + 2 * jb + 1] = e01;
        E[(2 * ib + 1) * 40 + 2 * jb]     = e10;
        E[(2 * ib + 1) * 40 + 2 * jb + 1] = e11;
        E[(2 * jb)     * 40 + 2 * ib]     = e00;
        E[(2 * jb + 1) * 40 + 2 * ib]     = e01;
        E[(2 * jb)     * 40 + 2 * ib + 1] = e10;
        E[(2 * jb + 1) * 40 + 2 * ib + 1] = e11;
    }
    __syncthreads();

    if (tid < 40) {   // Z[t] = column sums (softmax dim=1)
        float z = 0.f;
        for (int s = 0; s < 40; s++) z += E[s * 40 + tid];
        Z[tid] = 1.f / z;
    }
    __syncthreads();
    for (int i = tid; i < 1600; i += 256) E[i] *= Z[i % 40];
    __syncthreads();

    // logits[s][c] = sum_t P[s][t] * C1[t][c] + b[c]; 4s x 4c tiles
    for (int task = tid; task < 260; task += 256) {
        int sb = task / 26, cq = task % 26;
        float acc[4][4];
#pragma unroll
        for (int i = 0; i < 4; i++)
#pragma unroll
            for (int q = 0; q < 4; q++) acc[i][q] = 0.f;
        const float* E0 = E + (4 * sb) * 40;
#pragma unroll 4
        for (int t = 0; t < 40; t++) {
            uint2 cw = *(const uint2*)(C1s + t * CW_ + 2 * cq);
            float c0 = bflo(cw.x), c1 = bfhi(cw.x), c2 = bflo(cw.y), c3 = bfhi(cw.y);
            float p0 = E0[t], p1 = E0[40 + t], p2 = E0[80 + t], p3 = E0[120 + t];
            acc[0][0] += p0 * c0; acc[0][1] += p0 * c1; acc[0][2] += p0 * c2; acc[0][3] += p0 * c3;
            acc[1][0] += p1 * c0; acc[1][1] += p1 * c1; acc[1][2] += p1 * c2; acc[1][3] += p1 * c3;
            acc[2][0] += p2 * c0; acc[2][1] += p2 * c1; acc[2][2] += p2 * c2; acc[2][3] += p2 * c3;
            acc[3][0] += p3 * c0; acc[3][1] += p3 * c1; acc[3][2] += p3 * c2; acc[3][3] += p3 * c3;
        }
#pragma unroll
        for (int i = 0; i < 4; i++)
#pragma unroll
            for (int q = 0; q < 4; q++)
                L[(4 * sb + i) * CP_ + 4 * cq + q] = acc[i][q] + bs[4 * cq + q];
    }
    __syncthreads();

    // per-row softmax over classes -> out
    {
        const int w = tid >> 5, lane = tid & 31;
        for (int s = w; s < 40; s += 8) {
            const float* Lr = L + s * CP_;
            float m = -1e30f;
            for (int c = lane; c < C_; c += 32) m = fmaxf(m, Lr[c]);
#pragma unroll
            for (int o = 16; o; o >>= 1) m = fmaxf(m, __shfl_xor_sync(~0u, m, o));
            float e[4]; int cnt = 0; float sum = 0.f;
            for (int c = lane; c < C_; c += 32) { float v = __expf(Lr[c] - m); e[cnt++] = v; sum += v; }
#pragma unroll
            for (int o = 16; o; o >>= 1) sum += __shfl_xor_sync(~0u, sum, o);
            float r = 1.f / sum; cnt = 0;
            float* op = out + ((size_t)b * T_ + s) * C_;
            for (int c = lane; c < C_; c += 32) op[c] = e[cnt++] * r;
        }
    }
}

// ------------------------------------------------------------------ launch --
#define GX_SMEM   ((192 * 64 + 64 * 64 + 192) * 4)
#define SCAN_SMEM ((384 * 64 + 2 * 32 * 64 + 128) * 4)
#define CLS_SMEM  ((104 * 64 + 128 * 64) * 4)
#define ATTN_SMEM ((40 * UAW + 1600 + 40 + 40 * CW_ + CP_ + 40 * CP_) * 4)

extern "C" void kernel_launch(void* const* d_in, const int* in_sizes, int n_in,
                              void* d_out, int out_size) {
    const int*   tokens = (const int*)  d_in[0];
    const float* emb_c  = (const float*)d_in[1];
    const float* emb_a  = (const float*)d_in[2];
    const float* W_ih   = (const float*)d_in[3];
    const float* W_hh   = (const float*)d_in[4];
    const float* b_ih   = (const float*)d_in[5];
    const float* b_hh   = (const float*)d_in[6];
    const float* W_cls  = (const float*)d_in[7];
    const float* b_cls  = (const float*)d_in[8];
    float* out = (float*)d_out;

    cudaFuncSetAttribute(tok_gx_kernel, cudaFuncAttributeMaxDynamicSharedMemorySize, GX_SMEM);
    cudaFuncSetAttribute(scan_kernel,   cudaFuncAttributeMaxDynamicSharedMemorySize, SCAN_SMEM);
    cudaFuncSetAttribute(cls_kernel,    cudaFuncAttributeMaxDynamicSharedMemorySize, CLS_SMEM);
    cudaFuncSetAttribute(attn_kernel,   cudaFuncAttributeMaxDynamicSharedMemorySize, ATTN_SMEM);

    tok_gx_kernel<<<dim3(70, 2, 2), 256, GX_SMEM>>>(emb_a, emb_c, W_ih, b_ih, b_hh);
    scan_kernel  <<<256,            256, SCAN_SMEM>>>(W_hh, b_hh, tokens);
    cls_kernel   <<<BT_ / 128,      256, CLS_SMEM>>>(W_cls);
    attn_kernel  <<<B_,             256, ATTN_SMEM>>>(b_cls, out);
}

// round 11
// speedup vs baseline: 4.2375x; 1.0188x over previous
#include <cuda_runtime.h>
#include <cuda_fp16.h>

#define B_  2048
#define T_  40
#define H_  128
#define V_  4450
#define VP_ 4480   // 70 * 64, padded vocab
#define C_  102
#define CP_ 104    // padded classes (13 * 8)
#define CW_ 52     // CP_/2 f16x2 words
#define G3  384    // 3H
#define GW_ 192    // G3/2 f16x2 words
#define BT_ (B_ * T_)

// Scratch: __device__ globals (the sanctioned no-alloc workaround)
__device__ unsigned g_tokG[2][VP_][GW_];   // per-token input gates, f16x2 (b_ih + b_hh[r,z] folded)
__device__ unsigned g_mix [2][B_][T_][64]; // mixed fwd/bwd states, f16x2 words
__device__ unsigned g_C1  [BT_][CW_];      // mix_c @ W_cls^T (no bias), f16x2 words

// ---------------------------------------------------------------- helpers ---
__device__ __forceinline__ unsigned pack_f16(float lo, float hi) {
    unsigned r; asm("cvt.rn.f16x2.f32 %0, %1, %2;" : "=r"(r) : "f"(hi), "f"(lo)); return r;
}
__device__ __forceinline__ __half2 u2h2(unsigned u) { return *reinterpret_cast<__half2*>(&u); }
__device__ __forceinline__ unsigned h22u(__half2 h) { return *reinterpret_cast<unsigned*>(&h); }
__device__ __forceinline__ float2 h2f(unsigned u) { return __half22float2(u2h2(u)); }
__device__ __forceinline__ __half2 tanh2(__half2 x) {
    unsigned u = h22u(x), y;
    asm("tanh.approx.f16x2 %0, %1;" : "=r"(y) : "r"(u));
    return u2h2(y);
}

__device__ __forceinline__ void mma_f16(float* d,
                                        unsigned a0, unsigned a1, unsigned a2, unsigned a3,
                                        unsigned b0, unsigned b1) {
    asm volatile(
        "mma.sync.aligned.m16n8k16.row.col.f32.f16.f16.f32 "
        "{%0,%1,%2,%3},{%4,%5,%6,%7},{%8,%9},{%0,%1,%2,%3};"
        : "+f"(d[0]), "+f"(d[1]), "+f"(d[2]), "+f"(d[3])
        : "r"(a0), "r"(a1), "r"(a2), "r"(a3), "r"(b0), "r"(b1));
}

// --------------------------------------------------------------- kernel 1 ---
// Token-gate table via f16 MMA, f16x2 output. 64 vocab rows x 192 gate-cols
// per block. grid (70, 2 streams, 2 halves) = 280 blocks, 2/SM.
__global__ __launch_bounds__(256, 2) void tok_gx_kernel(const float* __restrict__ emb_a,
                                                        const float* __restrict__ emb_c,
                                                        const float* __restrict__ W_ih,
                                                        const float* __restrict__ b_ih,
                                                        const float* __restrict__ b_hh) {
    extern __shared__ unsigned smu[];
    unsigned* Wb  = smu;                     // [192][64] f16x2 words, swizzled
    unsigned* Ab  = smu + 192 * 64;          // [64][64] f16x2 words, swizzled
    float*    bias = (float*)(Ab + 64 * 64); // [192]

    const int tid = threadIdx.x;
    const int tile = blockIdx.x, stream = blockIdx.y, half = blockIdx.z;
    const float* emb = (stream == 0) ? emb_a : emb_c;
    const int row0 = tile * 64;
    const int nbase = half * 192;

    for (int i = tid; i < 192 * 64; i += 256) {
        int n = i >> 6, w = i & 63;
        float2 v = *(const float2*)(W_ih + (size_t)(nbase + n) * 128 + 2 * w);
        Wb[(n << 6) + (w ^ ((n & 7) << 2))] = pack_f16(v.x, v.y);
    }
    for (int i = tid; i < 192; i += 256) {
        int n = nbase + i;
        bias[i] = b_ih[n] + (n < 256 ? b_hh[n] : 0.f);
    }
    for (int i = tid; i < 64 * 64; i += 256) {
        int r = i >> 6, w = i & 63;
        int vr = row0 + r; if (vr >= V_) vr = V_ - 1;
        float2 v = *(const float2*)(emb + (size_t)vr * H_ + 2 * w);
        Ab[(r << 6) + (w ^ ((r & 7) << 2))] = pack_f16(v.x, v.y);
    }
    __syncthreads();

    const int warp = tid >> 5, lane = tid & 31;
    const int rt = warp & 3, ct = warp >> 2;
    const int gid = lane >> 2, qid = lane & 3;
    const int gsw = gid << 2;
    const int ra0 = (rt * 16 + gid) << 6;
    const int ra1 = ra0 + (8 << 6);

    float acc[12][4];
#pragma unroll
    for (int nt = 0; nt < 12; nt++)
#pragma unroll
        for (int e = 0; e < 4; e++) acc[nt][e] = 0.f;

#pragma unroll
    for (int kb = 0; kb < 8; kb++) {
        const int k0 = kb * 8;
        unsigned a0 = Ab[ra0 + ((k0 + qid)     ^ gsw)];
        unsigned a1 = Ab[ra1 + ((k0 + qid)     ^ gsw)];
        unsigned a2 = Ab[ra0 + ((k0 + qid + 4) ^ gsw)];
        unsigned a3 = Ab[ra1 + ((k0 + qid + 4) ^ gsw)];
#pragma unroll
        for (int nt = 0; nt < 12; nt++) {
            const unsigned* wr = Wb + ((ct * 96 + nt * 8 + gid) << 6);
            unsigned b0 = wr[(k0 + qid)     ^ gsw];
            unsigned b1 = wr[(k0 + qid + 4) ^ gsw];
            mma_f16(acc[nt], a0, a1, a2, a3, b0, b1);
        }
    }

#pragma unroll
    for (int m = 0; m < 2; m++) {
        const int row = rt * 16 + gid + 8 * m;
        unsigned* gp = &g_tokG[stream][row0 + row][half * 96];
#pragma unroll
        for (int nt = 0; nt < 12; nt++) {
            const int nl = ct * 96 + nt * 8 + qid * 2;  // local col (0..191)
            gp[ct * 48 + nt * 4 + qid] =
                pack_f16(acc[nt][2 * m] + bias[nl], acc[nt][2 * m + 1] + bias[nl + 1]);
        }
    }
}

// --------------------------------------------------------------- kernel 2 ---
// 4 GRU scans, f16 MMA. Block = (scan, 32-row tile), 256 blocks, 2/SM.
// Packed f16x2 h carry in registers; double-buffered f16 Hs, ONE barrier/step.
// Gate words prefetched before the GEMM; epilogue entirely in f16x2 with
// tanh.approx.f16x2 -> MUFU count halved vs scalar.
__global__ __launch_bounds__(256, 2) void scan_kernel(const float* __restrict__ W_hh,
                                                      const float* __restrict__ b_hh,
                                                      const int* __restrict__ tokens) {
    extern __shared__ unsigned smu[];
    unsigned* Ws   = smu;                       // 384 * 64 f16x2 words, swizzled
    unsigned* Hbuf = smu + 384 * 64;            // 2 x [32*64] words
    unsigned* bnw  = Hbuf + 2 * 32 * 64;        // 64 f16x2 = b_hh for n gate

    const int tid = threadIdx.x;
    const int scan = blockIdx.x >> 6, tile = blockIdx.x & 63;
    const int stream = scan >> 1, rev = scan & 1;
    const int row0 = tile * 32;

    for (int i = tid; i < 384 * 64; i += 256) {
        int n = i >> 6, w = i & 63;
        float2 v = *(const float2*)(W_hh + n * 128 + 2 * w);
        Ws[(n << 6) + (w ^ ((n & 7) << 2))] = pack_f16(v.x, v.y);
    }
    for (int i = tid; i < 32 * 64; i += 256) Hbuf[i] = 0u;   // buffer 0 only
    if (tid < 64) bnw[tid] = pack_f16(b_hh[256 + 2 * tid], b_hh[256 + 2 * tid + 1]);
    __syncthreads();

    const int warp = tid >> 5, lane = tid & 31;
    const int rt = warp & 1, ct = warp >> 1;
    const int gid = lane >> 2, qid = lane & 3;
    const int gsw = gid << 2;
    const int raA = (rt * 16 + gid) << 6;
    const int raB = raA + (8 << 6);
    const unsigned* tokG = &g_tokG[stream][0][0];
    const int rbase = row0 + rt * 16 + gid;
    const int wbase = ct * 16 + qid;    // word offset of this thread's col pair at nf=0

    const __half2 chalf = __floats2half2_rn(0.5f, 0.5f);
    __half2 hreg[2][4];
#pragma unroll
    for (int m = 0; m < 2; m++)
#pragma unroll
        for (int nf = 0; nf < 4; nf++) hreg[m][nf] = __floats2half2_rn(0.f, 0.f);

    for (int step = 0; step < 40; step++) {
        const int t = rev ? 39 - step : step;
        const int tk0 = __ldg(&tokens[(rbase)     * T_ + t]);
        const int tk1 = __ldg(&tokens[(rbase + 8) * T_ + t]);
        unsigned* Hcur = Hbuf + ((step & 1) ? 32 * 64 : 0);
        unsigned* Hnxt = Hbuf + ((step & 1) ? 0 : 32 * 64);

        // PREFETCH all gate words for this step (independent of the GEMM)
        const unsigned* gr0 = tokG + (size_t)tk0 * GW_ + wbase;
        const unsigned* gr1 = tokG + (size_t)tk1 * GW_ + wbase;
        unsigned gw[2][4][3];
#pragma unroll
        for (int nf = 0; nf < 4; nf++)
#pragma unroll
            for (int g = 0; g < 3; g++) {
                gw[0][nf][g] = __ldg(gr0 + nf * 4 + g * 64);
                gw[1][nf][g] = __ldg(gr1 + nf * 4 + g * 64);
            }

        float acc[3][4][4];
#pragma unroll
        for (int g = 0; g < 3; g++)
#pragma unroll
            for (int nf = 0; nf < 4; nf++)
#pragma unroll
                for (int e = 0; e < 4; e++) acc[g][nf][e] = 0.f;

#pragma unroll
        for (int kb = 0; kb < 8; kb++) {
            const int k0 = kb * 8;
            unsigned a0 = Hcur[raA + ((k0 + qid)     ^ gsw)];
            unsigned a1 = Hcur[raB + ((k0 + qid)     ^ gsw)];
            unsigned a2 = Hcur[raA + ((k0 + qid + 4) ^ gsw)];
            unsigned a3 = Hcur[raB + ((k0 + qid + 4) ^ gsw)];
#pragma unroll
            for (int g = 0; g < 3; g++)
#pragma unroll
                for (int nf = 0; nf < 4; nf++) {
                    const unsigned* wr = Ws + ((g * 128 + ct * 32 + nf * 8 + gid) << 6);
                    unsigned b0 = wr[(k0 + qid)     ^ gsw];
                    unsigned b1 = wr[(k0 + qid + 4) ^ gsw];
                    mma_f16(acc[g][nf], a0, a1, a2, a3, b0, b1);
                }
        }

        const bool wmix = (step >= 20);   // fwd: t>=20; rev: t<20 -> both step>=20
#pragma unroll
        for (int m = 0; m < 2; m++) {
            const int row = rt * 16 + gid + 8 * m;
#pragma unroll
            for (int nf = 0; nf < 4; nf++) {
                const int wj = ct * 16 + nf * 4 + qid;      // h word index (col pair / 2)
                __half2 xr = u2h2(gw[m][nf][0]);
                __half2 xz = u2h2(gw[m][nf][1]);
                __half2 xn = u2h2(gw[m][nf][2]);
                __half2 gr_ = __floats2half2_rn(acc[0][nf][2 * m], acc[0][nf][2 * m + 1]);
                __half2 gz_ = __floats2half2_rn(acc[1][nf][2 * m], acc[1][nf][2 * m + 1]);
                __half2 gn_ = __floats2half2_rn(acc[2][nf][2 * m], acc[2][nf][2 * m + 1]);
                __half2 r  = __hfma2(tanh2(__hmul2(__hadd2(xr, gr_), chalf)), chalf, chalf);
                __half2 z  = __hfma2(tanh2(__hmul2(__hadd2(xz, gz_), chalf)), chalf, chalf);
                __half2 cn = __hadd2(gn_, u2h2(bnw[wj]));
                __half2 n  = tanh2(__hfma2(r, cn, xn));
                __half2 h  = __hfma2(z, __hsub2(hreg[m][nf], n), n);
                hreg[m][nf] = h;
                unsigned hw = h22u(h);
                Hnxt[(row << 6) + (wj ^ gsw)] = hw;
                if (wmix) g_mix[stream][row0 + row][t][wj] = hw;
            }
        }
        __syncthreads();   // Hnxt visible before next step's GEMM reads it
    }
}

// --------------------------------------------------------------- kernel 3 ---
// C1 = mix_c @ W_cls^T (no bias), f16 in / f16 out. 640 blocks, 3/SM.
__global__ __launch_bounds__(256, 3) void cls_kernel(const float* __restrict__ W_cls) {
    extern __shared__ unsigned smu[];
    unsigned* Wb = smu;              // [104][64] f16x2 words, swizzled
    unsigned* Ab = smu + 104 * 64;   // [128][64] f16x2 words, swizzled

    const int tid = threadIdx.x;
    const int row0 = blockIdx.x * 128;
    const unsigned* mixc = &g_mix[1][0][0][0];

    for (int i = tid; i < 104 * 64; i += 256) {
        int c = i >> 6, w = i & 63;
        float2 v;
        if (c < C_) v = *(const float2*)(W_cls + (size_t)c * 256 + 2 * w);
        else        v = make_float2(0.f, 0.f);
        Wb[(c << 6) + (w ^ ((c & 7) << 2))] = pack_f16(v.x, v.y);
    }
    for (int i = tid; i < 128 * 64; i += 256) {
        int r = i >> 6, w = i & 63;
        Ab[(r << 6) + (w ^ ((r & 7) << 2))] = mixc[(size_t)(row0 + r) * 64 + w];
    }
    __syncthreads();

    const int warp = tid >> 5, lane = tid & 31;
    const int gid = lane >> 2, qid = lane & 3;
    const int gsw = gid << 2;
    const int ra0 = (warp * 16 + gid) << 6;
    const int ra1 = ra0 + (8 << 6);

    float acc[13][4];
#pragma unroll
    for (int nt = 0; nt < 13; nt++)
#pragma unroll
        for (int e = 0; e < 4; e++) acc[nt][e] = 0.f;

#pragma unroll
    for (int kb = 0; kb < 8; kb++) {
        const int k0 = kb * 8;
        unsigned a0 = Ab[ra0 + ((k0 + qid)     ^ gsw)];
        unsigned a1 = Ab[ra1 + ((k0 + qid)     ^ gsw)];
        unsigned a2 = Ab[ra0 + ((k0 + qid + 4) ^ gsw)];
        unsigned a3 = Ab[ra1 + ((k0 + qid + 4) ^ gsw)];
#pragma unroll
        for (int nt = 0; nt < 13; nt++) {
            const unsigned* wr = Wb + ((nt * 8 + gid) << 6);
            unsigned b0 = wr[(k0 + qid)     ^ gsw];
            unsigned b1 = wr[(k0 + qid + 4) ^ gsw];
            mma_f16(acc[nt], a0, a1, a2, a3, b0, b1);
        }
    }

#pragma unroll
    for (int m = 0; m < 2; m++) {
        const int row = warp * 16 + gid + 8 * m;
        unsigned* cp = &g_C1[row0 + row][0];
#pragma unroll
        for (int nt = 0; nt < 13; nt++)
            cp[nt * 4 + qid] = pack_f16(acc[nt][2 * m], acc[nt][2 * m + 1]);
    }
}

// --------------------------------------------------------------- kernel 4 ---
// per-batch: Gram via f16 MMA (15 m16n8 tiles, zero-padded 48-row operand),
// col-softmax (MLP-unrolled colsum), logits = P*C1(f16) + bias, row-softmax.
// ~44 KB smem -> 4/SM.
#define UAW 68   // padded word stride (68 % 32 == 4 -> conflict-free fragments)
__global__ __launch_bounds__(256, 4) void attn_kernel(const float* __restrict__ b_cls,
                                                      float* __restrict__ out) {
    extern __shared__ float sm[];
    unsigned* Uab = (unsigned*)sm;          // mix_a packed [48][UAW] (rows 40-47 zero)
    float*    E   = sm + 48 * UAW;          // [40*40]
    float*    Z   = E + 1600;               // [40]
    unsigned* C1s = (unsigned*)(Z + 40);    // [40][52] packed
    float*    bs  = (float*)(C1s + 40 * CW_);   // [104]
    float*    L   = bs + CP_;               // logits [40][104]

    const int b = blockIdx.x, tid = threadIdx.x;
    const unsigned* pma = &g_mix[0][b][0][0];
    const unsigned* pc1 = &g_C1[b * T_][0];

    for (int i = tid; i < 48 * UAW; i += 256) {
        int t = i / UAW, w = i - t * UAW;
        Uab[i] = (t < 40 && w < 64) ? pma[t * 64 + w] : 0u;
    }
    for (int i = tid; i < 40 * CW_ / 4; i += 256)
        *(uint4*)(C1s + 4 * i) = *(const uint4*)(pc1 + 4 * i);
    for (int i = tid; i < CP_; i += 256) bs[i] = (i < C_) ? b_cls[i] : 0.f;
    __syncthreads();

    // Gram via f16 MMA: M = Ua Ua^T. 15 tiles (3 m16 x 5 n8) over 8 warps.
    {
        const int warp = tid >> 5, lane = tid & 31;
        const int gid = lane >> 2, qid = lane & 3;
#pragma unroll
        for (int half = 0; half < 2; half++) {
            const int idx = warp + 8 * half;
            if (idx < 15) {
                const int mi = idx / 5, ni = idx - mi * 5;
                const unsigned* A0 = Uab + (mi * 16 + gid) * UAW;
                const unsigned* A1 = A0 + 8 * UAW;
                const unsigned* B0 = Uab + (ni * 8 + gid) * UAW;
                float acc[4] = {0.f, 0.f, 0.f, 0.f};
#pragma unroll
                for (int kb = 0; kb < 8; kb++) {
                    const int k0 = kb * 8;
                    mma_f16(acc,
                            A0[k0 + qid], A1[k0 + qid], A0[k0 + qid + 4], A1[k0 + qid + 4],
                            B0[k0 + qid], B0[k0 + qid + 4]);
                }
                const int r0 = mi * 16 + gid, c0 = ni * 8 + 2 * qid;
                E[r0 * 40 + c0]     = __expf(acc[0]);
                E[r0 * 40 + c0 + 1] = __expf(acc[1]);
                if (r0 + 8 < 40) {
                    E[(r0 + 8) * 40 + c0]     = __expf(acc[2]);
                    E[(r0 + 8) * 40 + c0 + 1] = __expf(acc[3]);
                }
            }
        }
    }
    __syncthreads();

    if (tid < 40) {   // Z[t] = column sums (softmax dim=1), 4-way MLP unroll
        float z0 = 0.f, z1 = 0.f, z2 = 0.f, z3 = 0.f;
        for (int s = 0; s < 40; s += 4) {
            z0 += E[(s)     * 40 + tid];
            z1 += E[(s + 1) * 40 + tid];
            z2 += E[(s + 2) * 40 + tid];
            z3 += E[(s + 3) * 40 + tid];
        }
        Z[tid] = 1.f / ((z0 + z1) + (z2 + z3));
    }
    __syncthreads();
    for (int i = tid; i < 1600; i += 256) E[i] *= Z[i % 40];
    __syncthreads();

    // logits[s][c] = sum_t P[s][t] * C1[t][c] + b[c]; 4s x 4c tiles
    for (int task = tid; task < 260; task += 256) {
        int sb = task / 26, cq = task % 26;
        float acc[4][4];
#pragma unroll
        for (int i = 0; i < 4; i++)
#pragma unroll
            for (int q = 0; q < 4; q++) acc[i][q] = 0.f;
        const float* E0 = E + (4 * sb) * 40;
#pragma unroll 4
        for (int t = 0; t < 40; t++) {
            uint2 cw = *(const uint2*)(C1s + t * CW_ + 2 * cq);
            float2 ca = h2f(cw.x), cb = h2f(cw.y);
            float p0 = E0[t], p1 = E0[40 + t], p2 = E0[80 + t], p3 = E0[120 + t];
            acc[0][0] += p0 * ca.x; acc[0][1] += p0 * ca.y; acc[0][2] += p0 * cb.x; acc[0][3] += p0 * cb.y;
            acc[1][0] += p1 * ca.x; acc[1][1] += p1 * ca.y; acc[1][2] += p1 * cb.x; acc[1][3] += p1 * cb.y;
            acc[2][0] += p2 * ca.x; acc[2][1] += p2 * ca.y; acc[2][2] += p2 * cb.x; acc[2][3] += p2 * cb.y;
            acc[3][0] += p3 * ca.x; acc[3][1] += p3 * ca.y; acc[3][2] += p3 * cb.x; acc[3][3] += p3 * cb.y;
        }
#pragma unroll
        for (int i = 0; i < 4; i++)
#pragma unroll
            for (int q = 0; q < 4; q++)
                L[(4 * sb + i) * CP_ + 4 * cq + q] = acc[i][q] + bs[4 * cq + q];
    }
    __syncthreads();

    // per-row softmax over classes -> out
    {
        const int w = tid >> 5, lane = tid & 31;
        for (int s = w; s < 40; s += 8) {
            const float* Lr = L + s * CP_;
            float m = -1e30f;
            for (int c = lane; c < C_; c += 32) m = fmaxf(m, Lr[c]);
#pragma unroll
            for (int o = 16; o; o >>= 1) m = fmaxf(m, __shfl_xor_sync(~0u, m, o));
            float e[4]; int cnt = 0; float sum = 0.f;
            for (int c = lane; c < C_; c += 32) { float v = __expf(Lr[c] - m); e[cnt++] = v; sum += v; }
#pragma unroll
            for (int o = 16; o; o >>= 1) sum += __shfl_xor_sync(~0u, sum, o);
            float r = 1.f / sum; cnt = 0;
            float* op = out + ((size_t)b * T_ + s) * C_;
            for (int c = lane; c < C_; c += 32) op[c] = e[cnt++] * r;
        }
    }
}

// ------------------------------------------------------------------ launch --
#define GX_SMEM   ((192 * 64 + 64 * 64 + 192) * 4)
#define SCAN_SMEM ((384 * 64 + 2 * 32 * 64 + 64) * 4)
#define CLS_SMEM  ((104 * 64 + 128 * 64) * 4)
#define ATTN_SMEM ((48 * UAW + 1600 + 40 + 40 * CW_ + CP_ + 40 * CP_) * 4)

extern "C" void kernel_launch(void* const* d_in, const int* in_sizes, int n_in,
                              void* d_out, int out_size) {
    const int*   tokens = (const int*)  d_in[0];
    const float* emb_c  = (const float*)d_in[1];
    const float* emb_a  = (const float*)d_in[2];
    const float* W_ih   = (const float*)d_in[3];
    const float* W_hh   = (const float*)d_in[4];
    const float* b_ih   = (const float*)d_in[5];
    const float* b_hh   = (const float*)d_in[6];
    const float* W_cls  = (const float*)d_in[7];
    const float* b_cls  = (const float*)d_in[8];
    float* out = (float*)d_out;

    cudaFuncSetAttribute(tok_gx_kernel, cudaFuncAttributeMaxDynamicSharedMemorySize, GX_SMEM);
    cudaFuncSetAttribute(scan_kernel,   cudaFuncAttributeMaxDynamicSharedMemorySize, SCAN_SMEM);
    cudaFuncSetAttribute(cls_kernel,    cudaFuncAttributeMaxDynamicSharedMemorySize, CLS_SMEM);
    cudaFuncSetAttribute(attn_kernel,   cudaFuncAttributeMaxDynamicSharedMemorySize, ATTN_SMEM);

    tok_gx_kernel<<<dim3(70, 2, 2), 256, GX_SMEM>>>(emb_a, emb_c, W_ih, b_ih, b_hh);
    scan_kernel  <<<256,            256, SCAN_SMEM>>>(W_hh, b_hh, tokens);
    cls_kernel   <<<BT_ / 128,      256, CLS_SMEM>>>(W_cls);
    attn_kernel  <<<B_,             256, ATTN_SMEM>>>(b_cls, out);
}

// round 12
// speedup vs baseline: 4.5520x; 1.0742x over previous
#include <cuda_runtime.h>
#include <cuda_fp16.h>

#define B_  2048
#define T_  40
#define H_  128
#define V_  4450
#define VP_ 4480   // 70 * 64, padded vocab
#define C_  102
#define CP_ 104    // padded classes (13 * 8)
#define CW_ 52     // CP_/2 f16x2 words
#define G3  384    // 3H
#define GW_ 192    // G3/2 f16x2 words
#define BT_ (B_ * T_)

// Scratch: __device__ globals (the sanctioned no-alloc workaround)
__device__ unsigned g_tokG[2][VP_][GW_];   // per-token input gates, f16x2 (b_ih + b_hh[r,z] folded)
__device__ unsigned g_mix [2][B_][T_][64]; // mixed fwd/bwd states, f16x2 words
__device__ unsigned g_C1  [BT_][CW_];      // mix_c @ W_cls^T (no bias), f16x2 words

// ---------------------------------------------------------------- helpers ---
__device__ __forceinline__ unsigned pack_f16(float lo, float hi) {
    unsigned r; asm("cvt.rn.f16x2.f32 %0, %1, %2;" : "=r"(r) : "f"(hi), "f"(lo)); return r;
}
__device__ __forceinline__ __half2 u2h2(unsigned u) { return *reinterpret_cast<__half2*>(&u); }
__device__ __forceinline__ unsigned h22u(__half2 h) { return *reinterpret_cast<unsigned*>(&h); }
__device__ __forceinline__ float2 h2f(unsigned u) { return __half22float2(u2h2(u)); }
__device__ __forceinline__ __half2 tanh2(__half2 x) {
    unsigned u = h22u(x), y;
    asm("tanh.approx.f16x2 %0, %1;" : "=r"(y) : "r"(u));
    return u2h2(y);
}

__device__ __forceinline__ void mma_f16(float* d,
                                        unsigned a0, unsigned a1, unsigned a2, unsigned a3,
                                        unsigned b0, unsigned b1) {
    asm volatile(
        "mma.sync.aligned.m16n8k16.row.col.f32.f16.f16.f32 "
        "{%0,%1,%2,%3},{%4,%5,%6,%7},{%8,%9},{%0,%1,%2,%3};"
        : "+f"(d[0]), "+f"(d[1]), "+f"(d[2]), "+f"(d[3])
        : "r"(a0), "r"(a1), "r"(a2), "r"(a3), "r"(b0), "r"(b1));
}

// --------------------------------------------------------------- kernel 1 ---
// Token-gate table via f16 MMA, f16x2 output. 64 vocab rows x 192 gate-cols
// per block. grid (70, 2 streams, 2 halves) = 280 blocks, 2/SM.
__global__ __launch_bounds__(256, 2) void tok_gx_kernel(const float* __restrict__ emb_a,
                                                        const float* __restrict__ emb_c,
                                                        const float* __restrict__ W_ih,
                                                        const float* __restrict__ b_ih,
                                                        const float* __restrict__ b_hh) {
    extern __shared__ unsigned smu[];
    unsigned* Wb  = smu;                     // [192][64] f16x2 words, swizzled
    unsigned* Ab  = smu + 192 * 64;          // [64][64] f16x2 words, swizzled
    float*    bias = (float*)(Ab + 64 * 64); // [192]

    const int tid = threadIdx.x;
    const int tile = blockIdx.x, stream = blockIdx.y, half = blockIdx.z;
    const float* emb = (stream == 0) ? emb_a : emb_c;
    const int row0 = tile * 64;
    const int nbase = half * 192;

    for (int i = tid; i < 192 * 64; i += 256) {
        int n = i >> 6, w = i & 63;
        float2 v = *(const float2*)(W_ih + (size_t)(nbase + n) * 128 + 2 * w);
        Wb[(n << 6) + (w ^ ((n & 7) << 2))] = pack_f16(v.x, v.y);
    }
    for (int i = tid; i < 192; i += 256) {
        int n = nbase + i;
        bias[i] = b_ih[n] + (n < 256 ? b_hh[n] : 0.f);
    }
    for (int i = tid; i < 64 * 64; i += 256) {
        int r = i >> 6, w = i & 63;
        int vr = row0 + r; if (vr >= V_) vr = V_ - 1;
        float2 v = *(const float2*)(emb + (size_t)vr * H_ + 2 * w);
        Ab[(r << 6) + (w ^ ((r & 7) << 2))] = pack_f16(v.x, v.y);
    }
    __syncthreads();

    const int warp = tid >> 5, lane = tid & 31;
    const int rt = warp & 3, ct = warp >> 2;
    const int gid = lane >> 2, qid = lane & 3;
    const int gsw = gid << 2;
    const int ra0 = (rt * 16 + gid) << 6;
    const int ra1 = ra0 + (8 << 6);

    float acc[12][4];
#pragma unroll
    for (int nt = 0; nt < 12; nt++)
#pragma unroll
        for (int e = 0; e < 4; e++) acc[nt][e] = 0.f;

#pragma unroll
    for (int kb = 0; kb < 8; kb++) {
        const int k0 = kb * 8;
        unsigned a0 = Ab[ra0 + ((k0 + qid)     ^ gsw)];
        unsigned a1 = Ab[ra1 + ((k0 + qid)     ^ gsw)];
        unsigned a2 = Ab[ra0 + ((k0 + qid + 4) ^ gsw)];
        unsigned a3 = Ab[ra1 + ((k0 + qid + 4) ^ gsw)];
#pragma unroll
        for (int nt = 0; nt < 12; nt++) {
            const unsigned* wr = Wb + ((ct * 96 + nt * 8 + gid) << 6);
            unsigned b0 = wr[(k0 + qid)     ^ gsw];
            unsigned b1 = wr[(k0 + qid + 4) ^ gsw];
            mma_f16(acc[nt], a0, a1, a2, a3, b0, b1);
        }
    }

#pragma unroll
    for (int m = 0; m < 2; m++) {
        const int row = rt * 16 + gid + 8 * m;
        unsigned* gp = &g_tokG[stream][row0 + row][half * 96];
#pragma unroll
        for (int nt = 0; nt < 12; nt++) {
            const int nl = ct * 96 + nt * 8 + qid * 2;  // local col (0..191)
            gp[ct * 48 + nt * 4 + qid] =
                pack_f16(acc[nt][2 * m] + bias[nl], acc[nt][2 * m + 1] + bias[nl + 1]);
        }
    }
}

// --------------------------------------------------------------- kernel 2 ---
// 4 GRU scans, f16 MMA. Block = (scan, 32-row tile), 256 blocks, 2/SM.
// RETILED: each warp covers ALL 32 rows x 16 h-cols (3 gates x 2 n8-tiles)
// -> smem traffic 20 words/kb/warp vs 28 before (-29% crossbar).
// Packed f16x2 h carry in registers; double-buffered Hs, ONE barrier/step;
// gate words prefetched before the GEMM.
__global__ __launch_bounds__(256, 2) void scan_kernel(const float* __restrict__ W_hh,
                                                      const float* __restrict__ b_hh,
                                                      const int* __restrict__ tokens) {
    extern __shared__ unsigned smu[];
    unsigned* Ws   = smu;                       // 384 * 64 f16x2 words, swizzled
    unsigned* Hbuf = smu + 384 * 64;            // 2 x [32*64] words
    unsigned* bnw  = Hbuf + 2 * 32 * 64;        // 64 f16x2 = b_hh for n gate

    const int tid = threadIdx.x;
    const int scan = blockIdx.x >> 6, tile = blockIdx.x & 63;
    const int stream = scan >> 1, rev = scan & 1;
    const int row0 = tile * 32;

    for (int i = tid; i < 384 * 64; i += 256) {
        int n = i >> 6, w = i & 63;
        float2 v = *(const float2*)(W_hh + n * 128 + 2 * w);
        Ws[(n << 6) + (w ^ ((n & 7) << 2))] = pack_f16(v.x, v.y);
    }
    for (int i = tid; i < 32 * 64; i += 256) Hbuf[i] = 0u;   // buffer 0 only
    if (tid < 64) bnw[tid] = pack_f16(b_hh[256 + 2 * tid], b_hh[256 + 2 * tid + 1]);
    __syncthreads();

    const int ct = tid >> 5, lane = tid & 31;   // ct: 16-h-col slice (0..7)
    const int gid = lane >> 2, qid = lane & 3;
    const int gsw = gid << 2;
    const unsigned* tokG = &g_tokG[stream][0][0];
    const int gidx0 = ct * 8 + qid;             // gate word base (g=0, nt=0)

    const __half2 chalf = __floats2half2_rn(0.5f, 0.5f);
    __half2 hreg[4][2];                         // [row e][nt]
#pragma unroll
    for (int e = 0; e < 4; e++)
#pragma unroll
        for (int nt = 0; nt < 2; nt++) hreg[e][nt] = __floats2half2_rn(0.f, 0.f);

    for (int step = 0; step < 40; step++) {
        const int t = rev ? 39 - step : step;
        unsigned* Hcur = Hbuf + ((step & 1) ? 32 * 64 : 0);
        unsigned* Hnxt = Hbuf + ((step & 1) ? 0 : 32 * 64);

        int tk[4];
#pragma unroll
        for (int e = 0; e < 4; e++)
            tk[e] = __ldg(&tokens[(row0 + gid + 8 * e) * T_ + t]);

        // PREFETCH all gate words (independent of the GEMM; hides under MMA)
        unsigned gw[4][6];                      // [row e][2*g + nt]
#pragma unroll
        for (int e = 0; e < 4; e++) {
            const unsigned* gr = tokG + (size_t)tk[e] * GW_ + gidx0;
#pragma unroll
            for (int g = 0; g < 3; g++) {
                gw[e][2 * g]     = __ldg(gr + g * 64);
                gw[e][2 * g + 1] = __ldg(gr + g * 64 + 4);
            }
        }

        float acc[3][2][2][4];                  // [g][nt][mt][4]
#pragma unroll
        for (int g = 0; g < 3; g++)
#pragma unroll
            for (int nt = 0; nt < 2; nt++)
#pragma unroll
                for (int mt = 0; mt < 2; mt++)
#pragma unroll
                    for (int e = 0; e < 4; e++) acc[g][nt][mt][e] = 0.f;

#pragma unroll
        for (int kb = 0; kb < 8; kb++) {
            const int k0 = kb * 8;
            const int w0 = (k0 + qid) ^ gsw, w1 = (k0 + qid + 4) ^ gsw;
            unsigned a[2][4];
#pragma unroll
            for (int mt = 0; mt < 2; mt++) {
                const int r = (mt * 16 + gid) << 6;
                a[mt][0] = Hcur[r + w0];
                a[mt][1] = Hcur[r + (8 << 6) + w0];
                a[mt][2] = Hcur[r + w1];
                a[mt][3] = Hcur[r + (8 << 6) + w1];
            }
#pragma unroll
            for (int g = 0; g < 3; g++)
#pragma unroll
                for (int nt = 0; nt < 2; nt++) {
                    const unsigned* wr = Ws + ((g * 128 + ct * 16 + nt * 8 + gid) << 6);
                    unsigned b0 = wr[w0], b1 = wr[w1];
                    mma_f16(acc[g][nt][0], a[0][0], a[0][1], a[0][2], a[0][3], b0, b1);
                    mma_f16(acc[g][nt][1], a[1][0], a[1][1], a[1][2], a[1][3], b0, b1);
                }
        }

        const bool wmix = (step >= 20);   // fwd: t>=20; rev: t<20 -> both step>=20
#pragma unroll
        for (int e = 0; e < 4; e++) {
            const int mt = e >> 1, hh = e & 1;
            const int row = gid + 8 * e;
#pragma unroll
            for (int nt = 0; nt < 2; nt++) {
                const int wj = ct * 8 + nt * 4 + qid;   // h word index (col pair)
                __half2 xr = u2h2(gw[e][nt]);
                __half2 xz = u2h2(gw[e][2 + nt]);
                __half2 xn = u2h2(gw[e][4 + nt]);
                __half2 gr_ = __floats2half2_rn(acc[0][nt][mt][2 * hh], acc[0][nt][mt][2 * hh + 1]);
                __half2 gz_ = __floats2half2_rn(acc[1][nt][mt][2 * hh], acc[1][nt][mt][2 * hh + 1]);
                __half2 gn_ = __floats2half2_rn(acc[2][nt][mt][2 * hh], acc[2][nt][mt][2 * hh + 1]);
                __half2 r  = __hfma2(tanh2(__hmul2(__hadd2(xr, gr_), chalf)), chalf, chalf);
                __half2 z  = __hfma2(tanh2(__hmul2(__hadd2(xz, gz_), chalf)), chalf, chalf);
                __half2 cn = __hadd2(gn_, u2h2(bnw[wj]));
                __half2 n  = tanh2(__hfma2(r, cn, xn));
                __half2 h  = __hfma2(z, __hsub2(hreg[e][nt], n), n);
                hreg[e][nt] = h;
                unsigned hw = h22u(h);
                Hnxt[(row << 6) + (wj ^ gsw)] = hw;
                if (wmix) g_mix[stream][row0 + row][t][wj] = hw;
            }
        }
        __syncthreads();   // Hnxt visible before next step's GEMM reads it
    }
}

// --------------------------------------------------------------- kernel 3 ---
// C1 = mix_c @ W_cls^T (no bias), f16 in / f16 out. 640 blocks, 3/SM.
__global__ __launch_bounds__(256, 3) void cls_kernel(const float* __restrict__ W_cls) {
    extern __shared__ unsigned smu[];
    unsigned* Wb = smu;              // [104][64] f16x2 words, swizzled
    unsigned* Ab = smu + 104 * 64;   // [128][64] f16x2 words, swizzled

    const int tid = threadIdx.x;
    const int row0 = blockIdx.x * 128;
    const unsigned* mixc = &g_mix[1][0][0][0];

    for (int i = tid; i < 104 * 64; i += 256) {
        int c = i >> 6, w = i & 63;
        float2 v;
        if (c < C_) v = *(const float2*)(W_cls + (size_t)c * 256 + 2 * w);
        else        v = make_float2(0.f, 0.f);
        Wb[(c << 6) + (w ^ ((c & 7) << 2))] = pack_f16(v.x, v.y);
    }
    for (int i = tid; i < 128 * 64; i += 256) {
        int r = i >> 6, w = i & 63;
        Ab[(r << 6) + (w ^ ((r & 7) << 2))] = mixc[(size_t)(row0 + r) * 64 + w];
    }
    __syncthreads();

    const int warp = tid >> 5, lane = tid & 31;
    const int gid = lane >> 2, qid = lane & 3;
    const int gsw = gid << 2;
    const int ra0 = (warp * 16 + gid) << 6;
    const int ra1 = ra0 + (8 << 6);

    float acc[13][4];
#pragma unroll
    for (int nt = 0; nt < 13; nt++)
#pragma unroll
        for (int e = 0; e < 4; e++) acc[nt][e] = 0.f;

#pragma unroll
    for (int kb = 0; kb < 8; kb++) {
        const int k0 = kb * 8;
        unsigned a0 = Ab[ra0 + ((k0 + qid)     ^ gsw)];
        unsigned a1 = Ab[ra1 + ((k0 + qid)     ^ gsw)];
        unsigned a2 = Ab[ra0 + ((k0 + qid + 4) ^ gsw)];
        unsigned a3 = Ab[ra1 + ((k0 + qid + 4) ^ gsw)];
#pragma unroll
        for (int nt = 0; nt < 13; nt++) {
            const unsigned* wr = Wb + ((nt * 8 + gid) << 6);
            unsigned b0 = wr[(k0 + qid)     ^ gsw];
            unsigned b1 = wr[(k0 + qid + 4) ^ gsw];
            mma_f16(acc[nt], a0, a1, a2, a3, b0, b1);
        }
    }

#pragma unroll
    for (int m = 0; m < 2; m++) {
        const int row = warp * 16 + gid + 8 * m;
        unsigned* cp = &g_C1[row0 + row][0];
#pragma unroll
        for (int nt = 0; nt < 13; nt++)
            cp[nt * 4 + qid] = pack_f16(acc[nt][2 * m], acc[nt][2 * m + 1]);
    }
}

// --------------------------------------------------------------- kernel 4 ---
// per-batch: Gram via f16 MMA (15 m16n8 tiles, zero-padded 48-row operand),
// col-softmax with Z FOLDED into the logits loop (no E-scale pass),
// logits = (E*Z)*C1(f16) + bias, row-softmax. ~44 KB smem -> 4/SM.
#define UAW 68   // padded word stride (68 % 32 == 4 -> conflict-free fragments)
__global__ __launch_bounds__(256, 4) void attn_kernel(const float* __restrict__ b_cls,
                                                      float* __restrict__ out) {
    extern __shared__ float sm[];
    unsigned* Uab = (unsigned*)sm;          // mix_a packed [48][UAW] (rows 40-47 zero)
    float*    E   = sm + 48 * UAW;          // [40*40]
    float*    Z   = E + 1600;               // [40]
    unsigned* C1s = (unsigned*)(Z + 40);    // [40][52] packed
    float*    bs  = (float*)(C1s + 40 * CW_);   // [104]
    float*    L   = bs + CP_;               // logits [40][104]

    const int b = blockIdx.x, tid = threadIdx.x;
    const unsigned* pma = &g_mix[0][b][0][0];
    const unsigned* pc1 = &g_C1[b * T_][0];

    for (int i = tid; i < 48 * UAW; i += 256) {
        int t = i / UAW, w = i - t * UAW;
        Uab[i] = (t < 40 && w < 64) ? pma[t * 64 + w] : 0u;
    }
    for (int i = tid; i < 40 * CW_ / 4; i += 256)
        *(uint4*)(C1s + 4 * i) = *(const uint4*)(pc1 + 4 * i);
    for (int i = tid; i < CP_; i += 256) bs[i] = (i < C_) ? b_cls[i] : 0.f;
    __syncthreads();

    // Gram via f16 MMA: M = Ua Ua^T. 15 tiles (3 m16 x 5 n8) over 8 warps.
    {
        const int warp = tid >> 5, lane = tid & 31;
        const int gid = lane >> 2, qid = lane & 3;
#pragma unroll
        for (int half = 0; half < 2; half++) {
            const int idx = warp + 8 * half;
            if (idx < 15) {
                const int mi = idx / 5, ni = idx - mi * 5;
                const unsigned* A0 = Uab + (mi * 16 + gid) * UAW;
                const unsigned* A1 = A0 + 8 * UAW;
                const unsigned* B0 = Uab + (ni * 8 + gid) * UAW;
                float acc[4] = {0.f, 0.f, 0.f, 0.f};
#pragma unroll
                for (int kb = 0; kb < 8; kb++) {
                    const int k0 = kb * 8;
                    mma_f16(acc,
                            A0[k0 + qid], A1[k0 + qid], A0[k0 + qid + 4], A1[k0 + qid + 4],
                            B0[k0 + qid], B0[k0 + qid + 4]);
                }
                const int r0 = mi * 16 + gid, c0 = ni * 8 + 2 * qid;
                E[r0 * 40 + c0]     = __expf(acc[0]);
                E[r0 * 40 + c0 + 1] = __expf(acc[1]);
                if (r0 + 8 < 40) {
                    E[(r0 + 8) * 40 + c0]     = __expf(acc[2]);
                    E[(r0 + 8) * 40 + c0 + 1] = __expf(acc[3]);
                }
            }
        }
    }
    __syncthreads();

    if (tid < 40) {   // Z[t] = 1/column sum (softmax dim=1), 4-way MLP unroll
        float z0 = 0.f, z1 = 0.f, z2 = 0.f, z3 = 0.f;
        for (int s = 0; s < 40; s += 4) {
            z0 += E[(s)     * 40 + tid];
            z1 += E[(s + 1) * 40 + tid];
            z2 += E[(s + 2) * 40 + tid];
            z3 += E[(s + 3) * 40 + tid];
        }
        Z[tid] = 1.f / ((z0 + z1) + (z2 + z3));
    }
    __syncthreads();

    // logits[s][c] = sum_t E[s][t]*Z[t] * C1[t][c] + b[c]; 4s x 4c tiles
    for (int task = tid; task < 260; task += 256) {
        int sb = task / 26, cq = task % 26;
        float acc[4][4];
#pragma unroll
        for (int i = 0; i < 4; i++)
#pragma unroll
            for (int q = 0; q < 4; q++) acc[i][q] = 0.f;
        const float* E0 = E + (4 * sb) * 40;
#pragma unroll 4
        for (int t = 0; t < 40; t++) {
            uint2 cw = *(const uint2*)(C1s + t * CW_ + 2 * cq);
            float2 ca = h2f(cw.x), cb = h2f(cw.y);
            float zt = Z[t];
            float p0 = E0[t] * zt, p1 = E0[40 + t] * zt;
            float p2 = E0[80 + t] * zt, p3 = E0[120 + t] * zt;
            acc[0][0] += p0 * ca.x; acc[0][1] += p0 * ca.y; acc[0][2] += p0 * cb.x; acc[0][3] += p0 * cb.y;
            acc[1][0] += p1 * ca.x; acc[1][1] += p1 * ca.y; acc[1][2] += p1 * cb.x; acc[1][3] += p1 * cb.y;
            acc[2][0] += p2 * ca.x; acc[2][1] += p2 * ca.y; acc[2][2] += p2 * cb.x; acc[2][3] += p2 * cb.y;
            acc[3][0] += p3 * ca.x; acc[3][1] += p3 * ca.y; acc[3][2] += p3 * cb.x; acc[3][3] += p3 * cb.y;
        }
#pragma unroll
        for (int i = 0; i < 4; i++)
#pragma unroll
            for (int q = 0; q < 4; q++)
                L[(4 * sb + i) * CP_ + 4 * cq + q] = acc[i][q] + bs[4 * cq + q];
    }
    __syncthreads();

    // per-row softmax over classes -> out
    {
        const int w = tid >> 5, lane = tid & 31;
        for (int s = w; s < 40; s += 8) {
            const float* Lr = L + s * CP_;
            float m = -1e30f;
            for (int c = lane; c < C_; c += 32) m = fmaxf(m, Lr[c]);
#pragma unroll
            for (int o = 16; o; o >>= 1) m = fmaxf(m, __shfl_xor_sync(~0u, m, o));
            float e[4]; int cnt = 0; float sum = 0.f;
            for (int c = lane; c < C_; c += 32) { float v = __expf(Lr[c] - m); e[cnt++] = v; sum += v; }
#pragma unroll
            for (int o = 16; o; o >>= 1) sum += __shfl_xor_sync(~0u, sum, o);
            float r = 1.f / sum; cnt = 0;
            float* op = out + ((size_t)b * T_ + s) * C_;
            for (int c = lane; c < C_; c += 32) op[c] = e[cnt++] * r;
        }
    }
}

// ------------------------------------------------------------------ launch --
#define GX_SMEM   ((192 * 64 + 64 * 64 + 192) * 4)
#define SCAN_SMEM ((384 * 64 + 2 * 32 * 64 + 64) * 4)
#define CLS_SMEM  ((104 * 64 + 128 * 64) * 4)
#define ATTN_SMEM ((48 * UAW + 1600 + 40 + 40 * CW_ + CP_ + 40 * CP_) * 4)

extern "C" void kernel_launch(void* const* d_in, const int* in_sizes, int n_in,
                              void* d_out, int out_size) {
    const int*   tokens = (const int*)  d_in[0];
    const float* emb_c  = (const float*)d_in[1];
    const float* emb_a  = (const float*)d_in[2];
    const float* W_ih   = (const float*)d_in[3];
    const float* W_hh   = (const float*)d_in[4];
    const float* b_ih   = (const float*)d_in[5];
    const float* b_hh   = (const float*)d_in[6];
    const float* W_cls  = (const float*)d_in[7];
    const float* b_cls  = (const float*)d_in[8];
    float* out = (float*)d_out;

    cudaFuncSetAttribute(tok_gx_kernel, cudaFuncAttributeMaxDynamicSharedMemorySize, GX_SMEM);
    cudaFuncSetAttribute(scan_kernel,   cudaFuncAttributeMaxDynamicSharedMemorySize, SCAN_SMEM);
    cudaFuncSetAttribute(cls_kernel,    cudaFuncAttributeMaxDynamicSharedMemorySize, CLS_SMEM);
    cudaFuncSetAttribute(attn_kernel,   cudaFuncAttributeMaxDynamicSharedMemorySize, ATTN_SMEM);

    tok_gx_kernel<<<dim3(70, 2, 2), 256, GX_SMEM>>>(emb_a, emb_c, W_ih, b_ih, b_hh);
    scan_kernel  <<<256,            256, SCAN_SMEM>>>(W_hh, b_hh, tokens);
    cls_kernel   <<<BT_ / 128,      256, CLS_SMEM>>>(W_cls);
    attn_kernel  <<<B_,             256, ATTN_SMEM>>>(b_cls, out);
}

// round 13
// speedup vs baseline: 4.6523x; 1.0220x over previous
#include <cuda_runtime.h>
#include <cuda_fp16.h>

#define B_  2048
#define T_  40
#define H_  128
#define V_  4450
#define VP_ 4480   // 70 * 64, padded vocab
#define C_  102
#define CP_ 104    // padded classes (13 * 8)
#define CW_ 52     // CP_/2 f16x2 words
#define G3  384    // 3H
#define GW_ 192    // G3/2 f16x2 words
#define BT_ (B_ * T_)

// Scratch: __device__ globals (the sanctioned no-alloc workaround)
__device__ unsigned g_tokG[2][VP_][GW_];   // per-token input gates, f16x2 (b_ih + b_hh[r,z] folded)
__device__ unsigned g_mix [2][B_][T_][64]; // mixed fwd/bwd states, f16x2 words
__device__ unsigned g_C1  [BT_][CW_];      // mix_c @ W_cls^T (no bias), f16x2 words

// ---------------------------------------------------------------- helpers ---
__device__ __forceinline__ unsigned pack_f16(float lo, float hi) {
    unsigned r; asm("cvt.rn.f16x2.f32 %0, %1, %2;" : "=r"(r) : "f"(hi), "f"(lo)); return r;
}
__device__ __forceinline__ __half2 u2h2(unsigned u) { return *reinterpret_cast<__half2*>(&u); }
__device__ __forceinline__ unsigned h22u(__half2 h) { return *reinterpret_cast<unsigned*>(&h); }
__device__ __forceinline__ float2 h2f(unsigned u) { return __half22float2(u2h2(u)); }
__device__ __forceinline__ __half2 tanh2(__half2 x) {
    unsigned u = h22u(x), y;
    asm("tanh.approx.f16x2 %0, %1;" : "=r"(y) : "r"(u));
    return u2h2(y);
}

__device__ __forceinline__ void mma_f16(float* d,
                                        unsigned a0, unsigned a1, unsigned a2, unsigned a3,
                                        unsigned b0, unsigned b1) {
    asm volatile(
        "mma.sync.aligned.m16n8k16.row.col.f32.f16.f16.f32 "
        "{%0,%1,%2,%3},{%4,%5,%6,%7},{%8,%9},{%0,%1,%2,%3};"
        : "+f"(d[0]), "+f"(d[1]), "+f"(d[2]), "+f"(d[3])
        : "r"(a0), "r"(a1), "r"(a2), "r"(a3), "r"(b0), "r"(b1));
}

// --------------------------------------------------------------- kernel 1 ---
// Token-gate table via f16 MMA, f16x2 output. 64 vocab rows x 192 gate-cols
// per block. grid (70, 2 streams, 2 halves) = 280 blocks, 2/SM.
__global__ __launch_bounds__(256, 2) void tok_gx_kernel(const float* __restrict__ emb_a,
                                                        const float* __restrict__ emb_c,
                                                        const float* __restrict__ W_ih,
                                                        const float* __restrict__ b_ih,
                                                        const float* __restrict__ b_hh) {
    extern __shared__ unsigned smu[];
    unsigned* Wb  = smu;                     // [192][64] f16x2 words, swizzled
    unsigned* Ab  = smu + 192 * 64;          // [64][64] f16x2 words, swizzled
    float*    bias = (float*)(Ab + 64 * 64); // [192]

    const int tid = threadIdx.x;
    const int tile = blockIdx.x, stream = blockIdx.y, half = blockIdx.z;
    const float* emb = (stream == 0) ? emb_a : emb_c;
    const int row0 = tile * 64;
    const int nbase = half * 192;

    for (int i = tid; i < 192 * 64; i += 256) {
        int n = i >> 6, w = i & 63;
        float2 v = *(const float2*)(W_ih + (size_t)(nbase + n) * 128 + 2 * w);
        Wb[(n << 6) + (w ^ ((n & 7) << 2))] = pack_f16(v.x, v.y);
    }
    for (int i = tid; i < 192; i += 256) {
        int n = nbase + i;
        bias[i] = b_ih[n] + (n < 256 ? b_hh[n] : 0.f);
    }
    for (int i = tid; i < 64 * 64; i += 256) {
        int r = i >> 6, w = i & 63;
        int vr = row0 + r; if (vr >= V_) vr = V_ - 1;
        float2 v = *(const float2*)(emb + (size_t)vr * H_ + 2 * w);
        Ab[(r << 6) + (w ^ ((r & 7) << 2))] = pack_f16(v.x, v.y);
    }
    __syncthreads();

    const int warp = tid >> 5, lane = tid & 31;
    const int rt = warp & 3, ct = warp >> 2;
    const int gid = lane >> 2, qid = lane & 3;
    const int gsw = gid << 2;
    const int ra0 = (rt * 16 + gid) << 6;
    const int ra1 = ra0 + (8 << 6);

    float acc[12][4];
#pragma unroll
    for (int nt = 0; nt < 12; nt++)
#pragma unroll
        for (int e = 0; e < 4; e++) acc[nt][e] = 0.f;

#pragma unroll
    for (int kb = 0; kb < 8; kb++) {
        const int k0 = kb * 8;
        unsigned a0 = Ab[ra0 + ((k0 + qid)     ^ gsw)];
        unsigned a1 = Ab[ra1 + ((k0 + qid)     ^ gsw)];
        unsigned a2 = Ab[ra0 + ((k0 + qid + 4) ^ gsw)];
        unsigned a3 = Ab[ra1 + ((k0 + qid + 4) ^ gsw)];
#pragma unroll
        for (int nt = 0; nt < 12; nt++) {
            const unsigned* wr = Wb + ((ct * 96 + nt * 8 + gid) << 6);
            unsigned b0 = wr[(k0 + qid)     ^ gsw];
            unsigned b1 = wr[(k0 + qid + 4) ^ gsw];
            mma_f16(acc[nt], a0, a1, a2, a3, b0, b1);
        }
    }

#pragma unroll
    for (int m = 0; m < 2; m++) {
        const int row = rt * 16 + gid + 8 * m;
        unsigned* gp = &g_tokG[stream][row0 + row][half * 96];
#pragma unroll
        for (int nt = 0; nt < 12; nt++) {
            const int nl = ct * 96 + nt * 8 + qid * 2;  // local col (0..191)
            gp[ct * 48 + nt * 4 + qid] =
                pack_f16(acc[nt][2 * m] + bias[nl], acc[nt][2 * m + 1] + bias[nl + 1]);
        }
    }
}

// --------------------------------------------------------------- kernel 2 ---
// 4 GRU scans, f16 MMA. Block = (scan, 32-row tile), 256 blocks, 2/SM.
// Each warp covers ALL 32 rows x 16 h-cols -> 20 smem words/kb/warp.
// Packed f16x2 h carry in registers; double-buffered Hs, ONE barrier/step;
// gate words prefetched before the GEMM.
__global__ __launch_bounds__(256, 2) void scan_kernel(const float* __restrict__ W_hh,
                                                      const float* __restrict__ b_hh,
                                                      const int* __restrict__ tokens) {
    extern __shared__ unsigned smu[];
    unsigned* Ws   = smu;                       // 384 * 64 f16x2 words, swizzled
    unsigned* Hbuf = smu + 384 * 64;            // 2 x [32*64] words
    unsigned* bnw  = Hbuf + 2 * 32 * 64;        // 64 f16x2 = b_hh for n gate

    const int tid = threadIdx.x;
    const int scan = blockIdx.x >> 6, tile = blockIdx.x & 63;
    const int stream = scan >> 1, rev = scan & 1;
    const int row0 = tile * 32;

    for (int i = tid; i < 384 * 64; i += 256) {
        int n = i >> 6, w = i & 63;
        float2 v = *(const float2*)(W_hh + n * 128 + 2 * w);
        Ws[(n << 6) + (w ^ ((n & 7) << 2))] = pack_f16(v.x, v.y);
    }
    for (int i = tid; i < 32 * 64; i += 256) Hbuf[i] = 0u;   // buffer 0 only
    if (tid < 64) bnw[tid] = pack_f16(b_hh[256 + 2 * tid], b_hh[256 + 2 * tid + 1]);
    __syncthreads();

    const int ct = tid >> 5, lane = tid & 31;   // ct: 16-h-col slice (0..7)
    const int gid = lane >> 2, qid = lane & 3;
    const int gsw = gid << 2;
    const unsigned* tokG = &g_tokG[stream][0][0];
    const int gidx0 = ct * 8 + qid;             // gate word base (g=0, nt=0)

    const __half2 chalf = __floats2half2_rn(0.5f, 0.5f);
    __half2 hreg[4][2];                         // [row e][nt]
#pragma unroll
    for (int e = 0; e < 4; e++)
#pragma unroll
        for (int nt = 0; nt < 2; nt++) hreg[e][nt] = __floats2half2_rn(0.f, 0.f);

    for (int step = 0; step < 40; step++) {
        const int t = rev ? 39 - step : step;
        unsigned* Hcur = Hbuf + ((step & 1) ? 32 * 64 : 0);
        unsigned* Hnxt = Hbuf + ((step & 1) ? 0 : 32 * 64);

        int tk[4];
#pragma unroll
        for (int e = 0; e < 4; e++)
            tk[e] = __ldg(&tokens[(row0 + gid + 8 * e) * T_ + t]);

        // PREFETCH all gate words (independent of the GEMM; hides under MMA)
        unsigned gw[4][6];                      // [row e][2*g + nt]
#pragma unroll
        for (int e = 0; e < 4; e++) {
            const unsigned* gr = tokG + (size_t)tk[e] * GW_ + gidx0;
#pragma unroll
            for (int g = 0; g < 3; g++) {
                gw[e][2 * g]     = __ldg(gr + g * 64);
                gw[e][2 * g + 1] = __ldg(gr + g * 64 + 4);
            }
        }

        float acc[3][2][2][4];                  // [g][nt][mt][4]
#pragma unroll
        for (int g = 0; g < 3; g++)
#pragma unroll
            for (int nt = 0; nt < 2; nt++)
#pragma unroll
                for (int mt = 0; mt < 2; mt++)
#pragma unroll
                    for (int e = 0; e < 4; e++) acc[g][nt][mt][e] = 0.f;

#pragma unroll
        for (int kb = 0; kb < 8; kb++) {
            const int k0 = kb * 8;
            const int w0 = (k0 + qid) ^ gsw, w1 = (k0 + qid + 4) ^ gsw;
            unsigned a[2][4];
#pragma unroll
            for (int mt = 0; mt < 2; mt++) {
                const int r = (mt * 16 + gid) << 6;
                a[mt][0] = Hcur[r + w0];
                a[mt][1] = Hcur[r + (8 << 6) + w0];
                a[mt][2] = Hcur[r + w1];
                a[mt][3] = Hcur[r + (8 << 6) + w1];
            }
#pragma unroll
            for (int g = 0; g < 3; g++)
#pragma unroll
                for (int nt = 0; nt < 2; nt++) {
                    const unsigned* wr = Ws + ((g * 128 + ct * 16 + nt * 8 + gid) << 6);
                    unsigned b0 = wr[w0], b1 = wr[w1];
                    mma_f16(acc[g][nt][0], a[0][0], a[0][1], a[0][2], a[0][3], b0, b1);
                    mma_f16(acc[g][nt][1], a[1][0], a[1][1], a[1][2], a[1][3], b0, b1);
                }
        }

        const bool wmix = (step >= 20);   // fwd: t>=20; rev: t<20 -> both step>=20
#pragma unroll
        for (int e = 0; e < 4; e++) {
            const int mt = e >> 1, hh = e & 1;
            const int row = gid + 8 * e;
#pragma unroll
            for (int nt = 0; nt < 2; nt++) {
                const int wj = ct * 8 + nt * 4 + qid;   // h word index (col pair)
                __half2 xr = u2h2(gw[e][nt]);
                __half2 xz = u2h2(gw[e][2 + nt]);
                __half2 xn = u2h2(gw[e][4 + nt]);
                __half2 gr_ = __floats2half2_rn(acc[0][nt][mt][2 * hh], acc[0][nt][mt][2 * hh + 1]);
                __half2 gz_ = __floats2half2_rn(acc[1][nt][mt][2 * hh], acc[1][nt][mt][2 * hh + 1]);
                __half2 gn_ = __floats2half2_rn(acc[2][nt][mt][2 * hh], acc[2][nt][mt][2 * hh + 1]);
                __half2 r  = __hfma2(tanh2(__hmul2(__hadd2(xr, gr_), chalf)), chalf, chalf);
                __half2 z  = __hfma2(tanh2(__hmul2(__hadd2(xz, gz_), chalf)), chalf, chalf);
                __half2 cn = __hadd2(gn_, u2h2(bnw[wj]));
                __half2 n  = tanh2(__hfma2(r, cn, xn));
                __half2 h  = __hfma2(z, __hsub2(hreg[e][nt], n), n);
                hreg[e][nt] = h;
                unsigned hw = h22u(h);
                Hnxt[(row << 6) + (wj ^ gsw)] = hw;
                if (wmix) g_mix[stream][row0 + row][t][wj] = hw;
            }
        }
        __syncthreads();   // Hnxt visible before next step's GEMM reads it
    }
}

// --------------------------------------------------------------- kernel 3 ---
// C1 = mix_c @ W_cls^T (no bias), f16 in / f16 out. 640 blocks, 3/SM.
__global__ __launch_bounds__(256, 3) void cls_kernel(const float* __restrict__ W_cls) {
    extern __shared__ unsigned smu[];
    unsigned* Wb = smu;              // [104][64] f16x2 words, swizzled
    unsigned* Ab = smu + 104 * 64;   // [128][64] f16x2 words, swizzled

    const int tid = threadIdx.x;
    const int row0 = blockIdx.x * 128;
    const unsigned* mixc = &g_mix[1][0][0][0];

    for (int i = tid; i < 104 * 64; i += 256) {
        int c = i >> 6, w = i & 63;
        float2 v;
        if (c < C_) v = *(const float2*)(W_cls + (size_t)c * 256 + 2 * w);
        else        v = make_float2(0.f, 0.f);
        Wb[(c << 6) + (w ^ ((c & 7) << 2))] = pack_f16(v.x, v.y);
    }
    for (int i = tid; i < 128 * 64; i += 256) {
        int r = i >> 6, w = i & 63;
        Ab[(r << 6) + (w ^ ((r & 7) << 2))] = mixc[(size_t)(row0 + r) * 64 + w];
    }
    __syncthreads();

    const int warp = tid >> 5, lane = tid & 31;
    const int gid = lane >> 2, qid = lane & 3;
    const int gsw = gid << 2;
    const int ra0 = (warp * 16 + gid) << 6;
    const int ra1 = ra0 + (8 << 6);

    float acc[13][4];
#pragma unroll
    for (int nt = 0; nt < 13; nt++)
#pragma unroll
        for (int e = 0; e < 4; e++) acc[nt][e] = 0.f;

#pragma unroll
    for (int kb = 0; kb < 8; kb++) {
        const int k0 = kb * 8;
        unsigned a0 = Ab[ra0 + ((k0 + qid)     ^ gsw)];
        unsigned a1 = Ab[ra1 + ((k0 + qid)     ^ gsw)];
        unsigned a2 = Ab[ra0 + ((k0 + qid + 4) ^ gsw)];
        unsigned a3 = Ab[ra1 + ((k0 + qid + 4) ^ gsw)];
#pragma unroll
        for (int nt = 0; nt < 13; nt++) {
            const unsigned* wr = Wb + ((nt * 8 + gid) << 6);
            unsigned b0 = wr[(k0 + qid)     ^ gsw];
            unsigned b1 = wr[(k0 + qid + 4) ^ gsw];
            mma_f16(acc[nt], a0, a1, a2, a3, b0, b1);
        }
    }

#pragma unroll
    for (int m = 0; m < 2; m++) {
        const int row = warp * 16 + gid + 8 * m;
        unsigned* cp = &g_C1[row0 + row][0];
#pragma unroll
        for (int nt = 0; nt < 13; nt++)
            cp[nt * 4 + qid] = pack_f16(acc[nt][2 * m], acc[nt][2 * m + 1]);
    }
}

// --------------------------------------------------------------- kernel 4 ---
// per-batch: Gram via f16 MMA; col-softmax; LOGITS via f16 MMA too
// (P packed to f16, C1 transposed to [class][t]); row-softmax.
// ~53.7 KB smem -> 4/SM (214.8 KB).
#define UAW 68   // padded word stride (conflict-free fragments)
#define PTW 28   // Pm/CT word stride (24 used + 4 pad; conflict-free)
__global__ __launch_bounds__(256, 4) void attn_kernel(const float* __restrict__ b_cls,
                                                      float* __restrict__ out) {
    extern __shared__ float sm[];
    unsigned* Uab = (unsigned*)sm;            // mix_a packed [48][UAW] (rows 40-47 zero)
    float*    E   = sm + 48 * UAW;            // [40*40]
    float*    Z   = E + 1600;                 // [40]
    unsigned* Pm  = (unsigned*)(Z + 40);      // [48][PTW]  P=E*Z packed f16
    unsigned* CT  = Pm + 48 * PTW;            // [104][PTW] C1 transposed
    float*    bs  = (float*)(CT + 104 * PTW); // [104]
    float*    L   = bs + CP_;                 // logits [40][104]; doubles as C1 stage

    const int b = blockIdx.x, tid = threadIdx.x;
    const unsigned* pma = &g_mix[0][b][0][0];
    const unsigned* pc1 = &g_C1[b * T_][0];
    unsigned* C1st = (unsigned*)L;            // staging: [40][CW_] words (2080 <= 4160)

    for (int i = tid; i < 48 * UAW; i += 256) {
        int t = i / UAW, w = i - t * UAW;
        Uab[i] = (t < 40 && w < 64) ? pma[t * 64 + w] : 0u;
    }
    for (int i = tid; i < 40 * CW_ / 4; i += 256)
        *(uint4*)(C1st + 4 * i) = *(const uint4*)(pc1 + 4 * i);
    for (int i = tid; i < CP_; i += 256) bs[i] = (i < C_) ? b_cls[i] : 0.f;
    __syncthreads();

    const int warp = tid >> 5, lane = tid & 31;
    const int gid = lane >> 2, qid = lane & 3;

    // Gram via f16 MMA: M = Ua Ua^T. 15 tiles (3 m16 x 5 n8) over 8 warps.
#pragma unroll
    for (int half = 0; half < 2; half++) {
        const int idx = warp + 8 * half;
        if (idx < 15) {
            const int mi = idx / 5, ni = idx - mi * 5;
            const unsigned* A0 = Uab + (mi * 16 + gid) * UAW;
            const unsigned* A1 = A0 + 8 * UAW;
            const unsigned* B0 = Uab + (ni * 8 + gid) * UAW;
            float acc[4] = {0.f, 0.f, 0.f, 0.f};
#pragma unroll
            for (int kb = 0; kb < 8; kb++) {
                const int k0 = kb * 8;
                mma_f16(acc,
                        A0[k0 + qid], A1[k0 + qid], A0[k0 + qid + 4], A1[k0 + qid + 4],
                        B0[k0 + qid], B0[k0 + qid + 4]);
            }
            const int r0 = mi * 16 + gid, c0 = ni * 8 + 2 * qid;
            E[r0 * 40 + c0]     = __expf(acc[0]);
            E[r0 * 40 + c0 + 1] = __expf(acc[1]);
            if (r0 + 8 < 40) {
                E[(r0 + 8) * 40 + c0]     = __expf(acc[2]);
                E[(r0 + 8) * 40 + c0 + 1] = __expf(acc[3]);
            }
        }
    }
    __syncthreads();

    if (tid < 40) {   // Z[t] = 1/column sum (softmax dim=1), 4-way MLP unroll
        float z0 = 0.f, z1 = 0.f, z2 = 0.f, z3 = 0.f;
        for (int s = 0; s < 40; s += 4) {
            z0 += E[(s)     * 40 + tid];
            z1 += E[(s + 1) * 40 + tid];
            z2 += E[(s + 2) * 40 + tid];
            z3 += E[(s + 3) * 40 + tid];
        }
        Z[tid] = 1.f / ((z0 + z1) + (z2 + z3));
    }
    __syncthreads();

    // Build packed operands: Pm[s][tw] = f16x2(E[s][2tw]Z[2tw], E[s][2tw+1]Z[2tw+1]),
    // CT[c][tw] = f16x2(C1[2tw][c], C1[2tw+1][c]). tw >= 20 and s >= 40 are zero.
    for (int i = tid; i < 48 * PTW; i += 256) {
        int s = i / PTW, w = i - s * PTW;
        unsigned v = 0u;
        if (s < 40 && w < 20)
            v = pack_f16(E[s * 40 + 2 * w] * Z[2 * w], E[s * 40 + 2 * w + 1] * Z[2 * w + 1]);
        Pm[i] = v;
    }
    for (int i = tid; i < 104 * PTW; i += 256) {
        int c = i / PTW, w = i - c * PTW;
        unsigned v = 0u;
        if (w < 20) {
            unsigned u0 = C1st[(2 * w)     * CW_ + (c >> 1)];
            unsigned u1 = C1st[(2 * w + 1) * CW_ + (c >> 1)];
            unsigned h0 = (c & 1) ? (u0 >> 16)        : (u0 & 0xffffu);
            unsigned h1 = (c & 1) ? (u1 & 0xffff0000u) : (u1 << 16);
            v = h0 | h1;
        }
        CT[i] = v;
    }
    __syncthreads();

    // Logits via f16 MMA: L = P * C1 + b. 39 tiles (3 m16 x 13 n8), K=48.
#pragma unroll
    for (int j = 0; j < 5; j++) {
        const int idx = warp + 8 * j;
        if (idx < 39) {
            const int mt = idx / 13, nt = idx - mt * 13;
            const unsigned* A0 = Pm + (mt * 16 + gid) * PTW;
            const unsigned* A1 = A0 + 8 * PTW;
            const unsigned* B0 = CT + (nt * 8 + gid) * PTW;
            float acc[4] = {0.f, 0.f, 0.f, 0.f};
#pragma unroll
            for (int kt = 0; kt < 3; kt++) {
                const int k0 = kt * 8;
                mma_f16(acc,
                        A0[k0 + qid], A1[k0 + qid], A0[k0 + qid + 4], A1[k0 + qid + 4],
                        B0[k0 + qid], B0[k0 + qid + 4]);
            }
            const int r0 = mt * 16 + gid, c0 = nt * 8 + 2 * qid;
            L[r0 * CP_ + c0]     = acc[0] + bs[c0];
            L[r0 * CP_ + c0 + 1] = acc[1] + bs[c0 + 1];
            if (r0 + 8 < 40) {
                L[(r0 + 8) * CP_ + c0]     = acc[2] + bs[c0];
                L[(r0 + 8) * CP_ + c0 + 1] = acc[3] + bs[c0 + 1];
            }
        }
    }
    __syncthreads();

    // per-row softmax over classes -> out
    {
        const int w = tid >> 5;
        for (int s = w; s < 40; s += 8) {
            const float* Lr = L + s * CP_;
            float m = -1e30f;
            for (int c = lane; c < C_; c += 32) m = fmaxf(m, Lr[c]);
#pragma unroll
            for (int o = 16; o; o >>= 1) m = fmaxf(m, __shfl_xor_sync(~0u, m, o));
            float e[4]; int cnt = 0; float sum = 0.f;
            for (int c = lane; c < C_; c += 32) { float v = __expf(Lr[c] - m); e[cnt++] = v; sum += v; }
#pragma unroll
            for (int o = 16; o; o >>= 1) sum += __shfl_xor_sync(~0u, sum, o);
            float r = 1.f / sum; cnt = 0;
            float* op = out + ((size_t)b * T_ + s) * C_;
            for (int c = lane; c < C_; c += 32) op[c] = e[cnt++] * r;
        }
    }
}

// ------------------------------------------------------------------ launch --
#define GX_SMEM   ((192 * 64 + 64 * 64 + 192) * 4)
#define SCAN_SMEM ((384 * 64 + 2 * 32 * 64 + 64) * 4)
#define CLS_SMEM  ((104 * 64 + 128 * 64) * 4)
#define ATTN_SMEM ((48 * UAW + 1600 + 40 + 48 * PTW + 104 * PTW + CP_ + 40 * CP_) * 4)

extern "C" void kernel_launch(void* const* d_in, const int* in_sizes, int n_in,
                              void* d_out, int out_size) {
    const int*   tokens = (const int*)  d_in[0];
    const float* emb_c  = (const float*)d_in[1];
    const float* emb_a  = (const float*)d_in[2];
    const float* W_ih   = (const float*)d_in[3];
    const float* W_hh   = (const float*)d_in[4];
    const float* b_ih   = (const float*)d_in[5];
    const float* b_hh   = (const float*)d_in[6];
    const float* W_cls  = (const float*)d_in[7];
    const float* b_cls  = (const float*)d_in[8];
    float* out = (float*)d_out;

    cudaFuncSetAttribute(tok_gx_kernel, cudaFuncAttributeMaxDynamicSharedMemorySize, GX_SMEM);
    cudaFuncSetAttribute(scan_kernel,   cudaFuncAttributeMaxDynamicSharedMemorySize, SCAN_SMEM);
    cudaFuncSetAttribute(cls_kernel,    cudaFuncAttributeMaxDynamicSharedMemorySize, CLS_SMEM);
    cudaFuncSetAttribute(attn_kernel,   cudaFuncAttributeMaxDynamicSharedMemorySize, ATTN_SMEM);

    tok_gx_kernel<<<dim3(70, 2, 2), 256, GX_SMEM>>>(emb_a, emb_c, W_ih, b_ih, b_hh);
    scan_kernel  <<<256,            256, SCAN_SMEM>>>(W_hh, b_hh, tokens);
    cls_kernel   <<<BT_ / 128,      256, CLS_SMEM>>>(W_cls);
    attn_kernel  <<<B_,             256, ATTN_SMEM>>>(b_cls, out);
}

// round 14
// speedup vs baseline: 5.1134x; 1.0991x over previous
#include <cuda_runtime.h>
#include <cuda_fp16.h>

#define B_  2048
#define T_  40
#define H_  128
#define V_  4450
#define VP_ 4480   // 70 * 64, padded vocab
#define C_  102
#define CP_ 104    // padded classes (13 * 8)
#define CW_ 52     // CP_/2 f16x2 words
#define G3  384    // 3H
#define GW_ 192    // G3/2 f16x2 words
#define BT_ (B_ * T_)

// Scratch: __device__ globals (the sanctioned no-alloc workaround)
__device__ unsigned g_tokG[2][VP_][GW_];   // per-token input gates, f16x2 (b_ih + b_hh[r,z] folded)
__device__ unsigned g_mix [2][B_][T_][64]; // mixed fwd/bwd states, f16x2 words
__device__ unsigned g_C1  [BT_][CW_];      // mix_c @ W_cls^T (no bias), f16x2 words

// ---------------------------------------------------------------- helpers ---
__device__ __forceinline__ unsigned pack_f16(float lo, float hi) {
    unsigned r; asm("cvt.rn.f16x2.f32 %0, %1, %2;" : "=r"(r) : "f"(hi), "f"(lo)); return r;
}
__device__ __forceinline__ __half2 u2h2(unsigned u) { return *reinterpret_cast<__half2*>(&u); }
__device__ __forceinline__ unsigned h22u(__half2 h) { return *reinterpret_cast<unsigned*>(&h); }
__device__ __forceinline__ float2 h2f(unsigned u) { return __half22float2(u2h2(u)); }
__device__ __forceinline__ __half2 tanh2(__half2 x) {
    unsigned u = h22u(x), y;
    asm("tanh.approx.f16x2 %0, %1;" : "=r"(y) : "r"(u));
    return u2h2(y);
}
__device__ __forceinline__ void mma_f16(float* d,
                                        unsigned a0, unsigned a1, unsigned a2, unsigned a3,
                                        unsigned b0, unsigned b1) {
    asm volatile(
        "mma.sync.aligned.m16n8k16.row.col.f32.f16.f16.f32 "
        "{%0,%1,%2,%3},{%4,%5,%6,%7},{%8,%9},{%0,%1,%2,%3};"
        : "+f"(d[0]), "+f"(d[1]), "+f"(d[2]), "+f"(d[3])
        : "r"(a0), "r"(a1), "r"(a2), "r"(a3), "r"(b0), "r"(b1));
}
__device__ __forceinline__ void ldsm_x4(unsigned& r0, unsigned& r1, unsigned& r2, unsigned& r3,
                                        unsigned a) {
    asm volatile("ldmatrix.sync.aligned.m8n8.x4.shared.b16 {%0,%1,%2,%3}, [%4];"
                 : "=r"(r0), "=r"(r1), "=r"(r2), "=r"(r3) : "r"(a));
}
__device__ __forceinline__ void ldsm_x2t(unsigned& r0, unsigned& r1, unsigned a) {
    asm volatile("ldmatrix.sync.aligned.m8n8.x2.trans.shared.b16 {%0,%1}, [%2];"
                 : "=r"(r0), "=r"(r1) : "r"(a));
}

// --------------------------------------------------------------- kernel 1 ---
// Token-gate table via f16 MMA, f16x2 output. 64 vocab rows x 192 gate-cols
// per block. grid (70, 2 streams, 2 halves) = 280 blocks, 2/SM.
__global__ __launch_bounds__(256, 2) void tok_gx_kernel(const float* __restrict__ emb_a,
                                                        const float* __restrict__ emb_c,
                                                        const float* __restrict__ W_ih,
                                                        const float* __restrict__ b_ih,
                                                        const float* __restrict__ b_hh) {
    extern __shared__ unsigned smu[];
    unsigned* Wb  = smu;                     // [192][64] f16x2 words, swizzled
    unsigned* Ab  = smu + 192 * 64;          // [64][64] f16x2 words, swizzled
    float*    bias = (float*)(Ab + 64 * 64); // [192]

    const int tid = threadIdx.x;
    const int tile = blockIdx.x, stream = blockIdx.y, half = blockIdx.z;
    const float* emb = (stream == 0) ? emb_a : emb_c;
    const int row0 = tile * 64;
    const int nbase = half * 192;

    for (int i = tid; i < 192 * 64; i += 256) {
        int n = i >> 6, w = i & 63;
        float2 v = *(const float2*)(W_ih + (size_t)(nbase + n) * 128 + 2 * w);
        Wb[(n << 6) + (w ^ ((n & 7) << 2))] = pack_f16(v.x, v.y);
    }
    for (int i = tid; i < 192; i += 256) {
        int n = nbase + i;
        bias[i] = b_ih[n] + (n < 256 ? b_hh[n] : 0.f);
    }
    for (int i = tid; i < 64 * 64; i += 256) {
        int r = i >> 6, w = i & 63;
        int vr = row0 + r; if (vr >= V_) vr = V_ - 1;
        float2 v = *(const float2*)(emb + (size_t)vr * H_ + 2 * w);
        Ab[(r << 6) + (w ^ ((r & 7) << 2))] = pack_f16(v.x, v.y);
    }
    __syncthreads();

    const int warp = tid >> 5, lane = tid & 31;
    const int rt = warp & 3, ct = warp >> 2;
    const int gid = lane >> 2, qid = lane & 3;
    const int gsw = gid << 2;
    const int ra0 = (rt * 16 + gid) << 6;
    const int ra1 = ra0 + (8 << 6);

    float acc[12][4];
#pragma unroll
    for (int nt = 0; nt < 12; nt++)
#pragma unroll
        for (int e = 0; e < 4; e++) acc[nt][e] = 0.f;

#pragma unroll
    for (int kb = 0; kb < 8; kb++) {
        const int k0 = kb * 8;
        unsigned a0 = Ab[ra0 + ((k0 + qid)     ^ gsw)];
        unsigned a1 = Ab[ra1 + ((k0 + qid)     ^ gsw)];
        unsigned a2 = Ab[ra0 + ((k0 + qid + 4) ^ gsw)];
        unsigned a3 = Ab[ra1 + ((k0 + qid + 4) ^ gsw)];
#pragma unroll
        for (int nt = 0; nt < 12; nt++) {
            const unsigned* wr = Wb + ((ct * 96 + nt * 8 + gid) << 6);
            unsigned b0 = wr[(k0 + qid)     ^ gsw];
            unsigned b1 = wr[(k0 + qid + 4) ^ gsw];
            mma_f16(acc[nt], a0, a1, a2, a3, b0, b1);
        }
    }

#pragma unroll
    for (int m = 0; m < 2; m++) {
        const int row = rt * 16 + gid + 8 * m;
        unsigned* gp = &g_tokG[stream][row0 + row][half * 96];
#pragma unroll
        for (int nt = 0; nt < 12; nt++) {
            const int nl = ct * 96 + nt * 8 + qid * 2;  // local col (0..191)
            gp[ct * 48 + nt * 4 + qid] =
                pack_f16(acc[nt][2 * m] + bias[nl], acc[nt][2 * m + 1] + bias[nl + 1]);
        }
    }
}

// --------------------------------------------------------------- kernel 2 ---
// 4 GRU scans, f16 MMA with LDMATRIX fragment loads (160 LDS.32 -> 40 LDSM
// per warp per step). Block = (scan, 32-row tile), 256 blocks, 2/SM.
// Packed f16x2 h carry in registers; double-buffered Hs, ONE barrier/step;
// gate words prefetched before the GEMM.
__global__ __launch_bounds__(256, 2) void scan_kernel(const float* __restrict__ W_hh,
                                                      const float* __restrict__ b_hh,
                                                      const int* __restrict__ tokens) {
    extern __shared__ unsigned smu[];
    unsigned* Ws   = smu;                       // 384 * 64 f16x2 words, swizzled
    unsigned* Hbuf = smu + 384 * 64;            // 2 x [32*64] words
    unsigned* bnw  = Hbuf + 2 * 32 * 64;        // 64 f16x2 = b_hh for n gate

    const int tid = threadIdx.x;
    const int scan = blockIdx.x >> 6, tile = blockIdx.x & 63;
    const int stream = scan >> 1, rev = scan & 1;
    const int row0 = tile * 32;

    for (int i = tid; i < 384 * 64; i += 256) {
        int n = i >> 6, w = i & 63;
        float2 v = *(const float2*)(W_hh + n * 128 + 2 * w);
        Ws[(n << 6) + (w ^ ((n & 7) << 2))] = pack_f16(v.x, v.y);
    }
    for (int i = tid; i < 32 * 64; i += 256) Hbuf[i] = 0u;   // buffer 0 only
    if (tid < 64) bnw[tid] = pack_f16(b_hh[256 + 2 * tid], b_hh[256 + 2 * tid + 1]);
    __syncthreads();

    const int ct = tid >> 5, lane = tid & 31;   // ct: 16-h-col slice (0..7)
    const int gid = lane >> 2, qid = lane & 3;
    const unsigned* tokG = &g_tokG[stream][0][0];
    const int gidx0 = ct * 8 + qid;             // gate word base (g=0, nt=0)

    // ldmatrix lane geometry
    const unsigned ws_sa = (unsigned)__cvta_generic_to_shared(Ws);
    const unsigned hb_sa = (unsigned)__cvta_generic_to_shared(Hbuf);
    const int l7 = lane & 7, grp = lane >> 3;
    const int swz  = l7 << 2;                   // (row&7)<<2, row&7 == l7 everywhere
    const int wselA = (grp >> 1) << 2;          // 0/4: k-halves
    const int wselB = grp << 2;                 // 0/4/8/12: kb-pair spread
    const unsigned rowA0 = (unsigned)((l7 + ((grp & 1) << 3)) << 8);        // mt=0 rows<<6 words<<2 B
    const unsigned rowA1 = rowA0 + (16 << 8);                                // mt=1
    unsigned bAddr[3][2];
#pragma unroll
    for (int g = 0; g < 3; g++)
#pragma unroll
        for (int nt = 0; nt < 2; nt++)
            bAddr[g][nt] = ws_sa + (unsigned)((g * 128 + ct * 16 + nt * 8 + l7) << 8);

    const __half2 chalf = __floats2half2_rn(0.5f, 0.5f);
    __half2 hreg[4][2];                         // [row e][nt]
#pragma unroll
    for (int e = 0; e < 4; e++)
#pragma unroll
        for (int nt = 0; nt < 2; nt++) hreg[e][nt] = __floats2half2_rn(0.f, 0.f);

    for (int step = 0; step < 40; step++) {
        const int t = rev ? 39 - step : step;
        unsigned* Hnxt = Hbuf + ((step & 1) ? 0 : 32 * 64);
        const unsigned hcur_sa = hb_sa + (unsigned)((step & 1) << 13);

        int tk[4];
#pragma unroll
        for (int e = 0; e < 4; e++)
            tk[e] = __ldg(&tokens[(row0 + gid + 8 * e) * T_ + t]);

        // PREFETCH all gate words (independent of the GEMM; hides under MMA)
        unsigned gw[4][6];                      // [row e][2*g + nt]
#pragma unroll
        for (int e = 0; e < 4; e++) {
            const unsigned* gr = tokG + (size_t)tk[e] * GW_ + gidx0;
#pragma unroll
            for (int g = 0; g < 3; g++) {
                gw[e][2 * g]     = __ldg(gr + g * 64);
                gw[e][2 * g + 1] = __ldg(gr + g * 64 + 4);
            }
        }

        float acc[3][2][2][4];                  // [g][nt][mt][4]
#pragma unroll
        for (int g = 0; g < 3; g++)
#pragma unroll
            for (int nt = 0; nt < 2; nt++)
#pragma unroll
                for (int mt = 0; mt < 2; mt++)
#pragma unroll
                    for (int e = 0; e < 4; e++) acc[g][nt][mt][e] = 0.f;

#pragma unroll
        for (int p = 0; p < 4; p++) {           // kb pair: kb = 2p, 2p+1
            const unsigned wA0 = (unsigned)(((p * 16 + wselA)     ^ swz) << 2);
            const unsigned wA1 = (unsigned)(((p * 16 + 8 + wselA) ^ swz) << 2);
            const unsigned wB  = (unsigned)(((p * 16 + wselB)     ^ swz) << 2);
            unsigned ae0[4], ae1[4], ao0[4], ao1[4];
            ldsm_x4(ae0[0], ae0[1], ae0[2], ae0[3], hcur_sa + rowA0 + wA0);
            ldsm_x4(ae1[0], ae1[1], ae1[2], ae1[3], hcur_sa + rowA1 + wA0);
            ldsm_x4(ao0[0], ao0[1], ao0[2], ao0[3], hcur_sa + rowA0 + wA1);
            ldsm_x4(ao1[0], ao1[1], ao1[2], ao1[3], hcur_sa + rowA1 + wA1);
#pragma unroll
            for (int g = 0; g < 3; g++)
#pragma unroll
                for (int nt = 0; nt < 2; nt++) {
                    unsigned b0, b1, b2, b3;
                    ldsm_x4(b0, b1, b2, b3, bAddr[g][nt] + wB);
                    mma_f16(acc[g][nt][0], ae0[0], ae0[1], ae0[2], ae0[3], b0, b1);
                    mma_f16(acc[g][nt][1], ae1[0], ae1[1], ae1[2], ae1[3], b0, b1);
                    mma_f16(acc[g][nt][0], ao0[0], ao0[1], ao0[2], ao0[3], b2, b3);
                    mma_f16(acc[g][nt][1], ao1[0], ao1[1], ao1[2], ao1[3], b2, b3);
                }
        }

        const bool wmix = (step >= 20);   // fwd: t>=20; rev: t<20 -> both step>=20
#pragma unroll
        for (int e = 0; e < 4; e++) {
            const int mt = e >> 1, hh = e & 1;
            const int row = gid + 8 * e;
#pragma unroll
            for (int nt = 0; nt < 2; nt++) {
                const int wj = ct * 8 + nt * 4 + qid;   // h word index (col pair)
                __half2 xr = u2h2(gw[e][nt]);
                __half2 xz = u2h2(gw[e][2 + nt]);
                __half2 xn = u2h2(gw[e][4 + nt]);
                __half2 gr_ = __floats2half2_rn(acc[0][nt][mt][2 * hh], acc[0][nt][mt][2 * hh + 1]);
                __half2 gz_ = __floats2half2_rn(acc[1][nt][mt][2 * hh], acc[1][nt][mt][2 * hh + 1]);
                __half2 gn_ = __floats2half2_rn(acc[2][nt][mt][2 * hh], acc[2][nt][mt][2 * hh + 1]);
                __half2 r  = __hfma2(tanh2(__hmul2(__hadd2(xr, gr_), chalf)), chalf, chalf);
                __half2 z  = __hfma2(tanh2(__hmul2(__hadd2(xz, gz_), chalf)), chalf, chalf);
                __half2 cn = __hadd2(gn_, u2h2(bnw[wj]));
                __half2 n  = tanh2(__hfma2(r, cn, xn));
                __half2 h  = __hfma2(z, __hsub2(hreg[e][nt], n), n);
                hreg[e][nt] = h;
                unsigned hw = h22u(h);
                Hnxt[(row << 6) + (wj ^ (gid << 2))] = hw;
                if (wmix) g_mix[stream][row0 + row][t][wj] = hw;
            }
        }
        __syncthreads();   // Hnxt visible before next step's GEMM reads it
    }
}

// --------------------------------------------------------------- kernel 3 ---
// C1 = mix_c @ W_cls^T (no bias), f16 in / f16 out. 640 blocks, 3/SM.
__global__ __launch_bounds__(256, 3) void cls_kernel(const float* __restrict__ W_cls) {
    extern __shared__ unsigned smu[];
    unsigned* Wb = smu;              // [104][64] f16x2 words, swizzled
    unsigned* Ab = smu + 104 * 64;   // [128][64] f16x2 words, swizzled

    const int tid = threadIdx.x;
    const int row0 = blockIdx.x * 128;
    const unsigned* mixc = &g_mix[1][0][0][0];

    for (int i = tid; i < 104 * 64; i += 256) {
        int c = i >> 6, w = i & 63;
        float2 v;
        if (c < C_) v = *(const float2*)(W_cls + (size_t)c * 256 + 2 * w);
        else        v = make_float2(0.f, 0.f);
        Wb[(c << 6) + (w ^ ((c & 7) << 2))] = pack_f16(v.x, v.y);
    }
    for (int i = tid; i < 128 * 64; i += 256) {
        int r = i >> 6, w = i & 63;
        Ab[(r << 6) + (w ^ ((r & 7) << 2))] = mixc[(size_t)(row0 + r) * 64 + w];
    }
    __syncthreads();

    const int warp = tid >> 5, lane = tid & 31;
    const int gid = lane >> 2, qid = lane & 3;
    const int gsw = gid << 2;
    const int ra0 = (warp * 16 + gid) << 6;
    const int ra1 = ra0 + (8 << 6);

    float acc[13][4];
#pragma unroll
    for (int nt = 0; nt < 13; nt++)
#pragma unroll
        for (int e = 0; e < 4; e++) acc[nt][e] = 0.f;

#pragma unroll
    for (int kb = 0; kb < 8; kb++) {
        const int k0 = kb * 8;
        unsigned a0 = Ab[ra0 + ((k0 + qid)     ^ gsw)];
        unsigned a1 = Ab[ra1 + ((k0 + qid)     ^ gsw)];
        unsigned a2 = Ab[ra0 + ((k0 + qid + 4) ^ gsw)];
        unsigned a3 = Ab[ra1 + ((k0 + qid + 4) ^ gsw)];
#pragma unroll
        for (int nt = 0; nt < 13; nt++) {
            const unsigned* wr = Wb + ((nt * 8 + gid) << 6);
            unsigned b0 = wr[(k0 + qid)     ^ gsw];
            unsigned b1 = wr[(k0 + qid + 4) ^ gsw];
            mma_f16(acc[nt], a0, a1, a2, a3, b0, b1);
        }
    }

#pragma unroll
    for (int m = 0; m < 2; m++) {
        const int row = warp * 16 + gid + 8 * m;
        unsigned* cp = &g_C1[row0 + row][0];
#pragma unroll
        for (int nt = 0; nt < 13; nt++)
            cp[nt * 4 + qid] = pack_f16(acc[nt][2 * m], acc[nt][2 * m + 1]);
    }
}

// --------------------------------------------------------------- kernel 4 ---
// per-batch: Gram via f16 MMA; col-softmax; logits via f16 MMA with the B
// operand transposed ON LOAD by ldmatrix.x2.trans (no CT build); logits stored
// packed f16 into the dead Uab region. ~34.6 KB smem -> 4/SM.
#define UAW 68   // padded word stride (conflict-free fragments)
#define PTW 28   // Pm word stride (24 used + 4 pad; conflict-free)
__global__ __launch_bounds__(256, 4) void attn_kernel(const float* __restrict__ b_cls,
                                                      float* __restrict__ out) {
    extern __shared__ float sm[];
    unsigned* Uab = (unsigned*)sm;            // [48][UAW] mix_a; later L f16x2 [40][52]
    float*    E   = sm + 48 * UAW;            // [40*40]
    float*    Z   = E + 1600;                 // [40]
    unsigned* Pm  = (unsigned*)(Z + 40);      // [48][PTW] P=E*Z packed f16 (tails zero)
    unsigned* C1s = Pm + 48 * PTW;            // [48][CW_] C1 rows (rows 40-47 zero)
    float*    bs  = (float*)(C1s + 48 * CW_); // [104]

    const int b = blockIdx.x, tid = threadIdx.x;
    const unsigned* pma = &g_mix[0][b][0][0];
    const unsigned* pc1 = &g_C1[b * T_][0];

    for (int i = tid; i < 48 * UAW; i += 256) {
        int t = i / UAW, w = i - t * UAW;
        Uab[i] = (t < 40 && w < 64) ? pma[t * 64 + w] : 0u;
    }
    for (int i = tid; i < 40 * CW_ / 4; i += 256)
        *(uint4*)(C1s + 4 * i) = *(const uint4*)(pc1 + 4 * i);
    for (int i = tid; i < 8 * CW_; i += 256) C1s[40 * CW_ + i] = 0u;   // zero tail rows
    for (int i = tid; i < CP_; i += 256) bs[i] = (i < C_) ? b_cls[i] : 0.f;
    __syncthreads();

    const int warp = tid >> 5, lane = tid & 31;
    const int gid = lane >> 2, qid = lane & 3;
    const int l7 = lane & 7, grp = lane >> 3;

    // Gram via f16 MMA: M = Ua Ua^T. 15 tiles (3 m16 x 5 n8) over 8 warps.
#pragma unroll
    for (int half = 0; half < 2; half++) {
        const int idx = warp + 8 * half;
        if (idx < 15) {
            const int mi = idx / 5, ni = idx - mi * 5;
            const unsigned* A0 = Uab + (mi * 16 + gid) * UAW;
            const unsigned* A1 = A0 + 8 * UAW;
            const unsigned* B0 = Uab + (ni * 8 + gid) * UAW;
            float acc[4] = {0.f, 0.f, 0.f, 0.f};
#pragma unroll
            for (int kb = 0; kb < 8; kb++) {
                const int k0 = kb * 8;
                mma_f16(acc,
                        A0[k0 + qid], A1[k0 + qid], A0[k0 + qid + 4], A1[k0 + qid + 4],
                        B0[k0 + qid], B0[k0 + qid + 4]);
            }
            const int r0 = mi * 16 + gid, c0 = ni * 8 + 2 * qid;
            E[r0 * 40 + c0]     = __expf(acc[0]);
            E[r0 * 40 + c0 + 1] = __expf(acc[1]);
            if (r0 + 8 < 40) {
                E[(r0 + 8) * 40 + c0]     = __expf(acc[2]);
                E[(r0 + 8) * 40 + c0 + 1] = __expf(acc[3]);
            }
        }
    }
    __syncthreads();

    if (tid < 40) {   // Z[t] = 1/column sum (softmax dim=1), 4-way MLP unroll
        float z0 = 0.f, z1 = 0.f, z2 = 0.f, z3 = 0.f;
        for (int s = 0; s < 40; s += 4) {
            z0 += E[(s)     * 40 + tid];
            z1 += E[(s + 1) * 40 + tid];
            z2 += E[(s + 2) * 40 + tid];
            z3 += E[(s + 3) * 40 + tid];
        }
        Z[tid] = 1.f / ((z0 + z1) + (z2 + z3));
    }
    __syncthreads();

    // Build Pm[s][tw] = f16x2(E[s][2tw]Z[2tw], E[s][2tw+1]Z[2tw+1]); tails zero.
    for (int i = tid; i < 48 * PTW; i += 256) {
        int s = i / PTW, w = i - s * PTW;
        unsigned v = 0u;
        if (s < 40 && w < 20)
            v = pack_f16(E[s * 40 + 2 * w] * Z[2 * w], E[s * 40 + 2 * w + 1] * Z[2 * w + 1]);
        Pm[i] = v;
    }
    __syncthreads();

    // Logits via f16 MMA: L = P * C1 + b. 39 tiles (3 m16 x 13 n8), K=48.
    // A via ldmatrix.x4 from Pm; B via ldmatrix.x2.trans straight from C1 rows.
    // L written packed f16 into Uab (dead after Gram).
    {
        const unsigned pm_sa = (unsigned)__cvta_generic_to_shared(Pm);
        const unsigned c1_sa = (unsigned)__cvta_generic_to_shared(C1s);
        const unsigned aLane = (unsigned)(((l7 + ((grp & 1) << 3)) * PTW + ((grp >> 1) << 2)) << 2);
        const unsigned bLane = (unsigned)(((lane & 15) * CW_) << 2);
        unsigned* Lw = Uab;
#pragma unroll
        for (int j = 0; j < 5; j++) {
            const int idx = warp + 8 * j;
            if (idx < 39) {
                const int mt = idx / 13, nt = idx - mt * 13;
                const unsigned aBase = pm_sa + aLane + (unsigned)((mt * 16 * PTW) << 2);
                const unsigned bBase = c1_sa + bLane + (unsigned)((nt * 4) << 2);
                float acc[4] = {0.f, 0.f, 0.f, 0.f};
#pragma unroll
                for (int kt = 0; kt < 3; kt++) {
                    unsigned a0, a1, a2, a3, b0, b1;
                    ldsm_x4(a0, a1, a2, a3, aBase + kt * 32);
                    ldsm_x2t(b0, b1, bBase + kt * 16 * CW_ * 4);
                    mma_f16(acc, a0, a1, a2, a3, b0, b1);
                }
                const int r0 = mt * 16 + gid, c0 = nt * 8 + 2 * qid;
                Lw[r0 * CW_ + nt * 4 + qid] = pack_f16(acc[0] + bs[c0], acc[1] + bs[c0 + 1]);
                if (r0 + 8 < 40)
                    Lw[(r0 + 8) * CW_ + nt * 4 + qid] = pack_f16(acc[2] + bs[c0], acc[3] + bs[c0 + 1]);
            }
        }
    }
    __syncthreads();

    // per-row softmax over classes (f16-packed logits) -> out
    {
        const unsigned* Lw = Uab;
        for (int s = warp; s < 40; s += 8) {
            const unsigned* Lr = Lw + s * CW_;
            float m = -1e30f;
            for (int w = lane; w < 51; w += 32) {
                float2 v = h2f(Lr[w]);
                m = fmaxf(m, fmaxf(v.x, v.y));
            }
#pragma unroll
            for (int o = 16; o; o >>= 1) m = fmaxf(m, __shfl_xor_sync(~0u, m, o));
            float e[4]; int cnt = 0; float sum = 0.f;
            for (int w = lane; w < 51; w += 32) {
                float2 v = h2f(Lr[w]);
                float e0 = __expf(v.x - m), e1 = __expf(v.y - m);
                e[cnt++] = e0; e[cnt++] = e1; sum += e0 + e1;
            }
#pragma unroll
            for (int o = 16; o; o >>= 1) sum += __shfl_xor_sync(~0u, sum, o);
            float r = 1.f / sum; cnt = 0;
            float* op = out + ((size_t)b * T_ + s) * C_;
            for (int w = lane; w < 51; w += 32) {
                op[2 * w]     = e[cnt++] * r;
                op[2 * w + 1] = e[cnt++] * r;
            }
        }
    }
}

// ------------------------------------------------------------------ launch --
#define GX_SMEM   ((192 * 64 + 64 * 64 + 192) * 4)
#define SCAN_SMEM ((384 * 64 + 2 * 32 * 64 + 64) * 4)
#define CLS_SMEM  ((104 * 64 + 128 * 64) * 4)
#define ATTN_SMEM ((48 * UAW + 1600 + 40 + 48 * PTW + 48 * CW_ + CP_) * 4)

extern "C" void kernel_launch(void* const* d_in, const int* in_sizes, int n_in,
                              void* d_out, int out_size) {
    const int*   tokens = (const int*)  d_in[0];
    const float* emb_c  = (const float*)d_in[1];
    const float* emb_a  = (const float*)d_in[2];
    const float* W_ih   = (const float*)d_in[3];
    const float* W_hh   = (const float*)d_in[4];
    const float* b_ih   = (const float*)d_in[5];
    const float* b_hh   = (const float*)d_in[6];
    const float* W_cls  = (const float*)d_in[7];
    const float* b_cls  = (const float*)d_in[8];
    float* out = (float*)d_out;

    cudaFuncSetAttribute(tok_gx_kernel, cudaFuncAttributeMaxDynamicSharedMemorySize, GX_SMEM);
    cudaFuncSetAttribute(scan_kernel,   cudaFuncAttributeMaxDynamicSharedMemorySize, SCAN_SMEM);
    cudaFuncSetAttribute(cls_kernel,    cudaFuncAttributeMaxDynamicSharedMemorySize, CLS_SMEM);
    cudaFuncSetAttribute(attn_kernel,   cudaFuncAttributeMaxDynamicSharedMemorySize, ATTN_SMEM);

    tok_gx_kernel<<<dim3(70, 2, 2), 256, GX_SMEM>>>(emb_a, emb_c, W_ih, b_ih, b_hh);
    scan_kernel  <<<256,            256, SCAN_SMEM>>>(W_hh, b_hh, tokens);
    cls_kernel   <<<BT_ / 128,      256, CLS_SMEM>>>(W_cls);
    attn_kernel  <<<B_,             256, ATTN_SMEM>>>(b_cls, out);
}

// round 15
// speedup vs baseline: 5.5829x; 1.0918x over previous
#include <cuda_runtime.h>
#include <cuda_fp16.h>

#define B_  2048
#define T_  40
#define H_  128
#define V_  4450
#define VP_ 4480   // 70 * 64, padded vocab
#define C_  102
#define CP_ 104    // padded classes (13 * 8)
#define CW_ 52     // CP_/2 f16x2 words
#define G3  384    // 3H
#define GW_ 192    // G3/2 f16x2 words
#define BT_ (B_ * T_)

// Scratch: __device__ globals (the sanctioned no-alloc workaround)
// tokG layout is GATHER-NATIVE for the scan: word index = ct*24 + qid*6 + (2g+nf)
// so one scan thread's 6 gate words are contiguous (24B) and the 4 qid-threads
// of a (token, warp) pair cover one 96B-aligned block = 3 fully-used sectors.
__device__ unsigned g_tokG[2][VP_][GW_];   // per-token input gates, f16x2 (b_ih + b_hh[r,z] folded)
__device__ unsigned g_mix [2][B_][T_][64]; // mixed fwd/bwd states, f16x2 words
__device__ unsigned g_C1  [BT_][CW_];      // mix_c @ W_cls^T (no bias), f16x2 words

// ---------------------------------------------------------------- helpers ---
__device__ __forceinline__ unsigned pack_f16(float lo, float hi) {
    unsigned r; asm("cvt.rn.f16x2.f32 %0, %1, %2;" : "=r"(r) : "f"(hi), "f"(lo)); return r;
}
__device__ __forceinline__ __half2 u2h2(unsigned u) { return *reinterpret_cast<__half2*>(&u); }
__device__ __forceinline__ unsigned h22u(__half2 h) { return *reinterpret_cast<unsigned*>(&h); }
__device__ __forceinline__ float2 h2f(unsigned u) { return __half22float2(u2h2(u)); }
__device__ __forceinline__ __half2 tanh2(__half2 x) {
    unsigned u = h22u(x), y;
    asm("tanh.approx.f16x2 %0, %1;" : "=r"(y) : "r"(u));
    return u2h2(y);
}
__device__ __forceinline__ void mma_f16(float* d,
                                        unsigned a0, unsigned a1, unsigned a2, unsigned a3,
                                        unsigned b0, unsigned b1) {
    asm volatile(
        "mma.sync.aligned.m16n8k16.row.col.f32.f16.f16.f32 "
        "{%0,%1,%2,%3},{%4,%5,%6,%7},{%8,%9},{%0,%1,%2,%3};"
        : "+f"(d[0]), "+f"(d[1]), "+f"(d[2]), "+f"(d[3])
        : "r"(a0), "r"(a1), "r"(a2), "r"(a3), "r"(b0), "r"(b1));
}
__device__ __forceinline__ void ldsm_x4(unsigned& r0, unsigned& r1, unsigned& r2, unsigned& r3,
                                        unsigned a) {
    asm volatile("ldmatrix.sync.aligned.m8n8.x4.shared.b16 {%0,%1,%2,%3}, [%4];"
                 : "=r"(r0), "=r"(r1), "=r"(r2), "=r"(r3) : "r"(a));
}
__device__ __forceinline__ void ldsm_x2t(unsigned& r0, unsigned& r1, unsigned a) {
    asm volatile("ldmatrix.sync.aligned.m8n8.x2.trans.shared.b16 {%0,%1}, [%2];"
                 : "=r"(r0), "=r"(r1) : "r"(a));
}

// --------------------------------------------------------------- kernel 1 ---
// Token-gate table via f16 MMA, f16x2 output in the gather-native layout.
// 64 vocab rows x 192 gate-cols per block. grid (70, 2, 2) = 280 blocks, 2/SM.
__global__ __launch_bounds__(256, 2) void tok_gx_kernel(const float* __restrict__ emb_a,
                                                        const float* __restrict__ emb_c,
                                                        const float* __restrict__ W_ih,
                                                        const float* __restrict__ b_ih,
                                                        const float* __restrict__ b_hh) {
    extern __shared__ unsigned smu[];
    unsigned* Wb  = smu;                     // [192][64] f16x2 words, swizzled
    unsigned* Ab  = smu + 192 * 64;          // [64][64] f16x2 words, swizzled
    float*    bias = (float*)(Ab + 64 * 64); // [192]

    const int tid = threadIdx.x;
    const int tile = blockIdx.x, stream = blockIdx.y, half = blockIdx.z;
    const float* emb = (stream == 0) ? emb_a : emb_c;
    const int row0 = tile * 64;
    const int nbase = half * 192;

    for (int i = tid; i < 192 * 64; i += 256) {
        int n = i >> 6, w = i & 63;
        float2 v = *(const float2*)(W_ih + (size_t)(nbase + n) * 128 + 2 * w);
        Wb[(n << 6) + (w ^ ((n & 7) << 2))] = pack_f16(v.x, v.y);
    }
    for (int i = tid; i < 192; i += 256) {
        int n = nbase + i;
        bias[i] = b_ih[n] + (n < 256 ? b_hh[n] : 0.f);
    }
    for (int i = tid; i < 64 * 64; i += 256) {
        int r = i >> 6, w = i & 63;
        int vr = row0 + r; if (vr >= V_) vr = V_ - 1;
        float2 v = *(const float2*)(emb + (size_t)vr * H_ + 2 * w);
        Ab[(r << 6) + (w ^ ((r & 7) << 2))] = pack_f16(v.x, v.y);
    }
    __syncthreads();

    const int warp = tid >> 5, lane = tid & 31;
    const int rt = warp & 3, ct = warp >> 2;
    const int gid = lane >> 2, qid = lane & 3;
    const int gsw = gid << 2;
    const int ra0 = (rt * 16 + gid) << 6;
    const int ra1 = ra0 + (8 << 6);

    float acc[12][4];
#pragma unroll
    for (int nt = 0; nt < 12; nt++)
#pragma unroll
        for (int e = 0; e < 4; e++) acc[nt][e] = 0.f;

#pragma unroll
    for (int kb = 0; kb < 8; kb++) {
        const int k0 = kb * 8;
        unsigned a0 = Ab[ra0 + ((k0 + qid)     ^ gsw)];
        unsigned a1 = Ab[ra1 + ((k0 + qid)     ^ gsw)];
        unsigned a2 = Ab[ra0 + ((k0 + qid + 4) ^ gsw)];
        unsigned a3 = Ab[ra1 + ((k0 + qid + 4) ^ gsw)];
#pragma unroll
        for (int nt = 0; nt < 12; nt++) {
            const unsigned* wr = Wb + ((ct * 96 + nt * 8 + gid) << 6);
            unsigned b0 = wr[(k0 + qid)     ^ gsw];
            unsigned b1 = wr[(k0 + qid + 4) ^ gsw];
            mma_f16(acc[nt], a0, a1, a2, a3, b0, b1);
        }
    }

#pragma unroll
    for (int m = 0; m < 2; m++) {
        const int row = rt * 16 + gid + 8 * m;
        unsigned* gp = &g_tokG[stream][row0 + row][0];
#pragma unroll
        for (int nt = 0; nt < 12; nt++) {
            const int nl = ct * 96 + nt * 8 + qid * 2;  // local col (0..191)
            // old word index in gate-major layout:
            const int w_old = half * 96 + ct * 48 + nt * 4 + qid;
            const int g = w_old >> 6, rem = w_old & 63;
            const int sct = rem >> 3, snf = (rem >> 2) & 1, sq = rem & 3;
            gp[sct * 24 + sq * 6 + g * 2 + snf] =
                pack_f16(acc[nt][2 * m] + bias[nl], acc[nt][2 * m + 1] + bias[nl + 1]);
        }
    }
}

// --------------------------------------------------------------- kernel 2 ---
// 4 GRU scans, f16 MMA with LDMATRIX fragment loads. Block = (scan, 32-row
// tile), 256 blocks, 2/SM. Gate words now fetched as 3 contiguous LDG.64 per
// row (gather-native tokG) -> fully-used sectors, half the L2 traffic.
__global__ __launch_bounds__(256, 2) void scan_kernel(const float* __restrict__ W_hh,
                                                      const float* __restrict__ b_hh,
                                                      const int* __restrict__ tokens) {
    extern __shared__ unsigned smu[];
    unsigned* Ws   = smu;                       // 384 * 64 f16x2 words, swizzled
    unsigned* Hbuf = smu + 384 * 64;            // 2 x [32*64] words
    unsigned* bnw  = Hbuf + 2 * 32 * 64;        // 64 f16x2 = b_hh for n gate

    const int tid = threadIdx.x;
    const int scan = blockIdx.x >> 6, tile = blockIdx.x & 63;
    const int stream = scan >> 1, rev = scan & 1;
    const int row0 = tile * 32;

    for (int i = tid; i < 384 * 64; i += 256) {
        int n = i >> 6, w = i & 63;
        float2 v = *(const float2*)(W_hh + n * 128 + 2 * w);
        Ws[(n << 6) + (w ^ ((n & 7) << 2))] = pack_f16(v.x, v.y);
    }
    for (int i = tid; i < 32 * 64; i += 256) Hbuf[i] = 0u;   // buffer 0 only
    if (tid < 64) bnw[tid] = pack_f16(b_hh[256 + 2 * tid], b_hh[256 + 2 * tid + 1]);
    __syncthreads();

    const int ct = tid >> 5, lane = tid & 31;   // ct: 16-h-col slice (0..7)
    const int gid = lane >> 2, qid = lane & 3;
    const unsigned* tokG = &g_tokG[stream][0][0];
    const int gidx0 = ct * 24 + qid * 6;        // contiguous 6-word gate base

    // ldmatrix lane geometry
    const unsigned ws_sa = (unsigned)__cvta_generic_to_shared(Ws);
    const unsigned hb_sa = (unsigned)__cvta_generic_to_shared(Hbuf);
    const int l7 = lane & 7, grp = lane >> 3;
    const int swz  = l7 << 2;                   // (row&7)<<2, row&7 == l7 everywhere
    const int wselA = (grp >> 1) << 2;          // 0/4: k-halves
    const int wselB = grp << 2;                 // 0/4/8/12: kb-pair spread
    const unsigned rowA0 = (unsigned)((l7 + ((grp & 1) << 3)) << 8);        // mt=0
    const unsigned rowA1 = rowA0 + (16 << 8);                                // mt=1
    unsigned bAddr[3][2];
#pragma unroll
    for (int g = 0; g < 3; g++)
#pragma unroll
        for (int nt = 0; nt < 2; nt++)
            bAddr[g][nt] = ws_sa + (unsigned)((g * 128 + ct * 16 + nt * 8 + l7) << 8);

    const __half2 chalf = __floats2half2_rn(0.5f, 0.5f);
    __half2 hreg[4][2];                         // [row e][nt]
#pragma unroll
    for (int e = 0; e < 4; e++)
#pragma unroll
        for (int nt = 0; nt < 2; nt++) hreg[e][nt] = __floats2half2_rn(0.f, 0.f);

    for (int step = 0; step < 40; step++) {
        const int t = rev ? 39 - step : step;
        unsigned* Hnxt = Hbuf + ((step & 1) ? 0 : 32 * 64);
        const unsigned hcur_sa = hb_sa + (unsigned)((step & 1) << 13);

        int tk[4];
#pragma unroll
        for (int e = 0; e < 4; e++)
            tk[e] = __ldg(&tokens[(row0 + gid + 8 * e) * T_ + t]);

        // PREFETCH gate words: 3 contiguous LDG.64 per row (fully-used sectors)
        unsigned gw[4][6];                      // [row e][2*g + nt]
#pragma unroll
        for (int e = 0; e < 4; e++) {
            const uint2* gr = (const uint2*)(tokG + (size_t)tk[e] * GW_ + gidx0);
            uint2 p0 = __ldg(gr), p1 = __ldg(gr + 1), p2 = __ldg(gr + 2);
            gw[e][0] = p0.x; gw[e][1] = p0.y;
            gw[e][2] = p1.x; gw[e][3] = p1.y;
            gw[e][4] = p2.x; gw[e][5] = p2.y;
        }

        float acc[3][2][2][4];                  // [g][nt][mt][4]
#pragma unroll
        for (int g = 0; g < 3; g++)
#pragma unroll
            for (int nt = 0; nt < 2; nt++)
#pragma unroll
                for (int mt = 0; mt < 2; mt++)
#pragma unroll
                    for (int e = 0; e < 4; e++) acc[g][nt][mt][e] = 0.f;

#pragma unroll
        for (int p = 0; p < 4; p++) {           // kb pair: kb = 2p, 2p+1
            const unsigned wA0 = (unsigned)(((p * 16 + wselA)     ^ swz) << 2);
            const unsigned wA1 = (unsigned)(((p * 16 + 8 + wselA) ^ swz) << 2);
            const unsigned wB  = (unsigned)(((p * 16 + wselB)     ^ swz) << 2);
            unsigned ae0[4], ae1[4], ao0[4], ao1[4];
            ldsm_x4(ae0[0], ae0[1], ae0[2], ae0[3], hcur_sa + rowA0 + wA0);
            ldsm_x4(ae1[0], ae1[1], ae1[2], ae1[3], hcur_sa + rowA1 + wA0);
            ldsm_x4(ao0[0], ao0[1], ao0[2], ao0[3], hcur_sa + rowA0 + wA1);
            ldsm_x4(ao1[0], ao1[1], ao1[2], ao1[3], hcur_sa + rowA1 + wA1);
#pragma unroll
            for (int g = 0; g < 3; g++)
#pragma unroll
                for (int nt = 0; nt < 2; nt++) {
                    unsigned b0, b1, b2, b3;
                    ldsm_x4(b0, b1, b2, b3, bAddr[g][nt] + wB);
                    mma_f16(acc[g][nt][0], ae0[0], ae0[1], ae0[2], ae0[3], b0, b1);
                    mma_f16(acc[g][nt][1], ae1[0], ae1[1], ae1[2], ae1[3], b0, b1);
                    mma_f16(acc[g][nt][0], ao0[0], ao0[1], ao0[2], ao0[3], b2, b3);
                    mma_f16(acc[g][nt][1], ao1[0], ao1[1], ao1[2], ao1[3], b2, b3);
                }
        }

        const bool wmix = (step >= 20);   // fwd: t>=20; rev: t<20 -> both step>=20
#pragma unroll
        for (int e = 0; e < 4; e++) {
            const int mt = e >> 1, hh = e & 1;
            const int row = gid + 8 * e;
#pragma unroll
            for (int nt = 0; nt < 2; nt++) {
                const int wj = ct * 8 + nt * 4 + qid;   // h word index (col pair)
                __half2 xr = u2h2(gw[e][nt]);
                __half2 xz = u2h2(gw[e][2 + nt]);
                __half2 xn = u2h2(gw[e][4 + nt]);
                __half2 gr_ = __floats2half2_rn(acc[0][nt][mt][2 * hh], acc[0][nt][mt][2 * hh + 1]);
                __half2 gz_ = __floats2half2_rn(acc[1][nt][mt][2 * hh], acc[1][nt][mt][2 * hh + 1]);
                __half2 gn_ = __floats2half2_rn(acc[2][nt][mt][2 * hh], acc[2][nt][mt][2 * hh + 1]);
                __half2 r  = __hfma2(tanh2(__hmul2(__hadd2(xr, gr_), chalf)), chalf, chalf);
                __half2 z  = __hfma2(tanh2(__hmul2(__hadd2(xz, gz_), chalf)), chalf, chalf);
                __half2 cn = __hadd2(gn_, u2h2(bnw[wj]));
                __half2 n  = tanh2(__hfma2(r, cn, xn));
                __half2 h  = __hfma2(z, __hsub2(hreg[e][nt], n), n);
                hreg[e][nt] = h;
                unsigned hw = h22u(h);
                Hnxt[(row << 6) + (wj ^ (gid << 2))] = hw;
                if (wmix) g_mix[stream][row0 + row][t][wj] = hw;
            }
        }
        __syncthreads();   // Hnxt visible before next step's GEMM reads it
    }
}

// --------------------------------------------------------------- kernel 3 ---
// C1 = mix_c @ W_cls^T (no bias), f16 in / f16 out. 640 blocks, 3/SM.
__global__ __launch_bounds__(256, 3) void cls_kernel(const float* __restrict__ W_cls) {
    extern __shared__ unsigned smu[];
    unsigned* Wb = smu;              // [104][64] f16x2 words, swizzled
    unsigned* Ab = smu + 104 * 64;   // [128][64] f16x2 words, swizzled

    const int tid = threadIdx.x;
    const int row0 = blockIdx.x * 128;
    const unsigned* mixc = &g_mix[1][0][0][0];

    for (int i = tid; i < 104 * 64; i += 256) {
        int c = i >> 6, w = i & 63;
        float2 v;
        if (c < C_) v = *(const float2*)(W_cls + (size_t)c * 256 + 2 * w);
        else        v = make_float2(0.f, 0.f);
        Wb[(c << 6) + (w ^ ((c & 7) << 2))] = pack_f16(v.x, v.y);
    }
    for (int i = tid; i < 128 * 64; i += 256) {
        int r = i >> 6, w = i & 63;
        Ab[(r << 6) + (w ^ ((r & 7) << 2))] = mixc[(size_t)(row0 + r) * 64 + w];
    }
    __syncthreads();

    const int warp = tid >> 5, lane = tid & 31;
    const int gid = lane >> 2, qid = lane & 3;
    const int gsw = gid << 2;
    const int ra0 = (warp * 16 + gid) << 6;
    const int ra1 = ra0 + (8 << 6);

    float acc[13][4];
#pragma unroll
    for (int nt = 0; nt < 13; nt++)
#pragma unroll
        for (int e = 0; e < 4; e++) acc[nt][e] = 0.f;

#pragma unroll
    for (int kb = 0; kb < 8; kb++) {
        const int k0 = kb * 8;
        unsigned a0 = Ab[ra0 + ((k0 + qid)     ^ gsw)];
        unsigned a1 = Ab[ra1 + ((k0 + qid)     ^ gsw)];
        unsigned a2 = Ab[ra0 + ((k0 + qid + 4) ^ gsw)];
        unsigned a3 = Ab[ra1 + ((k0 + qid + 4) ^ gsw)];
#pragma unroll
        for (int nt = 0; nt < 13; nt++) {
            const unsigned* wr = Wb + ((nt * 8 + gid) << 6);
            unsigned b0 = wr[(k0 + qid)     ^ gsw];
            unsigned b1 = wr[(k0 + qid + 4) ^ gsw];
            mma_f16(acc[nt], a0, a1, a2, a3, b0, b1);
        }
    }

#pragma unroll
    for (int m = 0; m < 2; m++) {
        const int row = warp * 16 + gid + 8 * m;
        unsigned* cp = &g_C1[row0 + row][0];
#pragma unroll
        for (int nt = 0; nt < 13; nt++)
            cp[nt * 4 + qid] = pack_f16(acc[nt][2 * m], acc[nt][2 * m + 1]);
    }
}

// --------------------------------------------------------------- kernel 4 ---
// per-batch: Gram via f16 MMA; col-softmax; logits via f16 MMA with the B
// operand transposed ON LOAD by ldmatrix.x2.trans; logits stored packed f16
// into the dead Uab region. ~34.6 KB smem -> 4/SM.
#define UAW 68   // padded word stride (conflict-free fragments)
#define PTW 28   // Pm word stride (24 used + 4 pad; conflict-free)
__global__ __launch_bounds__(256, 4) void attn_kernel(const float* __restrict__ b_cls,
                                                      float* __restrict__ out) {
    extern __shared__ float sm[];
    unsigned* Uab = (unsigned*)sm;            // [48][UAW] mix_a; later L f16x2 [40][52]
    float*    E   = sm + 48 * UAW;            // [40*40]
    float*    Z   = E + 1600;                 // [40]
    unsigned* Pm  = (unsigned*)(Z + 40);      // [48][PTW] P=E*Z packed f16 (tails zero)
    unsigned* C1s = Pm + 48 * PTW;            // [48][CW_] C1 rows (rows 40-47 zero)
    float*    bs  = (float*)(C1s + 48 * CW_); // [104]

    const int b = blockIdx.x, tid = threadIdx.x;
    const unsigned* pma = &g_mix[0][b][0][0];
    const unsigned* pc1 = &g_C1[b * T_][0];

    for (int i = tid; i < 48 * UAW; i += 256) {
        int t = i / UAW, w = i - t * UAW;
        Uab[i] = (t < 40 && w < 64) ? pma[t * 64 + w] : 0u;
    }
    for (int i = tid; i < 40 * CW_ / 4; i += 256)
        *(uint4*)(C1s + 4 * i) = *(const uint4*)(pc1 + 4 * i);
    for (int i = tid; i < 8 * CW_; i += 256) C1s[40 * CW_ + i] = 0u;   // zero tail rows
    for (int i = tid; i < CP_; i += 256) bs[i] = (i < C_) ? b_cls[i] : 0.f;
    __syncthreads();

    const int warp = tid >> 5, lane = tid & 31;
    const int gid = lane >> 2, qid = lane & 3;
    const int l7 = lane & 7, grp = lane >> 3;

    // Gram via f16 MMA: M = Ua Ua^T. 15 tiles (3 m16 x 5 n8) over 8 warps.
#pragma unroll
    for (int half = 0; half < 2; half++) {
        const int idx = warp + 8 * half;
        if (idx < 15) {
            const int mi = idx / 5, ni = idx - mi * 5;
            const unsigned* A0 = Uab + (mi * 16 + gid) * UAW;
            const unsigned* A1 = A0 + 8 * UAW;
            const unsigned* B0 = Uab + (ni * 8 + gid) * UAW;
            float acc[4] = {0.f, 0.f, 0.f, 0.f};
#pragma unroll
            for (int kb = 0; kb < 8; kb++) {
                const int k0 = kb * 8;
                mma_f16(acc,
                        A0[k0 + qid], A1[k0 + qid], A0[k0 + qid + 4], A1[k0 + qid + 4],
                        B0[k0 + qid], B0[k0 + qid + 4]);
            }
            const int r0 = mi * 16 + gid, c0 = ni * 8 + 2 * qid;
            E[r0 * 40 + c0]     = __expf(acc[0]);
            E[r0 * 40 + c0 + 1] = __expf(acc[1]);
            if (r0 + 8 < 40) {
                E[(r0 + 8) * 40 + c0]     = __expf(acc[2]);
                E[(r0 + 8) * 40 + c0 + 1] = __expf(acc[3]);
            }
        }
    }
    __syncthreads();

    if (tid < 40) {   // Z[t] = 1/column sum (softmax dim=1), 4-way MLP unroll
        float z0 = 0.f, z1 = 0.f, z2 = 0.f, z3 = 0.f;
        for (int s = 0; s < 40; s += 4) {
            z0 += E[(s)     * 40 + tid];
            z1 += E[(s + 1) * 40 + tid];
            z2 += E[(s + 2) * 40 + tid];
            z3 += E[(s + 3) * 40 + tid];
        }
        Z[tid] = 1.f / ((z0 + z1) + (z2 + z3));
    }
    __syncthreads();

    // Build Pm[s][tw] = f16x2(E[s][2tw]Z[2tw], E[s][2tw+1]Z[2tw+1]); tails zero.
    for (int i = tid; i < 48 * PTW; i += 256) {
        int s = i / PTW, w = i - s * PTW;
        unsigned v = 0u;
        if (s < 40 && w < 20)
            v = pack_f16(E[s * 40 + 2 * w] * Z[2 * w], E[s * 40 + 2 * w + 1] * Z[2 * w + 1]);
        Pm[i] = v;
    }
    __syncthreads();

    // Logits via f16 MMA: L = P * C1 + b. 39 tiles (3 m16 x 13 n8), K=48.
    {
        const unsigned pm_sa = (unsigned)__cvta_generic_to_shared(Pm);
        const unsigned c1_sa = (unsigned)__cvta_generic_to_shared(C1s);
        const unsigned aLane = (unsigned)(((l7 + ((grp & 1) << 3)) * PTW + ((grp >> 1) << 2)) << 2);
        const unsigned bLane = (unsigned)(((lane & 15) * CW_) << 2);
        unsigned* Lw = Uab;
#pragma unroll
        for (int j = 0; j < 5; j++) {
            const int idx = warp + 8 * j;
            if (idx < 39) {
                const int mt = idx / 13, nt = idx - mt * 13;
                const unsigned aBase = pm_sa + aLane + (unsigned)((mt * 16 * PTW) << 2);
                const unsigned bBase = c1_sa + bLane + (unsigned)((nt * 4) << 2);
                float acc[4] = {0.f, 0.f, 0.f, 0.f};
#pragma unroll
                for (int kt = 0; kt < 3; kt++) {
                    unsigned a0, a1, a2, a3, b0, b1;
                    ldsm_x4(a0, a1, a2, a3, aBase + kt * 32);
                    ldsm_x2t(b0, b1, bBase + kt * 16 * CW_ * 4);
                    mma_f16(acc, a0, a1, a2, a3, b0, b1);
                }
                const int r0 = mt * 16 + gid, c0 = nt * 8 + 2 * qid;
                Lw[r0 * CW_ + nt * 4 + qid] = pack_f16(acc[0] + bs[c0], acc[1] + bs[c0 + 1]);
                if (r0 + 8 < 40)
                    Lw[(r0 + 8) * CW_ + nt * 4 + qid] = pack_f16(acc[2] + bs[c0], acc[3] + bs[c0 + 1]);
            }
        }
    }
    __syncthreads();

    // per-row softmax over classes (f16-packed logits) -> out
    {
        const unsigned* Lw = Uab;
        for (int s = warp; s < 40; s += 8) {
            const unsigned* Lr = Lw + s * CW_;
            float m = -1e30f;
            for (int w = lane; w < 51; w += 32) {
                float2 v = h2f(Lr[w]);
                m = fmaxf(m, fmaxf(v.x, v.y));
            }
#pragma unroll
            for (int o = 16; o; o >>= 1) m = fmaxf(m, __shfl_xor_sync(~0u, m, o));
            float e[4]; int cnt = 0; float sum = 0.f;
            for (int w = lane; w < 51; w += 32) {
                float2 v = h2f(Lr[w]);
                float e0 = __expf(v.x - m), e1 = __expf(v.y - m);
                e[cnt++] = e0; e[cnt++] = e1; sum += e0 + e1;
            }
#pragma unroll
            for (int o = 16; o; o >>= 1) sum += __shfl_xor_sync(~0u, sum, o);
            float r = 1.f / sum; cnt = 0;
            float* op = out + ((size_t)b * T_ + s) * C_;
            for (int w = lane; w < 51; w += 32) {
                op[2 * w]     = e[cnt++] * r;
                op[2 * w + 1] = e[cnt++] * r;
            }
        }
    }
}

// ------------------------------------------------------------------ launch --
#define GX_SMEM   ((192 * 64 + 64 * 64 + 192) * 4)
#define SCAN_SMEM ((384 * 64 + 2 * 32 * 64 + 64) * 4)
#define CLS_SMEM  ((104 * 64 + 128 * 64) * 4)
#define ATTN_SMEM ((48 * UAW + 1600 + 40 + 48 * PTW + 48 * CW_ + CP_) * 4)

extern "C" void kernel_launch(void* const* d_in, const int* in_sizes, int n_in,
                              void* d_out, int out_size) {
    const int*   tokens = (const int*)  d_in[0];
    const float* emb_c  = (const float*)d_in[1];
    const float* emb_a  = (const float*)d_in[2];
    const float* W_ih   = (const float*)d_in[3];
    const float* W_hh   = (const float*)d_in[4];
    const float* b_ih   = (const float*)d_in[5];
    const float* b_hh   = (const float*)d_in[6];
    const float* W_cls  = (const float*)d_in[7];
    const float* b_cls  = (const float*)d_in[8];
    float* out = (float*)d_out;

    cudaFuncSetAttribute(tok_gx_kernel, cudaFuncAttributeMaxDynamicSharedMemorySize, GX_SMEM);
    cudaFuncSetAttribute(scan_kernel,   cudaFuncAttributeMaxDynamicSharedMemorySize, SCAN_SMEM);
    cudaFuncSetAttribute(cls_kernel,    cudaFuncAttributeMaxDynamicSharedMemorySize, CLS_SMEM);
    cudaFuncSetAttribute(attn_kernel,   cudaFuncAttributeMaxDynamicSharedMemorySize, ATTN_SMEM);

    tok_gx_kernel<<<dim3(70, 2, 2), 256, GX_SMEM>>>(emb_a, emb_c, W_ih, b_ih, b_hh);
    scan_kernel  <<<256,            256, SCAN_SMEM>>>(W_hh, b_hh, tokens);
    cls_kernel   <<<BT_ / 128,      256, CLS_SMEM>>>(W_cls);
    attn_kernel  <<<B_,             256, ATTN_SMEM>>>(b_cls, out);
}

// round 16
// speedup vs baseline: 5.7253x; 1.0255x over previous
#include <cuda_runtime.h>
#include <cuda_fp16.h>

#define B_  2048
#define T_  40
#define H_  128
#define V_  4450
#define VP_ 4480   // 70 * 64, padded vocab
#define C_  102
#define CP_ 104    // padded classes (13 * 8)
#define CW_ 52     // CP_/2 f16x2 words
#define G3  384    // 3H
#define GW_ 192    // G3/2 f16x2 words
#define BT_ (B_ * T_)

// Scratch: __device__ globals (the sanctioned no-alloc workaround)
// tokG layout is GATHER-NATIVE for the scan: word index = ct*24 + qid*6 + (2g+nf)
__device__ unsigned g_tokG[2][VP_][GW_];   // per-token input gates, f16x2 (b_ih + b_hh[r,z] folded)
__device__ unsigned g_mix [2][B_][T_][64]; // mixed fwd/bwd states, f16x2 words
__device__ unsigned g_C1  [BT_][CW_];      // mix_c @ W_cls^T (no bias), f16x2 words

// ---------------------------------------------------------------- helpers ---
__device__ __forceinline__ unsigned pack_f16(float lo, float hi) {
    unsigned r; asm("cvt.rn.f16x2.f32 %0, %1, %2;" : "=r"(r) : "f"(hi), "f"(lo)); return r;
}
__device__ __forceinline__ __half2 u2h2(unsigned u) { return *reinterpret_cast<__half2*>(&u); }
__device__ __forceinline__ unsigned h22u(__half2 h) { return *reinterpret_cast<unsigned*>(&h); }
__device__ __forceinline__ float2 h2f(unsigned u) { return __half22float2(u2h2(u)); }
__device__ __forceinline__ __half2 tanh2(__half2 x) {
    unsigned u = h22u(x), y;
    asm("tanh.approx.f16x2 %0, %1;" : "=r"(y) : "r"(u));
    return u2h2(y);
}
__device__ __forceinline__ void mma_f16(float* d,
                                        unsigned a0, unsigned a1, unsigned a2, unsigned a3,
                                        unsigned b0, unsigned b1) {
    asm volatile(
        "mma.sync.aligned.m16n8k16.row.col.f32.f16.f16.f32 "
        "{%0,%1,%2,%3},{%4,%5,%6,%7},{%8,%9},{%0,%1,%2,%3};"
        : "+f"(d[0]), "+f"(d[1]), "+f"(d[2]), "+f"(d[3])
        : "r"(a0), "r"(a1), "r"(a2), "r"(a3), "r"(b0), "r"(b1));
}
__device__ __forceinline__ void ldsm_x4(unsigned& r0, unsigned& r1, unsigned& r2, unsigned& r3,
                                        unsigned a) {
    asm volatile("ldmatrix.sync.aligned.m8n8.x4.shared.b16 {%0,%1,%2,%3}, [%4];"
                 : "=r"(r0), "=r"(r1), "=r"(r2), "=r"(r3) : "r"(a));
}
__device__ __forceinline__ void ldsm_x2t(unsigned& r0, unsigned& r1, unsigned a) {
    asm volatile("ldmatrix.sync.aligned.m8n8.x2.trans.shared.b16 {%0,%1}, [%2];"
                 : "=r"(r0), "=r"(r1) : "r"(a));
}

// --------------------------------------------------------------- kernel 1 ---
// Token-gate table via f16 MMA, f16x2 output in the gather-native layout.
__global__ __launch_bounds__(256, 2) void tok_gx_kernel(const float* __restrict__ emb_a,
                                                        const float* __restrict__ emb_c,
                                                        const float* __restrict__ W_ih,
                                                        const float* __restrict__ b_ih,
                                                        const float* __restrict__ b_hh) {
    extern __shared__ unsigned smu[];
    unsigned* Wb  = smu;                     // [192][64] f16x2 words, swizzled
    unsigned* Ab  = smu + 192 * 64;          // [64][64] f16x2 words, swizzled
    float*    bias = (float*)(Ab + 64 * 64); // [192]

    const int tid = threadIdx.x;
    const int tile = blockIdx.x, stream = blockIdx.y, half = blockIdx.z;
    const float* emb = (stream == 0) ? emb_a : emb_c;
    const int row0 = tile * 64;
    const int nbase = half * 192;

    for (int i = tid; i < 192 * 64; i += 256) {
        int n = i >> 6, w = i & 63;
        float2 v = *(const float2*)(W_ih + (size_t)(nbase + n) * 128 + 2 * w);
        Wb[(n << 6) + (w ^ ((n & 7) << 2))] = pack_f16(v.x, v.y);
    }
    for (int i = tid; i < 192; i += 256) {
        int n = nbase + i;
        bias[i] = b_ih[n] + (n < 256 ? b_hh[n] : 0.f);
    }
    for (int i = tid; i < 64 * 64; i += 256) {
        int r = i >> 6, w = i & 63;
        int vr = row0 + r; if (vr >= V_) vr = V_ - 1;
        float2 v = *(const float2*)(emb + (size_t)vr * H_ + 2 * w);
        Ab[(r << 6) + (w ^ ((r & 7) << 2))] = pack_f16(v.x, v.y);
    }
    __syncthreads();

    const int warp = tid >> 5, lane = tid & 31;
    const int rt = warp & 3, ct = warp >> 2;
    const int gid = lane >> 2, qid = lane & 3;
    const int gsw = gid << 2;
    const int ra0 = (rt * 16 + gid) << 6;
    const int ra1 = ra0 + (8 << 6);

    float acc[12][4];
#pragma unroll
    for (int nt = 0; nt < 12; nt++)
#pragma unroll
        for (int e = 0; e < 4; e++) acc[nt][e] = 0.f;

#pragma unroll
    for (int kb = 0; kb < 8; kb++) {
        const int k0 = kb * 8;
        unsigned a0 = Ab[ra0 + ((k0 + qid)     ^ gsw)];
        unsigned a1 = Ab[ra1 + ((k0 + qid)     ^ gsw)];
        unsigned a2 = Ab[ra0 + ((k0 + qid + 4) ^ gsw)];
        unsigned a3 = Ab[ra1 + ((k0 + qid + 4) ^ gsw)];
#pragma unroll
        for (int nt = 0; nt < 12; nt++) {
            const unsigned* wr = Wb + ((ct * 96 + nt * 8 + gid) << 6);
            unsigned b0 = wr[(k0 + qid)     ^ gsw];
            unsigned b1 = wr[(k0 + qid + 4) ^ gsw];
            mma_f16(acc[nt], a0, a1, a2, a3, b0, b1);
        }
    }

#pragma unroll
    for (int m = 0; m < 2; m++) {
        const int row = rt * 16 + gid + 8 * m;
        unsigned* gp = &g_tokG[stream][row0 + row][0];
#pragma unroll
        for (int nt = 0; nt < 12; nt++) {
            const int nl = ct * 96 + nt * 8 + qid * 2;  // local col (0..191)
            const int w_old = half * 96 + ct * 48 + nt * 4 + qid;
            const int g = w_old >> 6, rem = w_old & 63;
            const int sct = rem >> 3, snf = (rem >> 2) & 1, sq = rem & 3;
            gp[sct * 24 + sq * 6 + g * 2 + snf] =
                pack_f16(acc[nt][2 * m] + bias[nl], acc[nt][2 * m + 1] + bias[nl + 1]);
        }
    }
}

// --------------------------------------------------------------- kernel 2 ---
// 4 GRU scans, f16 MMA with LDMATRIX fragment loads. Block = (scan, 32-row
// tile), 256 blocks, 2/SM. Gate words fetched as 3 contiguous LDG.64 per row.
// bnw values hoisted into registers (ptxas won't hoist smem loads across BAR).
__global__ __launch_bounds__(256, 2) void scan_kernel(const float* __restrict__ W_hh,
                                                      const float* __restrict__ b_hh,
                                                      const int* __restrict__ tokens) {
    extern __shared__ unsigned smu[];
    unsigned* Ws   = smu;                       // 384 * 64 f16x2 words, swizzled
    unsigned* Hbuf = smu + 384 * 64;            // 2 x [32*64] words
    unsigned* bnw  = Hbuf + 2 * 32 * 64;        // 64 f16x2 = b_hh for n gate

    const int tid = threadIdx.x;
    const int scan = blockIdx.x >> 6, tile = blockIdx.x & 63;
    const int stream = scan >> 1, rev = scan & 1;
    const int row0 = tile * 32;

    for (int i = tid; i < 384 * 64; i += 256) {
        int n = i >> 6, w = i & 63;
        float2 v = *(const float2*)(W_hh + n * 128 + 2 * w);
        Ws[(n << 6) + (w ^ ((n & 7) << 2))] = pack_f16(v.x, v.y);
    }
    for (int i = tid; i < 32 * 64; i += 256) Hbuf[i] = 0u;   // buffer 0 only
    if (tid < 64) bnw[tid] = pack_f16(b_hh[256 + 2 * tid], b_hh[256 + 2 * tid + 1]);
    __syncthreads();

    const int ct = tid >> 5, lane = tid & 31;   // ct: 16-h-col slice (0..7)
    const int gid = lane >> 2, qid = lane & 3;
    const unsigned* tokG = &g_tokG[stream][0][0];
    const int gidx0 = ct * 24 + qid * 6;        // contiguous 6-word gate base

    // hoist loop-invariant n-gate bias words into registers
    const __half2 bn0 = u2h2(bnw[ct * 8 + qid]);
    const __half2 bn1 = u2h2(bnw[ct * 8 + 4 + qid]);

    // ldmatrix lane geometry
    const unsigned ws_sa = (unsigned)__cvta_generic_to_shared(Ws);
    const unsigned hb_sa = (unsigned)__cvta_generic_to_shared(Hbuf);
    const int l7 = lane & 7, grp = lane >> 3;
    const int swz  = l7 << 2;
    const int wselA = (grp >> 1) << 2;
    const int wselB = grp << 2;
    const unsigned rowA0 = (unsigned)((l7 + ((grp & 1) << 3)) << 8);
    const unsigned rowA1 = rowA0 + (16 << 8);
    unsigned bAddr[3][2];
#pragma unroll
    for (int g = 0; g < 3; g++)
#pragma unroll
        for (int nt = 0; nt < 2; nt++)
            bAddr[g][nt] = ws_sa + (unsigned)((g * 128 + ct * 16 + nt * 8 + l7) << 8);

    const __half2 chalf = __floats2half2_rn(0.5f, 0.5f);
    __half2 hreg[4][2];
#pragma unroll
    for (int e = 0; e < 4; e++)
#pragma unroll
        for (int nt = 0; nt < 2; nt++) hreg[e][nt] = __floats2half2_rn(0.f, 0.f);

    for (int step = 0; step < 40; step++) {
        const int t = rev ? 39 - step : step;
        unsigned* Hnxt = Hbuf + ((step & 1) ? 0 : 32 * 64);
        const unsigned hcur_sa = hb_sa + (unsigned)((step & 1) << 13);

        int tk[4];
#pragma unroll
        for (int e = 0; e < 4; e++)
            tk[e] = __ldg(&tokens[(row0 + gid + 8 * e) * T_ + t]);

        unsigned gw[4][6];
#pragma unroll
        for (int e = 0; e < 4; e++) {
            const uint2* gr = (const uint2*)(tokG + (size_t)tk[e] * GW_ + gidx0);
            uint2 p0 = __ldg(gr), p1 = __ldg(gr + 1), p2 = __ldg(gr + 2);
            gw[e][0] = p0.x; gw[e][1] = p0.y;
            gw[e][2] = p1.x; gw[e][3] = p1.y;
            gw[e][4] = p2.x; gw[e][5] = p2.y;
        }

        float acc[3][2][2][4];
#pragma unroll
        for (int g = 0; g < 3; g++)
#pragma unroll
            for (int nt = 0; nt < 2; nt++)
#pragma unroll
                for (int mt = 0; mt < 2; mt++)
#pragma unroll
                    for (int e = 0; e < 4; e++) acc[g][nt][mt][e] = 0.f;

#pragma unroll
        for (int p = 0; p < 4; p++) {
            const unsigned wA0 = (unsigned)(((p * 16 + wselA)     ^ swz) << 2);
            const unsigned wA1 = (unsigned)(((p * 16 + 8 + wselA) ^ swz) << 2);
            const unsigned wB  = (unsigned)(((p * 16 + wselB)     ^ swz) << 2);
            unsigned ae0[4], ae1[4], ao0[4], ao1[4];
            ldsm_x4(ae0[0], ae0[1], ae0[2], ae0[3], hcur_sa + rowA0 + wA0);
            ldsm_x4(ae1[0], ae1[1], ae1[2], ae1[3], hcur_sa + rowA1 + wA0);
            ldsm_x4(ao0[0], ao0[1], ao0[2], ao0[3], hcur_sa + rowA0 + wA1);
            ldsm_x4(ao1[0], ao1[1], ao1[2], ao1[3], hcur_sa + rowA1 + wA1);
#pragma unroll
            for (int g = 0; g < 3; g++)
#pragma unroll
                for (int nt = 0; nt < 2; nt++) {
                    unsigned b0, b1, b2, b3;
                    ldsm_x4(b0, b1, b2, b3, bAddr[g][nt] + wB);
                    mma_f16(acc[g][nt][0], ae0[0], ae0[1], ae0[2], ae0[3], b0, b1);
                    mma_f16(acc[g][nt][1], ae1[0], ae1[1], ae1[2], ae1[3], b0, b1);
                    mma_f16(acc[g][nt][0], ao0[0], ao0[1], ao0[2], ao0[3], b2, b3);
                    mma_f16(acc[g][nt][1], ao1[0], ao1[1], ao1[2], ao1[3], b2, b3);
                }
        }

        const bool wmix = (step >= 20);
#pragma unroll
        for (int e = 0; e < 4; e++) {
            const int mt = e >> 1, hh = e & 1;
            const int row = gid + 8 * e;
#pragma unroll
            for (int nt = 0; nt < 2; nt++) {
                const int wj = ct * 8 + nt * 4 + qid;
                __half2 xr = u2h2(gw[e][nt]);
                __half2 xz = u2h2(gw[e][2 + nt]);
                __half2 xn = u2h2(gw[e][4 + nt]);
                __half2 gr_ = __floats2half2_rn(acc[0][nt][mt][2 * hh], acc[0][nt][mt][2 * hh + 1]);
                __half2 gz_ = __floats2half2_rn(acc[1][nt][mt][2 * hh], acc[1][nt][mt][2 * hh + 1]);
                __half2 gn_ = __floats2half2_rn(acc[2][nt][mt][2 * hh], acc[2][nt][mt][2 * hh + 1]);
                __half2 r  = __hfma2(tanh2(__hmul2(__hadd2(xr, gr_), chalf)), chalf, chalf);
                __half2 z  = __hfma2(tanh2(__hmul2(__hadd2(xz, gz_), chalf)), chalf, chalf);
                __half2 cn = __hadd2(gn_, nt ? bn1 : bn0);
                __half2 n  = tanh2(__hfma2(r, cn, xn));
                __half2 h  = __hfma2(z, __hsub2(hreg[e][nt], n), n);
                hreg[e][nt] = h;
                unsigned hw = h22u(h);
                Hnxt[(row << 6) + (wj ^ (gid << 2))] = hw;
                if (wmix) g_mix[stream][row0 + row][t][wj] = hw;
            }
        }
        __syncthreads();
    }
}

// --------------------------------------------------------------- kernel 3 ---
// C1 = mix_c @ W_cls^T (no bias), f16 in / f16 out. 640 blocks, 3/SM.
__global__ __launch_bounds__(256, 3) void cls_kernel(const float* __restrict__ W_cls) {
    extern __shared__ unsigned smu[];
    unsigned* Wb = smu;              // [104][64] f16x2 words, swizzled
    unsigned* Ab = smu + 104 * 64;   // [128][64] f16x2 words, swizzled

    const int tid = threadIdx.x;
    const int row0 = blockIdx.x * 128;
    const unsigned* mixc = &g_mix[1][0][0][0];

    for (int i = tid; i < 104 * 64; i += 256) {
        int c = i >> 6, w = i & 63;
        float2 v;
        if (c < C_) v = *(const float2*)(W_cls + (size_t)c * 256 + 2 * w);
        else        v = make_float2(0.f, 0.f);
        Wb[(c << 6) + (w ^ ((c & 7) << 2))] = pack_f16(v.x, v.y);
    }
    for (int i = tid; i < 128 * 64; i += 256) {
        int r = i >> 6, w = i & 63;
        Ab[(r << 6) + (w ^ ((r & 7) << 2))] = mixc[(size_t)(row0 + r) * 64 + w];
    }
    __syncthreads();

    const int warp = tid >> 5, lane = tid & 31;
    const int gid = lane >> 2, qid = lane & 3;
    const int gsw = gid << 2;
    const int ra0 = (warp * 16 + gid) << 6;
    const int ra1 = ra0 + (8 << 6);

    float acc[13][4];
#pragma unroll
    for (int nt = 0; nt < 13; nt++)
#pragma unroll
        for (int e = 0; e < 4; e++) acc[nt][e] = 0.f;

#pragma unroll
    for (int kb = 0; kb < 8; kb++) {
        const int k0 = kb * 8;
        unsigned a0 = Ab[ra0 + ((k0 + qid)     ^ gsw)];
        unsigned a1 = Ab[ra1 + ((k0 + qid)     ^ gsw)];
        unsigned a2 = Ab[ra0 + ((k0 + qid + 4) ^ gsw)];
        unsigned a3 = Ab[ra1 + ((k0 + qid + 4) ^ gsw)];
#pragma unroll
        for (int nt = 0; nt < 13; nt++) {
            const unsigned* wr = Wb + ((nt * 8 + gid) << 6);
            unsigned b0 = wr[(k0 + qid)     ^ gsw];
            unsigned b1 = wr[(k0 + qid + 4) ^ gsw];
            mma_f16(acc[nt], a0, a1, a2, a3, b0, b1);
        }
    }

#pragma unroll
    for (int m = 0; m < 2; m++) {
        const int row = warp * 16 + gid + 8 * m;
        unsigned* cp = &g_C1[row0 + row][0];
#pragma unroll
        for (int nt = 0; nt < 13; nt++)
            cp[nt * 4 + qid] = pack_f16(acc[nt][2 * m], acc[nt][2 * m + 1]);
    }
}

// --------------------------------------------------------------- kernel 4 ---
// TWO batches per block (phases do 2x work per barrier -> better issue
// efficiency, half the per-batch sync overhead). 1024 blocks, ~68.7 KB smem
// -> 3 blocks/SM = 6 batches resident.
#define UAW 68   // padded word stride (conflict-free fragments)
#define PTW 28   // Pm word stride (24 used + 4 pad; conflict-free)
#define UASZ (48 * UAW)
#define PMSZ (48 * PTW)
#define C1SZ (48 * CW_)
__global__ __launch_bounds__(256, 3) void attn_kernel(const float* __restrict__ b_cls,
                                                      float* __restrict__ out) {
    extern __shared__ float sm[];
    unsigned* Uab = (unsigned*)sm;                  // [2][48][UAW]; later L f16x2 [40][52]
    float*    E   = sm + 2 * UASZ;                  // [2][1600]
    float*    Z   = E + 2 * 1600;                   // [2][40]
    unsigned* Pm  = (unsigned*)(Z + 80);            // [2][48][PTW]
    unsigned* C1s = Pm + 2 * PMSZ;                  // [2][48][CW_] (rows 40-47 zero)
    float*    bs  = (float*)(C1s + 2 * C1SZ);       // [104]

    const int b0 = blockIdx.x * 2, tid = threadIdx.x;

#pragma unroll
    for (int bi = 0; bi < 2; bi++) {
        const unsigned* pma = &g_mix[0][b0 + bi][0][0];
        const unsigned* pc1 = &g_C1[(b0 + bi) * T_][0];
        unsigned* Ub = Uab + bi * UASZ;
        unsigned* Cb = C1s + bi * C1SZ;
        for (int i = tid; i < UASZ; i += 256) {
            int t = i / UAW, w = i - t * UAW;
            Ub[i] = (t < 40 && w < 64) ? pma[t * 64 + w] : 0u;
        }
        for (int i = tid; i < 40 * CW_ / 4; i += 256)
            *(uint4*)(Cb + 4 * i) = *(const uint4*)(pc1 + 4 * i);
        for (int i = tid; i < 8 * CW_; i += 256) Cb[40 * CW_ + i] = 0u;
    }
    for (int i = tid; i < CP_; i += 256) bs[i] = (i < C_) ? b_cls[i] : 0.f;
    __syncthreads();

    const int warp = tid >> 5, lane = tid & 31;
    const int gid = lane >> 2, qid = lane & 3;
    const int l7 = lane & 7, grp = lane >> 3;

    // Gram via f16 MMA: 15 tiles x 2 batches = 30 tasks over 8 warps.
#pragma unroll
    for (int j = 0; j < 4; j++) {
        const int idx = warp + 8 * j;
        if (idx < 30) {
            const int bi = idx / 15, t15 = idx - bi * 15;
            const int mi = t15 / 5, ni = t15 - mi * 5;
            const unsigned* Ub = Uab + bi * UASZ;
            const unsigned* A0 = Ub + (mi * 16 + gid) * UAW;
            const unsigned* A1 = A0 + 8 * UAW;
            const unsigned* B0 = Ub + (ni * 8 + gid) * UAW;
            float acc[4] = {0.f, 0.f, 0.f, 0.f};
#pragma unroll
            for (int kb = 0; kb < 8; kb++) {
                const int k0 = kb * 8;
                mma_f16(acc,
                        A0[k0 + qid], A1[k0 + qid], A0[k0 + qid + 4], A1[k0 + qid + 4],
                        B0[k0 + qid], B0[k0 + qid + 4]);
            }
            float* Eb = E + bi * 1600;
            const int r0 = mi * 16 + gid, c0 = ni * 8 + 2 * qid;
            Eb[r0 * 40 + c0]     = __expf(acc[0]);
            Eb[r0 * 40 + c0 + 1] = __expf(acc[1]);
            if (r0 + 8 < 40) {
                Eb[(r0 + 8) * 40 + c0]     = __expf(acc[2]);
                Eb[(r0 + 8) * 40 + c0 + 1] = __expf(acc[3]);
            }
        }
    }
    __syncthreads();

    if (tid < 80) {   // Z: 2 batches x 40 cols
        const int bi = tid / 40, t = tid - bi * 40;
        const float* Eb = E + bi * 1600;
        float z0 = 0.f, z1 = 0.f, z2 = 0.f, z3 = 0.f;
        for (int s = 0; s < 40; s += 4) {
            z0 += Eb[(s)     * 40 + t];
            z1 += Eb[(s + 1) * 40 + t];
            z2 += Eb[(s + 2) * 40 + t];
            z3 += Eb[(s + 3) * 40 + t];
        }
        Z[bi * 40 + t] = 1.f / ((z0 + z1) + (z2 + z3));
    }
    __syncthreads();

    // Build Pm for both batches
    for (int i = tid; i < 2 * PMSZ; i += 256) {
        const int bi = i / PMSZ, r = i - bi * PMSZ;
        const int s = r / PTW, w = r - s * PTW;
        unsigned v = 0u;
        if (s < 40 && w < 20) {
            const float* Eb = E + bi * 1600;
            const float* Zb = Z + bi * 40;
            v = pack_f16(Eb[s * 40 + 2 * w] * Zb[2 * w], Eb[s * 40 + 2 * w + 1] * Zb[2 * w + 1]);
        }
        Pm[i] = v;
    }
    __syncthreads();

    // Logits via f16 MMA: 39 tiles x 2 batches = 78 tasks over 8 warps.
    {
        const unsigned pm_sa = (unsigned)__cvta_generic_to_shared(Pm);
        const unsigned c1_sa = (unsigned)__cvta_generic_to_shared(C1s);
        const unsigned aLane = (unsigned)(((l7 + ((grp & 1) << 3)) * PTW + ((grp >> 1) << 2)) << 2);
        const unsigned bLane = (unsigned)(((lane & 15) * CW_) << 2);
#pragma unroll
        for (int j = 0; j < 10; j++) {
            const int idx = warp + 8 * j;
            if (idx < 78) {
                const int bi = idx / 39, t39 = idx - bi * 39;
                const int mt = t39 / 13, nt = t39 - mt * 13;
                const unsigned aBase = pm_sa + (unsigned)(bi * PMSZ * 4) + aLane
                                     + (unsigned)((mt * 16 * PTW) << 2);
                const unsigned bBase = c1_sa + (unsigned)(bi * C1SZ * 4) + bLane
                                     + (unsigned)((nt * 4) << 2);
                float acc[4] = {0.f, 0.f, 0.f, 0.f};
#pragma unroll
                for (int kt = 0; kt < 3; kt++) {
                    unsigned a0, a1, a2, a3, b0, b1;
                    ldsm_x4(a0, a1, a2, a3, aBase + kt * 32);
                    ldsm_x2t(b0, b1, bBase + kt * 16 * CW_ * 4);
                    mma_f16(acc, a0, a1, a2, a3, b0, b1);
                }
                unsigned* Lw = Uab + bi * UASZ;   // L overwrites Uab (dead after Gram)
                const int r0 = mt * 16 + gid, c0 = nt * 8 + 2 * qid;
                Lw[r0 * CW_ + nt * 4 + qid] = pack_f16(acc[0] + bs[c0], acc[1] + bs[c0 + 1]);
                if (r0 + 8 < 40)
                    Lw[(r0 + 8) * CW_ + nt * 4 + qid] = pack_f16(acc[2] + bs[c0], acc[3] + bs[c0 + 1]);
            }
        }
    }
    __syncthreads();

    // per-row softmax over classes: 80 rows over 8 warps
    for (int s8 = warp; s8 < 80; s8 += 8) {
        const int bi = s8 / 40, s = s8 - bi * 40;
        const unsigned* Lr = Uab + bi * UASZ + s * CW_;
        float m = -1e30f;
        for (int w = lane; w < 51; w += 32) {
            float2 v = h2f(Lr[w]);
            m = fmaxf(m, fmaxf(v.x, v.y));
        }
#pragma unroll
        for (int o = 16; o; o >>= 1) m = fmaxf(m, __shfl_xor_sync(~0u, m, o));
        float e[4]; int cnt = 0; float sum = 0.f;
        for (int w = lane; w < 51; w += 32) {
            float2 v = h2f(Lr[w]);
            float e0 = __expf(v.x - m), e1 = __expf(v.y - m);
            e[cnt++] = e0; e[cnt++] = e1; sum += e0 + e1;
        }
#pragma unroll
        for (int o = 16; o; o >>= 1) sum += __shfl_xor_sync(~0u, sum, o);
        float r = 1.f / sum; cnt = 0;
        float* op = out + ((size_t)(b0 + bi) * T_ + s) * C_;
        for (int w = lane; w < 51; w += 32) {
            op[2 * w]     = e[cnt++] * r;
            op[2 * w + 1] = e[cnt++] * r;
        }
    }
}

// ------------------------------------------------------------------ launch --
#define GX_SMEM   ((192 * 64 + 64 * 64 + 192) * 4)
#define SCAN_SMEM ((384 * 64 + 2 * 32 * 64 + 64) * 4)
#define CLS_SMEM  ((104 * 64 + 128 * 64) * 4)
#define ATTN_SMEM ((2 * UASZ + 2 * 1600 + 80 + 2 * PMSZ + 2 * C1SZ + CP_) * 4)

extern "C" void kernel_launch(void* const* d_in, const int* in_sizes, int n_in,
                              void* d_out, int out_size) {
    const int*   tokens = (const int*)  d_in[0];
    const float* emb_c  = (const float*)d_in[1];
    const float* emb_a  = (const float*)d_in[2];
    const float* W_ih   = (const float*)d_in[3];
    const float* W_hh   = (const float*)d_in[4];
    const float* b_ih   = (const float*)d_in[5];
    const float* b_hh   = (const float*)d_in[6];
    const float* W_cls  = (const float*)d_in[7];
    const float* b_cls  = (const float*)d_in[8];
    float* out = (float*)d_out;

    cudaFuncSetAttribute(tok_gx_kernel, cudaFuncAttributeMaxDynamicSharedMemorySize, GX_SMEM);
    cudaFuncSetAttribute(scan_kernel,   cudaFuncAttributeMaxDynamicSharedMemorySize, SCAN_SMEM);
    cudaFuncSetAttribute(cls_kernel,    cudaFuncAttributeMaxDynamicSharedMemorySize, CLS_SMEM);
    cudaFuncSetAttribute(attn_kernel,   cudaFuncAttributeMaxDynamicSharedMemorySize, ATTN_SMEM);

    tok_gx_kernel<<<dim3(70, 2, 2), 256, GX_SMEM>>>(emb_a, emb_c, W_ih, b_ih, b_hh);
    scan_kernel  <<<256,            256, SCAN_SMEM>>>(W_hh, b_hh, tokens);
    cls_kernel   <<<BT_ / 128,      256, CLS_SMEM>>>(W_cls);
    attn_kernel  <<<B_ / 2,         256, ATTN_SMEM>>>(b_cls, out);
}